// round 1
// baseline (speedup 1.0000x reference)
#include <cuda_runtime.h>
#include <math.h>
#include <stdint.h>

// Problem constants
#define Bq  2
#define Sq  2048
#define Dq  1024
#define Hq  16
#define HDq 64
#define DIq 2730            // int(8/3 * 1024)
#define BSq (Bq*Sq)         // 4096 rows

// ---------------- scratch (device globals; no allocation allowed) -----------
__device__ float g_xn  [(size_t)BSq*Dq];
__device__ float g_qkv [(size_t)BSq*3*Dq];
__device__ float g_q   [(size_t)Bq*Hq*Sq*HDq];
__device__ float g_k   [(size_t)Bq*Hq*Sq*HDq];
__device__ float g_v   [(size_t)Bq*Hq*Sq*HDq];
__device__ float g_attn[(size_t)BSq*Dq];
__device__ float g_h   [(size_t)BSq*Dq];
__device__ float g_hn  [(size_t)BSq*Dq];
__device__ float g_ff1 [(size_t)BSq*DIq];
__device__ float g_ff2 [(size_t)BSq*DIq];

// ---------------- RMSNorm: one block per row of 1024 ------------------------
__global__ void __launch_bounds__(256) rmsnorm_k(const float* __restrict__ x,
                                                 const float* __restrict__ gamma,
                                                 float* __restrict__ out)
{
    const size_t row = blockIdx.x;
    const float* xr = x + row * Dq;
    float ss = 0.f;
    for (int c = threadIdx.x; c < Dq; c += 256) { float v = xr[c]; ss += v * v; }
    #pragma unroll
    for (int d = 16; d > 0; d >>= 1) ss += __shfl_xor_sync(0xffffffffu, ss, d);
    __shared__ float red[8];
    __shared__ float s_inv;
    if ((threadIdx.x & 31) == 0) red[threadIdx.x >> 5] = ss;
    __syncthreads();
    if (threadIdx.x == 0) {
        float t = 0.f;
        #pragma unroll
        for (int i = 0; i < 8; i++) t += red[i];
        s_inv = rsqrtf(t / (float)Dq + 1e-5f);
    }
    __syncthreads();
    float* orow = out + row * Dq;
    const float inv = s_inv;
    for (int c = threadIdx.x; c < Dq; c += 256) orow[c] = xr[c] * inv * gamma[c];
}

// ---------------- Tiled SGEMM:  C[M,N] = A[M,K] @ W[N,K]^T  -----------------
// MODE 0: +bias
// MODE 1: silu(+bias)
// MODE 2: (+bias) * extra[m,n]
// MODE 3: (+bias) + extra[m,n]
template <int MODE>
__global__ void __launch_bounds__(256) gemm_nt(const float* __restrict__ A,
                                               const float* __restrict__ W,
                                               const float* __restrict__ bias,
                                               const float* __restrict__ extra,
                                               float* __restrict__ C,
                                               int M, int N, int K)
{
    __shared__ float As[32][65];   // [k][m], padded: conflict-free store & read
    __shared__ float Ws[32][65];   // [k][n]
    const int m0 = blockIdx.y * 64;
    const int n0 = blockIdx.x * 64;
    const int tid = threadIdx.x;
    const int tx = tid & 15, ty = tid >> 4;

    float acc[4][4] = {};

    for (int k0 = 0; k0 < K; k0 += 32) {
        #pragma unroll
        for (int t = 0; t < 8; t++) {
            int idx = tid + t * 256;          // 2048 elements per operand tile
            int m  = idx >> 5;                // 0..63
            int kk = idx & 31;                // 0..31  (coalesced in k)
            int gk = k0 + kk;
            float av = 0.f, wv = 0.f;
            if (gk < K) {
                av = A[(size_t)(m0 + m) * K + gk];        // M % 64 == 0 always
                int gn = n0 + m;
                if (gn < N) wv = W[(size_t)gn * K + gk];
            }
            As[kk][m] = av;
            Ws[kk][m] = wv;
        }
        __syncthreads();
        #pragma unroll
        for (int kk = 0; kk < 32; kk++) {
            float a0 = As[kk][ty*4+0], a1 = As[kk][ty*4+1];
            float a2 = As[kk][ty*4+2], a3 = As[kk][ty*4+3];
            float b0 = Ws[kk][tx*4+0], b1 = Ws[kk][tx*4+1];
            float b2 = Ws[kk][tx*4+2], b3 = Ws[kk][tx*4+3];
            acc[0][0] += a0*b0; acc[0][1] += a0*b1; acc[0][2] += a0*b2; acc[0][3] += a0*b3;
            acc[1][0] += a1*b0; acc[1][1] += a1*b1; acc[1][2] += a1*b2; acc[1][3] += a1*b3;
            acc[2][0] += a2*b0; acc[2][1] += a2*b1; acc[2][2] += a2*b2; acc[2][3] += a2*b3;
            acc[3][0] += a3*b0; acc[3][1] += a3*b1; acc[3][2] += a3*b2; acc[3][3] += a3*b3;
        }
        __syncthreads();
    }

    #pragma unroll
    for (int i = 0; i < 4; i++) {
        int gm = m0 + ty * 4 + i;
        #pragma unroll
        for (int j = 0; j < 4; j++) {
            int gn = n0 + tx * 4 + j;
            if (gn < N) {
                float v = acc[i][j] + bias[gn];
                if (MODE == 1) v = v / (1.f + expf(-v));                 // silu
                if (MODE == 2) v *= extra[(size_t)gm * N + gn];
                if (MODE == 3) v += extra[(size_t)gm * N + gn];
                C[(size_t)gm * N + gn] = v;
            }
        }
    }
}

// ---------------- RoPE + split/transpose:  qkv[b,s,3D] -> q,k,v [b,h,s,64] --
__global__ void __launch_bounds__(256) rope_split(const float* __restrict__ qkv,
                                                  float* __restrict__ q,
                                                  float* __restrict__ k,
                                                  float* __restrict__ v)
{
    int idx = blockIdx.x * 256 + threadIdx.x;       // B*S*H*32 = 2^21 threads
    int i = idx & 31;                               // rotation pair index
    int h = (idx >> 5) & 15;
    int s = (idx >> 9) & 2047;
    int b = idx >> 20;

    const size_t row = ((size_t)(b * Sq + s)) * (3 * Dq);
    const int off = h * HDq;

    float theta = powf(10000.f, -((float)(2 * i)) / 64.f);
    float sn, cs;
    sincosf((float)s * theta, &sn, &cs);

    float q1 = qkv[row + off + 2*i], q2 = qkv[row + off + 2*i + 1];
    float k1 = qkv[row + Dq + off + 2*i], k2 = qkv[row + Dq + off + 2*i + 1];
    float v1 = qkv[row + 2*Dq + off + 2*i], v2 = qkv[row + 2*Dq + off + 2*i + 1];

    size_t orow = ((size_t)(b * Hq + h) * Sq + s) * HDq;
    q[orow + i]      = q1 * cs - q2 * sn;
    q[orow + 32 + i] = q1 * sn + q2 * cs;
    k[orow + i]      = k1 * cs - k2 * sn;
    k[orow + 32 + i] = k1 * sn + k2 * cs;
    v[orow + 2*i]     = v1;
    v[orow + 2*i + 1] = v2;
}

// ---------------- Causal flash attention (BM=64, BN=32, HD=64, fp32) --------
// Q,K,V: [B,H,S,64]; O written as [B,S,H*64] (ready for out-proj GEMM).
__global__ void __launch_bounds__(256) flash_attn(const float* __restrict__ Q,
                                                  const float* __restrict__ K,
                                                  const float* __restrict__ V,
                                                  float* __restrict__ O)
{
    __shared__ float Qs[64][65];
    __shared__ float KPs[32][65];   // holds K tile, then reused for P^T
    __shared__ float Vs[32][64];

    const int qt = blockIdx.x, h = blockIdx.y, b = blockIdx.z;
    const int qm0 = qt * 64;
    const size_t base = ((size_t)(b * Hq + h)) * Sq * HDq;
    const float* Qb = Q + base;
    const float* Kb = K + base;
    const float* Vb = V + base;

    const int tid = threadIdx.x;
    const int tx = tid & 15, ty = tid >> 4;   // cols tx*2+{0,1}; rows ty*4+{0..3}

    for (int i = tid; i < 64 * 64; i += 256) {
        int r = i >> 6, c = i & 63;
        Qs[r][c] = Qb[(size_t)(qm0 + r) * 64 + c];
    }

    float m_i[4], l_i[4], o[4][4];
    #pragma unroll
    for (int i = 0; i < 4; i++) {
        m_i[i] = -1e30f; l_i[i] = 0.f;
        #pragma unroll
        for (int j = 0; j < 4; j++) o[i][j] = 0.f;
    }

    const int nkt = (qm0 + 64) >> 5;          // causal: key tiles [0, qm0+64)
    for (int kt = 0; kt < nkt; kt++) {
        const int kn0 = kt << 5;
        __syncthreads();                       // prior P/V readers done
        for (int i = tid; i < 32 * 64; i += 256) {
            int r = i >> 6, c = i & 63;
            KPs[r][c] = Kb[(size_t)(kn0 + r) * 64 + c];
            Vs[r][c]  = Vb[(size_t)(kn0 + r) * 64 + c];
        }
        __syncthreads();

        float s[4][2] = {};
        #pragma unroll 4
        for (int kd = 0; kd < 64; kd++) {
            float b0 = KPs[tx*2 + 0][kd];
            float b1 = KPs[tx*2 + 1][kd];
            #pragma unroll
            for (int i = 0; i < 4; i++) {
                float a = Qs[ty*4 + i][kd];
                s[i][0] += a * b0;
                s[i][1] += a * b1;
            }
        }

        float p[4][2];
        #pragma unroll
        for (int i = 0; i < 4; i++) {
            int qi = qm0 + ty*4 + i;
            float s0 = (kn0 + tx*2 + 0 <= qi) ? s[i][0] * 0.125f : -1e30f;
            float s1 = (kn0 + tx*2 + 1 <= qi) ? s[i][1] * 0.125f : -1e30f;
            float mr = fmaxf(s0, s1);
            #pragma unroll
            for (int d = 1; d < 16; d <<= 1)
                mr = fmaxf(mr, __shfl_xor_sync(0xffffffffu, mr, d));
            float mnew  = fmaxf(m_i[i], mr);
            float alpha = expf(m_i[i] - mnew);
            float p0 = expf(s0 - mnew);
            float p1 = expf(s1 - mnew);
            float rs = p0 + p1;
            #pragma unroll
            for (int d = 1; d < 16; d <<= 1)
                rs += __shfl_xor_sync(0xffffffffu, rs, d);
            l_i[i] = l_i[i] * alpha + rs;
            m_i[i] = mnew;
            #pragma unroll
            for (int j = 0; j < 4; j++) o[i][j] *= alpha;
            p[i][0] = p0; p[i][1] = p1;
        }

        __syncthreads();                       // done reading K tile
        #pragma unroll
        for (int i = 0; i < 4; i++) {          // store P^T into KPs[col][row]
            KPs[tx*2 + 0][ty*4 + i] = p[i][0];
            KPs[tx*2 + 1][ty*4 + i] = p[i][1];
        }
        __syncthreads();

        for (int kk = 0; kk < 32; kk++) {      // O += P @ V
            float4 v4 = *(const float4*)&Vs[kk][tx*4];
            #pragma unroll
            for (int i = 0; i < 4; i++) {
                float pr = KPs[kk][ty*4 + i];
                o[i][0] += pr * v4.x; o[i][1] += pr * v4.y;
                o[i][2] += pr * v4.z; o[i][3] += pr * v4.w;
            }
        }
    }

    #pragma unroll
    for (int i = 0; i < 4; i++) {
        int qi = qm0 + ty*4 + i;
        float inv = 1.f / l_i[i];
        size_t orow = ((size_t)(b * Sq + qi)) * Dq + h * HDq + tx * 4;
        O[orow + 0] = o[i][0] * inv;
        O[orow + 1] = o[i][1] * inv;
        O[orow + 2] = o[i][2] * inv;
        O[orow + 3] = o[i][3] * inv;
    }
}

// ---------------- launch --------------------------------------------------
extern "C" void kernel_launch(void* const* d_in, const int* in_sizes, int n_in,
                              void* d_out, int out_size)
{
    const float* x          = (const float*)d_in[0];
    // d_in[1] = mask (tril, causal) — handled analytically in flash_attn
    const float* gamma_attn = (const float*)d_in[2];
    const float* w_qkv      = (const float*)d_in[3];
    const float* b_qkv      = (const float*)d_in[4];
    const float* w_out      = (const float*)d_in[5];
    const float* b_out      = (const float*)d_in[6];
    const float* gamma_ffn  = (const float*)d_in[7];
    const float* w1         = (const float*)d_in[8];
    const float* b1         = (const float*)d_in[9];
    const float* w2         = (const float*)d_in[10];
    const float* b2         = (const float*)d_in[11];
    const float* w3         = (const float*)d_in[12];
    const float* b3         = (const float*)d_in[13];
    float* out = (float*)d_out;

    float *xn, *qkv, *q, *k, *v, *attn, *h, *hn, *ff1, *ff2;
    cudaGetSymbolAddress((void**)&xn,   g_xn);
    cudaGetSymbolAddress((void**)&qkv,  g_qkv);
    cudaGetSymbolAddress((void**)&q,    g_q);
    cudaGetSymbolAddress((void**)&k,    g_k);
    cudaGetSymbolAddress((void**)&v,    g_v);
    cudaGetSymbolAddress((void**)&attn, g_attn);
    cudaGetSymbolAddress((void**)&h,    g_h);
    cudaGetSymbolAddress((void**)&hn,   g_hn);
    cudaGetSymbolAddress((void**)&ff1,  g_ff1);
    cudaGetSymbolAddress((void**)&ff2,  g_ff2);

    // 1) xn = rmsnorm(x, gamma_attn)
    rmsnorm_k<<<BSq, 256>>>(x, gamma_attn, xn);

    // 2) qkv = xn @ w_qkv^T + b_qkv            [4096, 3072]
    gemm_nt<0><<<dim3(3*Dq/64, BSq/64), 256>>>(xn, w_qkv, b_qkv, nullptr, qkv,
                                               BSq, 3*Dq, Dq);

    // 3) rope(q), rope(k), transpose v -> [b,h,s,64]
    rope_split<<<(Bq*Sq*Hq*32)/256, 256>>>(qkv, q, k, v);

    // 4) causal flash attention -> attn [b,s,1024]
    flash_attn<<<dim3(Sq/64, Hq, Bq), 256>>>(q, k, v, attn);

    // 5) h = xn + attn @ w_out^T + b_out
    gemm_nt<3><<<dim3(Dq/64, BSq/64), 256>>>(attn, w_out, b_out, xn, h,
                                             BSq, Dq, Dq);

    // 6) hn = rmsnorm(h, gamma_ffn)
    rmsnorm_k<<<BSq, 256>>>(h, gamma_ffn, hn);

    // 7) gate = silu(hn @ w2^T + b2)           [4096, 2730]
    gemm_nt<1><<<dim3((DIq+63)/64, BSq/64), 256>>>(hn, w2, b2, nullptr, ff2,
                                                   BSq, DIq, Dq);

    // 8) ff = (hn @ w1^T + b1) * gate
    gemm_nt<2><<<dim3((DIq+63)/64, BSq/64), 256>>>(hn, w1, b1, ff2, ff1,
                                                   BSq, DIq, Dq);

    // 9) out = hn + ff @ w3^T + b3
    gemm_nt<3><<<dim3(Dq/64, BSq/64), 256>>>(ff1, w3, b3, hn, out,
                                             BSq, Dq, DIq);
}

// round 2
// speedup vs baseline: 2.6413x; 2.6413x over previous
#include <cuda_runtime.h>
#include <math.h>
#include <stdint.h>

// Problem constants
#define Bq  2
#define Sq  2048
#define Dq  1024
#define Hq  16
#define HDq 64
#define DIq 2730            // int(8/3 * 1024)
#define DIpad 2736          // padded row stride (mult of 16B/float4)
#define BSq (Bq*Sq)         // 4096 rows

// ---------------- scratch (device globals; no allocation allowed) -----------
__device__ float g_xn  [(size_t)BSq*Dq];
__device__ float g_qkv [(size_t)BSq*3*Dq];
__device__ float g_q   [(size_t)Bq*Hq*Sq*HDq];
__device__ float g_k   [(size_t)Bq*Hq*Sq*HDq];
__device__ float g_v   [(size_t)Bq*Hq*Sq*HDq];
__device__ float g_attn[(size_t)BSq*Dq];
__device__ float g_h   [(size_t)BSq*Dq];
__device__ float g_hn  [(size_t)BSq*Dq];
__device__ float g_ff1 [(size_t)BSq*DIpad];
__device__ float g_ff2 [(size_t)BSq*DIpad];

// ---------------- RMSNorm: one block per row of 1024 ------------------------
__global__ void __launch_bounds__(256) rmsnorm_k(const float* __restrict__ x,
                                                 const float* __restrict__ gamma,
                                                 float* __restrict__ out)
{
    const size_t row = blockIdx.x;
    const float* xr = x + row * Dq;
    float ss = 0.f;
    for (int c = threadIdx.x; c < Dq; c += 256) { float v = xr[c]; ss += v * v; }
    #pragma unroll
    for (int d = 16; d > 0; d >>= 1) ss += __shfl_xor_sync(0xffffffffu, ss, d);
    __shared__ float red[8];
    __shared__ float s_inv;
    if ((threadIdx.x & 31) == 0) red[threadIdx.x >> 5] = ss;
    __syncthreads();
    if (threadIdx.x == 0) {
        float t = 0.f;
        #pragma unroll
        for (int i = 0; i < 8; i++) t += red[i];
        s_inv = rsqrtf(t / (float)Dq + 1e-5f);
    }
    __syncthreads();
    float* orow = out + row * Dq;
    const float inv = s_inv;
    for (int c = threadIdx.x; c < Dq; c += 256) orow[c] = xr[c] * inv * gamma[c];
}

// ---------------- TF32 tensor-core GEMM:  C[M,N] = A[M,K] @ W[N,K]^T --------
// MODE 0: +bias
// MODE 1: silu(+bias)
// MODE 2: (+bias) * extra[m,n]
// MODE 3: (+bias) + extra[m,n]
// CTA tile 128x128x32, 8 warps (2x4), warp tile 64x32, mma m16n8k8 tf32.
// smem rows padded to 36 floats -> conflict-free fragment reads.
#define GBM 128
#define GBN 128
#define GBK 32
#define GPAD 36

__device__ __forceinline__ float tf32_rna(float x) {
    float r;
    asm("cvt.rna.tf32.f32 %0, %1;" : "=f"(r) : "f"(x));
    return r;
}

template <int MODE>
__global__ void __launch_bounds__(256, 1) gemm_tf32(const float* __restrict__ A,
                                                    const float* __restrict__ W,
                                                    const float* __restrict__ bias,
                                                    const float* __restrict__ extra,
                                                    float* __restrict__ C,
                                                    int M, int N, int K,
                                                    int lda, int ldc)
{
    extern __shared__ float smem[];
    float* As = smem;                    // [2][128][36]
    float* Bs = smem + 2 * GBM * GPAD;   // [2][128][36]

    const int tid  = threadIdx.x;
    const int lane = tid & 31;
    const int w    = tid >> 5;
    const int wm   = (w >> 2) * 64;      // warp m-origin within CTA tile
    const int wn   = (w & 3) * 32;       // warp n-origin
    const int m0   = blockIdx.y * GBM;
    const int n0   = blockIdx.x * GBN;
    const int qr   = lane >> 2;          // quad row 0..7
    const int qc   = lane & 3;           // quad col 0..3

    float acc[4][4][4];
    #pragma unroll
    for (int i = 0; i < 4; i++)
        #pragma unroll
        for (int j = 0; j < 4; j++)
            #pragma unroll
            for (int t = 0; t < 4; t++) acc[i][j][t] = 0.f;

    float2 ra[8], rb[8];

    auto load_stage = [&](int k0) {
        #pragma unroll
        for (int i = 0; i < 8; i++) {
            int c    = tid + i * 256;        // 0..2047 float2 chunks
            int row  = c >> 4;               // 0..127
            int col2 = (c & 15) * 2;         // 0,2,..30
            int gk   = k0 + col2;
            float2 va = make_float2(0.f, 0.f);
            if (gk < K)                      // K even, gk even -> pair valid
                va = *(const float2*)&A[(size_t)(m0 + row) * lda + gk];
            ra[i] = va;
            float2 vb = make_float2(0.f, 0.f);
            int gn = n0 + row;
            if (gk < K && gn < N)
                vb = *(const float2*)&W[(size_t)gn * K + gk];
            rb[i] = vb;
        }
    };

    auto store_stage = [&](int buf) {
        float* as = As + buf * GBM * GPAD;
        float* bs = Bs + buf * GBM * GPAD;
        #pragma unroll
        for (int i = 0; i < 8; i++) {
            int c    = tid + i * 256;
            int row  = c >> 4;
            int col2 = (c & 15) * 2;
            as[row * GPAD + col2]     = tf32_rna(ra[i].x);
            as[row * GPAD + col2 + 1] = tf32_rna(ra[i].y);
            bs[row * GPAD + col2]     = tf32_rna(rb[i].x);
            bs[row * GPAD + col2 + 1] = tf32_rna(rb[i].y);
        }
    };

    auto compute = [&](int buf) {
        const float* as = As + buf * GBM * GPAD;
        const float* bs = Bs + buf * GBM * GPAD;
        #pragma unroll
        for (int kk = 0; kk < 4; kk++) {
            const int kb = kk * 8;
            uint32_t af[4][4], bf[4][2];
            #pragma unroll
            for (int mt = 0; mt < 4; mt++) {
                const float* p = as + (wm + mt * 16 + qr) * GPAD + kb + qc;
                af[mt][0] = __float_as_uint(p[0]);
                af[mt][1] = __float_as_uint(p[8 * GPAD]);
                af[mt][2] = __float_as_uint(p[4]);
                af[mt][3] = __float_as_uint(p[8 * GPAD + 4]);
            }
            #pragma unroll
            for (int nt = 0; nt < 4; nt++) {
                const float* p = bs + (wn + nt * 8 + qr) * GPAD + kb + qc;
                bf[nt][0] = __float_as_uint(p[0]);
                bf[nt][1] = __float_as_uint(p[4]);
            }
            #pragma unroll
            for (int mt = 0; mt < 4; mt++)
                #pragma unroll
                for (int nt = 0; nt < 4; nt++) {
                    asm volatile(
                        "mma.sync.aligned.m16n8k8.row.col.f32.tf32.tf32.f32 "
                        "{%0,%1,%2,%3}, {%4,%5,%6,%7}, {%8,%9}, {%0,%1,%2,%3};"
                        : "+f"(acc[mt][nt][0]), "+f"(acc[mt][nt][1]),
                          "+f"(acc[mt][nt][2]), "+f"(acc[mt][nt][3])
                        : "r"(af[mt][0]), "r"(af[mt][1]),
                          "r"(af[mt][2]), "r"(af[mt][3]),
                          "r"(bf[nt][0]), "r"(bf[nt][1]));
                }
        }
    };

    const int kt = (K + GBK - 1) / GBK;
    load_stage(0);
    store_stage(0);
    __syncthreads();
    for (int t = 0; t < kt; t++) {
        if (t + 1 < kt) load_stage((t + 1) * GBK);
        compute(t & 1);
        if (t + 1 < kt) store_stage((t + 1) & 1);
        __syncthreads();
    }

    // Epilogue
    #pragma unroll
    for (int mt = 0; mt < 4; mt++) {
        int r0 = m0 + wm + mt * 16 + qr;
        int r1 = r0 + 8;
        #pragma unroll
        for (int nt = 0; nt < 4; nt++) {
            int col = n0 + wn + nt * 8 + qc * 2;
            if (col < N) {   // N even, col even -> pair fully in range
                float bv0 = bias[col], bv1 = bias[col + 1];
                float v00 = acc[mt][nt][0] + bv0;
                float v01 = acc[mt][nt][1] + bv1;
                float v10 = acc[mt][nt][2] + bv0;
                float v11 = acc[mt][nt][3] + bv1;
                if (MODE == 1) {
                    v00 = v00 / (1.f + expf(-v00));
                    v01 = v01 / (1.f + expf(-v01));
                    v10 = v10 / (1.f + expf(-v10));
                    v11 = v11 / (1.f + expf(-v11));
                }
                if (MODE == 2 || MODE == 3) {
                    float2 e0 = *(const float2*)&extra[(size_t)r0 * ldc + col];
                    float2 e1 = *(const float2*)&extra[(size_t)r1 * ldc + col];
                    if (MODE == 2) { v00 *= e0.x; v01 *= e0.y; v10 *= e1.x; v11 *= e1.y; }
                    else           { v00 += e0.x; v01 += e0.y; v10 += e1.x; v11 += e1.y; }
                }
                *(float2*)&C[(size_t)r0 * ldc + col] = make_float2(v00, v01);
                *(float2*)&C[(size_t)r1 * ldc + col] = make_float2(v10, v11);
            }
        }
    }
}

// ---------------- RoPE + split/transpose:  qkv[b,s,3D] -> q,k,v [b,h,s,64] --
__global__ void __launch_bounds__(256) rope_split(const float* __restrict__ qkv,
                                                  float* __restrict__ q,
                                                  float* __restrict__ k,
                                                  float* __restrict__ v)
{
    int idx = blockIdx.x * 256 + threadIdx.x;       // B*S*H*32 = 2^21 threads
    int i = idx & 31;                               // rotation pair index
    int h = (idx >> 5) & 15;
    int s = (idx >> 9) & 2047;
    int b = idx >> 20;

    const size_t row = ((size_t)(b * Sq + s)) * (3 * Dq);
    const int off = h * HDq;

    float theta = powf(10000.f, -((float)(2 * i)) / 64.f);
    float sn, cs;
    sincosf((float)s * theta, &sn, &cs);

    float q1 = qkv[row + off + 2*i], q2 = qkv[row + off + 2*i + 1];
    float k1 = qkv[row + Dq + off + 2*i], k2 = qkv[row + Dq + off + 2*i + 1];
    float v1 = qkv[row + 2*Dq + off + 2*i], v2 = qkv[row + 2*Dq + off + 2*i + 1];

    size_t orow = ((size_t)(b * Hq + h) * Sq + s) * HDq;
    q[orow + i]      = q1 * cs - q2 * sn;
    q[orow + 32 + i] = q1 * sn + q2 * cs;
    k[orow + i]      = k1 * cs - k2 * sn;
    k[orow + 32 + i] = k1 * sn + k2 * cs;
    v[orow + 2*i]     = v1;
    v[orow + 2*i + 1] = v2;
}

// ---------------- Causal flash attention (BM=64, BN=32, HD=64, fp32) --------
// Q,K,V: [B,H,S,64]; O written as [B,S,H*64] (ready for out-proj GEMM).
__global__ void __launch_bounds__(256) flash_attn(const float* __restrict__ Q,
                                                  const float* __restrict__ K,
                                                  const float* __restrict__ V,
                                                  float* __restrict__ O)
{
    __shared__ float Qs[64][65];
    __shared__ float KPs[32][65];   // holds K tile, then reused for P^T
    __shared__ float Vs[32][64];

    const int qt = blockIdx.x, h = blockIdx.y, b = blockIdx.z;
    const int qm0 = qt * 64;
    const size_t base = ((size_t)(b * Hq + h)) * Sq * HDq;
    const float* Qb = Q + base;
    const float* Kb = K + base;
    const float* Vb = V + base;

    const int tid = threadIdx.x;
    const int tx = tid & 15, ty = tid >> 4;   // cols tx*2+{0,1}; rows ty*4+{0..3}

    for (int i = tid; i < 64 * 64; i += 256) {
        int r = i >> 6, c = i & 63;
        Qs[r][c] = Qb[(size_t)(qm0 + r) * 64 + c];
    }

    float m_i[4], l_i[4], o[4][4];
    #pragma unroll
    for (int i = 0; i < 4; i++) {
        m_i[i] = -1e30f; l_i[i] = 0.f;
        #pragma unroll
        for (int j = 0; j < 4; j++) o[i][j] = 0.f;
    }

    const int nkt = (qm0 + 64) >> 5;          // causal: key tiles [0, qm0+64)
    for (int kt = 0; kt < nkt; kt++) {
        const int kn0 = kt << 5;
        __syncthreads();                       // prior P/V readers done
        for (int i = tid; i < 32 * 64; i += 256) {
            int r = i >> 6, c = i & 63;
            KPs[r][c] = Kb[(size_t)(kn0 + r) * 64 + c];
            Vs[r][c]  = Vb[(size_t)(kn0 + r) * 64 + c];
        }
        __syncthreads();

        float s[4][2] = {};
        #pragma unroll 4
        for (int kd = 0; kd < 64; kd++) {
            float b0 = KPs[tx*2 + 0][kd];
            float b1 = KPs[tx*2 + 1][kd];
            #pragma unroll
            for (int i = 0; i < 4; i++) {
                float a = Qs[ty*4 + i][kd];
                s[i][0] += a * b0;
                s[i][1] += a * b1;
            }
        }

        float p[4][2];
        #pragma unroll
        for (int i = 0; i < 4; i++) {
            int qi = qm0 + ty*4 + i;
            float s0 = (kn0 + tx*2 + 0 <= qi) ? s[i][0] * 0.125f : -1e30f;
            float s1 = (kn0 + tx*2 + 1 <= qi) ? s[i][1] * 0.125f : -1e30f;
            float mr = fmaxf(s0, s1);
            #pragma unroll
            for (int d = 1; d < 16; d <<= 1)
                mr = fmaxf(mr, __shfl_xor_sync(0xffffffffu, mr, d));
            float mnew  = fmaxf(m_i[i], mr);
            float alpha = expf(m_i[i] - mnew);
            float p0 = expf(s0 - mnew);
            float p1 = expf(s1 - mnew);
            float rs = p0 + p1;
            #pragma unroll
            for (int d = 1; d < 16; d <<= 1)
                rs += __shfl_xor_sync(0xffffffffu, rs, d);
            l_i[i] = l_i[i] * alpha + rs;
            m_i[i] = mnew;
            #pragma unroll
            for (int j = 0; j < 4; j++) o[i][j] *= alpha;
            p[i][0] = p0; p[i][1] = p1;
        }

        __syncthreads();                       // done reading K tile
        #pragma unroll
        for (int i = 0; i < 4; i++) {          // store P^T into KPs[col][row]
            KPs[tx*2 + 0][ty*4 + i] = p[i][0];
            KPs[tx*2 + 1][ty*4 + i] = p[i][1];
        }
        __syncthreads();

        for (int kk = 0; kk < 32; kk++) {      // O += P @ V
            float4 v4 = *(const float4*)&Vs[kk][tx*4];
            #pragma unroll
            for (int i = 0; i < 4; i++) {
                float pr = KPs[kk][ty*4 + i];
                o[i][0] += pr * v4.x; o[i][1] += pr * v4.y;
                o[i][2] += pr * v4.z; o[i][3] += pr * v4.w;
            }
        }
    }

    #pragma unroll
    for (int i = 0; i < 4; i++) {
        int qi = qm0 + ty*4 + i;
        float inv = 1.f / l_i[i];
        size_t orow = ((size_t)(b * Sq + qi)) * Dq + h * HDq + tx * 4;
        O[orow + 0] = o[i][0] * inv;
        O[orow + 1] = o[i][1] * inv;
        O[orow + 2] = o[i][2] * inv;
        O[orow + 3] = o[i][3] * inv;
    }
}

// ---------------- launch --------------------------------------------------
extern "C" void kernel_launch(void* const* d_in, const int* in_sizes, int n_in,
                              void* d_out, int out_size)
{
    const float* x          = (const float*)d_in[0];
    // d_in[1] = mask (tril, causal) — handled analytically in flash_attn
    const float* gamma_attn = (const float*)d_in[2];
    const float* w_qkv      = (const float*)d_in[3];
    const float* b_qkv      = (const float*)d_in[4];
    const float* w_out      = (const float*)d_in[5];
    const float* b_out      = (const float*)d_in[6];
    const float* gamma_ffn  = (const float*)d_in[7];
    const float* w1         = (const float*)d_in[8];
    const float* b1         = (const float*)d_in[9];
    const float* w2         = (const float*)d_in[10];
    const float* b2         = (const float*)d_in[11];
    const float* w3         = (const float*)d_in[12];
    const float* b3         = (const float*)d_in[13];
    float* out = (float*)d_out;

    float *xn, *qkv, *q, *k, *v, *attn, *h, *hn, *ff1, *ff2;
    cudaGetSymbolAddress((void**)&xn,   g_xn);
    cudaGetSymbolAddress((void**)&qkv,  g_qkv);
    cudaGetSymbolAddress((void**)&q,    g_q);
    cudaGetSymbolAddress((void**)&k,    g_k);
    cudaGetSymbolAddress((void**)&v,    g_v);
    cudaGetSymbolAddress((void**)&attn, g_attn);
    cudaGetSymbolAddress((void**)&h,    g_h);
    cudaGetSymbolAddress((void**)&hn,   g_hn);
    cudaGetSymbolAddress((void**)&ff1,  g_ff1);
    cudaGetSymbolAddress((void**)&ff2,  g_ff2);

    const int smem = 4 * GBM * GPAD * (int)sizeof(float);   // 73728 B
    cudaFuncSetAttribute(gemm_tf32<0>, cudaFuncAttributeMaxDynamicSharedMemorySize, smem);
    cudaFuncSetAttribute(gemm_tf32<1>, cudaFuncAttributeMaxDynamicSharedMemorySize, smem);
    cudaFuncSetAttribute(gemm_tf32<2>, cudaFuncAttributeMaxDynamicSharedMemorySize, smem);
    cudaFuncSetAttribute(gemm_tf32<3>, cudaFuncAttributeMaxDynamicSharedMemorySize, smem);

    // 1) xn = rmsnorm(x, gamma_attn)
    rmsnorm_k<<<BSq, 256>>>(x, gamma_attn, xn);

    // 2) qkv = xn @ w_qkv^T + b_qkv            [4096, 3072]
    gemm_tf32<0><<<dim3(3*Dq/128, BSq/128), 256, smem>>>(
        xn, w_qkv, b_qkv, nullptr, qkv, BSq, 3*Dq, Dq, Dq, 3*Dq);

    // 3) rope(q), rope(k), transpose v -> [b,h,s,64]
    rope_split<<<(Bq*Sq*Hq*32)/256, 256>>>(qkv, q, k, v);

    // 4) causal flash attention -> attn [b,s,1024]
    flash_attn<<<dim3(Sq/64, Hq, Bq), 256>>>(q, k, v, attn);

    // 5) h = xn + attn @ w_out^T + b_out
    gemm_tf32<3><<<dim3(Dq/128, BSq/128), 256, smem>>>(
        attn, w_out, b_out, xn, h, BSq, Dq, Dq, Dq, Dq);

    // 6) hn = rmsnorm(h, gamma_ffn)
    rmsnorm_k<<<BSq, 256>>>(h, gamma_ffn, hn);

    // 7) gate = silu(hn @ w2^T + b2)           [4096, 2730] (stride 2736)
    gemm_tf32<1><<<dim3((DIq+127)/128, BSq/128), 256, smem>>>(
        hn, w2, b2, nullptr, ff2, BSq, DIq, Dq, Dq, DIpad);

    // 8) ff = (hn @ w1^T + b1) * gate
    gemm_tf32<2><<<dim3((DIq+127)/128, BSq/128), 256, smem>>>(
        hn, w1, b1, ff2, ff1, BSq, DIq, Dq, Dq, DIpad);

    // 9) out = hn + ff @ w3^T + b3
    gemm_tf32<3><<<dim3(Dq/128, BSq/128), 256, smem>>>(
        ff1, w3, b3, hn, out, BSq, Dq, DIq, DIpad, Dq);
}

// round 5
// speedup vs baseline: 3.5759x; 1.3539x over previous
#include <cuda_runtime.h>
#include <math.h>
#include <stdint.h>

// Problem constants
#define Bq  2
#define Sq  2048
#define Dq  1024
#define Hq  16
#define HDq 64
#define DIq 2730            // int(8/3 * 1024)
#define DIpad 2736          // padded row stride (mult of 16B/float4)
#define BSq (Bq*Sq)         // 4096 rows

// ---------------- scratch (device globals; no allocation allowed) -----------
__device__ float g_xn  [(size_t)BSq*Dq];
__device__ float g_qkv [(size_t)BSq*3*Dq];
__device__ float g_q   [(size_t)Bq*Hq*Sq*HDq];
__device__ float g_k   [(size_t)Bq*Hq*Sq*HDq];
__device__ float g_v   [(size_t)Bq*Hq*Sq*HDq];
__device__ float g_attn[(size_t)BSq*Dq];
__device__ float g_h   [(size_t)BSq*Dq];
__device__ float g_hn  [(size_t)BSq*Dq];
__device__ float g_ff1 [(size_t)BSq*DIpad];
__device__ float g_ff2 [(size_t)BSq*DIpad];

__device__ __forceinline__ float tf32_rna(float x) {
    float r;
    asm("cvt.rna.tf32.f32 %0, %1;" : "=f"(r) : "f"(x));
    return r;
}

// ---------------- RMSNorm: one block per row of 1024 ------------------------
__global__ void __launch_bounds__(256) rmsnorm_k(const float* __restrict__ x,
                                                 const float* __restrict__ gamma,
                                                 float* __restrict__ out)
{
    const size_t row = blockIdx.x;
    const float* xr = x + row * Dq;
    float ss = 0.f;
    for (int c = threadIdx.x; c < Dq; c += 256) { float v = xr[c]; ss += v * v; }
    #pragma unroll
    for (int d = 16; d > 0; d >>= 1) ss += __shfl_xor_sync(0xffffffffu, ss, d);
    __shared__ float red[8];
    __shared__ float s_inv;
    if ((threadIdx.x & 31) == 0) red[threadIdx.x >> 5] = ss;
    __syncthreads();
    if (threadIdx.x == 0) {
        float t = 0.f;
        #pragma unroll
        for (int i = 0; i < 8; i++) t += red[i];
        s_inv = rsqrtf(t / (float)Dq + 1e-5f);
    }
    __syncthreads();
    float* orow = out + row * Dq;
    const float inv = s_inv;
    for (int c = threadIdx.x; c < Dq; c += 256) orow[c] = xr[c] * inv * gamma[c];
}

// ---------------- TF32 tensor-core GEMM:  C[M,N] = A[M,K] @ W[N,K]^T --------
#define GBM 128
#define GBN 128
#define GBK 32
#define GPAD 36

template <int MODE>
__global__ void __launch_bounds__(256, 1) gemm_tf32(const float* __restrict__ A,
                                                    const float* __restrict__ W,
                                                    const float* __restrict__ bias,
                                                    const float* __restrict__ extra,
                                                    float* __restrict__ C,
                                                    int M, int N, int K,
                                                    int lda, int ldc)
{
    extern __shared__ float smem[];
    float* As = smem;                    // [2][128][36]
    float* Bs = smem + 2 * GBM * GPAD;   // [2][128][36]

    const int tid  = threadIdx.x;
    const int lane = tid & 31;
    const int w    = tid >> 5;
    const int wm   = (w >> 2) * 64;
    const int wn   = (w & 3) * 32;
    const int m0   = blockIdx.y * GBM;
    const int n0   = blockIdx.x * GBN;
    const int qr   = lane >> 2;
    const int qc   = lane & 3;

    float acc[4][4][4];
    #pragma unroll
    for (int i = 0; i < 4; i++)
        #pragma unroll
        for (int j = 0; j < 4; j++)
            #pragma unroll
            for (int t = 0; t < 4; t++) acc[i][j][t] = 0.f;

    float2 ra[8], rb[8];

    auto load_stage = [&](int k0) {
        #pragma unroll
        for (int i = 0; i < 8; i++) {
            int c    = tid + i * 256;
            int row  = c >> 4;
            int col2 = (c & 15) * 2;
            int gk   = k0 + col2;
            float2 va = make_float2(0.f, 0.f);
            if (gk < K)
                va = *(const float2*)&A[(size_t)(m0 + row) * lda + gk];
            ra[i] = va;
            float2 vb = make_float2(0.f, 0.f);
            int gn = n0 + row;
            if (gk < K && gn < N)
                vb = *(const float2*)&W[(size_t)gn * K + gk];
            rb[i] = vb;
        }
    };

    auto store_stage = [&](int buf) {
        float* as = As + buf * GBM * GPAD;
        float* bs = Bs + buf * GBM * GPAD;
        #pragma unroll
        for (int i = 0; i < 8; i++) {
            int c    = tid + i * 256;
            int row  = c >> 4;
            int col2 = (c & 15) * 2;
            as[row * GPAD + col2]     = tf32_rna(ra[i].x);
            as[row * GPAD + col2 + 1] = tf32_rna(ra[i].y);
            bs[row * GPAD + col2]     = tf32_rna(rb[i].x);
            bs[row * GPAD + col2 + 1] = tf32_rna(rb[i].y);
        }
    };

    auto compute = [&](int buf) {
        const float* as = As + buf * GBM * GPAD;
        const float* bs = Bs + buf * GBM * GPAD;
        #pragma unroll
        for (int kk = 0; kk < 4; kk++) {
            const int kb = kk * 8;
            uint32_t af[4][4], bf[4][2];
            #pragma unroll
            for (int mt = 0; mt < 4; mt++) {
                const float* p = as + (wm + mt * 16 + qr) * GPAD + kb + qc;
                af[mt][0] = __float_as_uint(p[0]);
                af[mt][1] = __float_as_uint(p[8 * GPAD]);
                af[mt][2] = __float_as_uint(p[4]);
                af[mt][3] = __float_as_uint(p[8 * GPAD + 4]);
            }
            #pragma unroll
            for (int nt = 0; nt < 4; nt++) {
                const float* p = bs + (wn + nt * 8 + qr) * GPAD + kb + qc;
                bf[nt][0] = __float_as_uint(p[0]);
                bf[nt][1] = __float_as_uint(p[4]);
            }
            #pragma unroll
            for (int mt = 0; mt < 4; mt++)
                #pragma unroll
                for (int nt = 0; nt < 4; nt++) {
                    asm volatile(
                        "mma.sync.aligned.m16n8k8.row.col.f32.tf32.tf32.f32 "
                        "{%0,%1,%2,%3}, {%4,%5,%6,%7}, {%8,%9}, {%0,%1,%2,%3};"
                        : "+f"(acc[mt][nt][0]), "+f"(acc[mt][nt][1]),
                          "+f"(acc[mt][nt][2]), "+f"(acc[mt][nt][3])
                        : "r"(af[mt][0]), "r"(af[mt][1]),
                          "r"(af[mt][2]), "r"(af[mt][3]),
                          "r"(bf[nt][0]), "r"(bf[nt][1]));
                }
        }
    };

    const int kt = (K + GBK - 1) / GBK;
    load_stage(0);
    store_stage(0);
    __syncthreads();
    for (int t = 0; t < kt; t++) {
        if (t + 1 < kt) load_stage((t + 1) * GBK);
        compute(t & 1);
        if (t + 1 < kt) store_stage((t + 1) & 1);
        __syncthreads();
    }

    #pragma unroll
    for (int mt = 0; mt < 4; mt++) {
        int r0 = m0 + wm + mt * 16 + qr;
        int r1 = r0 + 8;
        #pragma unroll
        for (int nt = 0; nt < 4; nt++) {
            int col = n0 + wn + nt * 8 + qc * 2;
            if (col < N) {
                float bv0 = bias[col], bv1 = bias[col + 1];
                float v00 = acc[mt][nt][0] + bv0;
                float v01 = acc[mt][nt][1] + bv1;
                float v10 = acc[mt][nt][2] + bv0;
                float v11 = acc[mt][nt][3] + bv1;
                if (MODE == 1) {
                    v00 = v00 / (1.f + expf(-v00));
                    v01 = v01 / (1.f + expf(-v01));
                    v10 = v10 / (1.f + expf(-v10));
                    v11 = v11 / (1.f + expf(-v11));
                }
                if (MODE == 2 || MODE == 3) {
                    float2 e0 = *(const float2*)&extra[(size_t)r0 * ldc + col];
                    float2 e1 = *(const float2*)&extra[(size_t)r1 * ldc + col];
                    if (MODE == 2) { v00 *= e0.x; v01 *= e0.y; v10 *= e1.x; v11 *= e1.y; }
                    else           { v00 += e0.x; v01 += e0.y; v10 += e1.x; v11 += e1.y; }
                }
                *(float2*)&C[(size_t)r0 * ldc + col] = make_float2(v00, v01);
                *(float2*)&C[(size_t)r1 * ldc + col] = make_float2(v10, v11);
            }
        }
    }
}

// ---------------- RoPE + split/transpose:  qkv[b,s,3D] -> q,k,v [b,h,s,64] --
__global__ void __launch_bounds__(256) rope_split(const float* __restrict__ qkv,
                                                  float* __restrict__ q,
                                                  float* __restrict__ k,
                                                  float* __restrict__ v)
{
    int idx = blockIdx.x * 256 + threadIdx.x;
    int i = idx & 31;
    int h = (idx >> 5) & 15;
    int s = (idx >> 9) & 2047;
    int b = idx >> 20;

    const size_t row = ((size_t)(b * Sq + s)) * (3 * Dq);
    const int off = h * HDq;

    float theta = powf(10000.f, -((float)(2 * i)) / 64.f);
    float sn, cs;
    sincosf((float)s * theta, &sn, &cs);

    float q1 = qkv[row + off + 2*i], q2 = qkv[row + off + 2*i + 1];
    float k1 = qkv[row + Dq + off + 2*i], k2 = qkv[row + Dq + off + 2*i + 1];
    float v1 = qkv[row + 2*Dq + off + 2*i], v2 = qkv[row + 2*Dq + off + 2*i + 1];

    size_t orow = ((size_t)(b * Hq + h) * Sq + s) * HDq;
    q[orow + i]      = q1 * cs - q2 * sn;
    q[orow + 32 + i] = q1 * sn + q2 * cs;
    k[orow + i]      = k1 * cs - k2 * sn;
    k[orow + 32 + i] = k1 * sn + k2 * cs;
    v[orow + 2*i]     = v1;
    v[orow + 2*i + 1] = v2;
}

// ---------------- TF32 tensor-core causal flash attention -------------------
// CTA: 128 q-rows, 8 warps (16 rows each). Key tiles of 64. HD = 64.
// Smem: Qs[128][68] + Ks[64][68] + Vt[64][68] (V transposed) + Ps[128][68].
#define FA_BM 128
#define FA_BN 64
#define FPAD 68
#define FA_SMEM ((FA_BM*FPAD + FA_BN*FPAD + FA_BN*FPAD + FA_BM*FPAD) * 4)

__global__ void __launch_bounds__(256, 2) flash_attn_tf32(const float* __restrict__ Q,
                                                          const float* __restrict__ K,
                                                          const float* __restrict__ V,
                                                          float* __restrict__ O)
{
    extern __shared__ float fs[];
    float* Qs = fs;                          // [128][68]
    float* Ks = Qs + FA_BM * FPAD;           // [64][68]
    float* Vt = Ks + FA_BN * FPAD;           // [68*64] as [hd][key]
    float* Ps = Vt + FA_BN * FPAD;           // [128][68]

    const int qt = gridDim.x - 1 - blockIdx.x;   // long CTAs first
    const int h = blockIdx.y, b = blockIdx.z;
    const int qm0 = qt * FA_BM;
    const size_t base = ((size_t)(b * Hq + h)) * Sq * HDq;
    const float* Qb = Q + base;
    const float* Kb = K + base;
    const float* Vb = V + base;

    const int tid  = threadIdx.x;
    const int lane = tid & 31;
    const int w    = tid >> 5;
    const int qr   = lane >> 2;
    const int qc   = lane & 3;
    const int wrow = w * 16;

    // Stage Q once (tf32-rounded)
    for (int i = tid; i < FA_BM * HDq; i += 256) {
        int r = i >> 6, c = i & 63;
        Qs[r * FPAD + c] = tf32_rna(Qb[(size_t)(qm0 + r) * HDq + c]);
    }

    float o[8][4];
    #pragma unroll
    for (int j = 0; j < 8; j++)
        #pragma unroll
        for (int t = 0; t < 4; t++) o[j][t] = 0.f;
    float m0 = -1e30f, m1 = -1e30f, l0 = 0.f, l1 = 0.f;

    const int row0 = qm0 + wrow + qr;
    const int row1 = row0 + 8;
    const int nkt = (qm0 + FA_BM) / FA_BN;

    for (int kt = 0; kt < nkt; kt++) {
        const int kn0 = kt * FA_BN;
        __syncthreads();                     // prev tile's Ks/Vt readers done
        for (int i = tid; i < FA_BN * HDq; i += 256) {
            int r = i >> 6, c = i & 63;
            float kv = Kb[(size_t)(kn0 + r) * HDq + c];
            float vv = Vb[(size_t)(kn0 + r) * HDq + c];
            Ks[r * FPAD + c] = tf32_rna(kv);
            Vt[c * FPAD + r] = tf32_rna(vv);
        }
        __syncthreads();

        const bool active = (kn0 <= qm0 + wrow + 15);
        if (active) {
            // ---- S = Q @ K^T (warp's 16 rows x 64 keys) ----
            float s[8][4];
            #pragma unroll
            for (int j = 0; j < 8; j++)
                #pragma unroll
                for (int t = 0; t < 4; t++) s[j][t] = 0.f;

            #pragma unroll
            for (int kb = 0; kb < 64; kb += 8) {
                const float* ap = Qs + (wrow + qr) * FPAD + kb + qc;
                uint32_t a0 = __float_as_uint(ap[0]);
                uint32_t a1 = __float_as_uint(ap[8 * FPAD]);
                uint32_t a2 = __float_as_uint(ap[4]);
                uint32_t a3 = __float_as_uint(ap[8 * FPAD + 4]);
                #pragma unroll
                for (int j = 0; j < 8; j++) {
                    const float* bp = Ks + (j * 8 + qr) * FPAD + kb + qc;
                    uint32_t b0 = __float_as_uint(bp[0]);
                    uint32_t b1 = __float_as_uint(bp[4]);
                    asm volatile(
                        "mma.sync.aligned.m16n8k8.row.col.f32.tf32.tf32.f32 "
                        "{%0,%1,%2,%3}, {%4,%5,%6,%7}, {%8,%9}, {%0,%1,%2,%3};"
                        : "+f"(s[j][0]), "+f"(s[j][1]), "+f"(s[j][2]), "+f"(s[j][3])
                        : "r"(a0), "r"(a1), "r"(a2), "r"(a3), "r"(b0), "r"(b1));
                }
            }

            // ---- causal mask + online softmax ----
            float rmax0 = -1e30f, rmax1 = -1e30f;
            #pragma unroll
            for (int j = 0; j < 8; j++) {
                int c0 = kn0 + j * 8 + 2 * qc, c1 = c0 + 1;
                s[j][0] = (c0 <= row0) ? s[j][0] * 0.125f : -1e30f;
                s[j][1] = (c1 <= row0) ? s[j][1] * 0.125f : -1e30f;
                s[j][2] = (c0 <= row1) ? s[j][2] * 0.125f : -1e30f;
                s[j][3] = (c1 <= row1) ? s[j][3] * 0.125f : -1e30f;
                rmax0 = fmaxf(rmax0, fmaxf(s[j][0], s[j][1]));
                rmax1 = fmaxf(rmax1, fmaxf(s[j][2], s[j][3]));
            }
            rmax0 = fmaxf(rmax0, __shfl_xor_sync(0xffffffffu, rmax0, 1));
            rmax0 = fmaxf(rmax0, __shfl_xor_sync(0xffffffffu, rmax0, 2));
            rmax1 = fmaxf(rmax1, __shfl_xor_sync(0xffffffffu, rmax1, 1));
            rmax1 = fmaxf(rmax1, __shfl_xor_sync(0xffffffffu, rmax1, 2));

            float mn0 = fmaxf(m0, rmax0), mn1 = fmaxf(m1, rmax1);
            float a0 = __expf(m0 - mn0),  a1 = __expf(m1 - mn1);
            // (masked rows in later tiles: m already finite since key 0 is
            //  always visible; exp(-1e30 - finite) underflows to exactly 0)
            float rs0 = 0.f, rs1 = 0.f;
            float* pr0 = Ps + (wrow + qr) * FPAD;
            float* pr1 = pr0 + 8 * FPAD;
            #pragma unroll
            for (int j = 0; j < 8; j++) {
                float p00 = tf32_rna(__expf(s[j][0] - mn0));
                float p01 = tf32_rna(__expf(s[j][1] - mn0));
                float p10 = tf32_rna(__expf(s[j][2] - mn1));
                float p11 = tf32_rna(__expf(s[j][3] - mn1));
                rs0 += p00 + p01;
                rs1 += p10 + p11;
                *(float2*)&pr0[j * 8 + 2 * qc] = make_float2(p00, p01);
                *(float2*)&pr1[j * 8 + 2 * qc] = make_float2(p10, p11);
            }
            rs0 += __shfl_xor_sync(0xffffffffu, rs0, 1);
            rs0 += __shfl_xor_sync(0xffffffffu, rs0, 2);
            rs1 += __shfl_xor_sync(0xffffffffu, rs1, 1);
            rs1 += __shfl_xor_sync(0xffffffffu, rs1, 2);

            l0 = l0 * a0 + rs0; m0 = mn0;
            l1 = l1 * a1 + rs1; m1 = mn1;
            #pragma unroll
            for (int j = 0; j < 8; j++) {
                o[j][0] *= a0; o[j][1] *= a0;
                o[j][2] *= a1; o[j][3] *= a1;
            }
            __syncwarp();      // P visible to whole warp before fragment loads

            // ---- O += P @ V (A from Ps own rows, B from Vt) ----
            #pragma unroll
            for (int kb = 0; kb < 64; kb += 8) {
                const float* ap = Ps + (wrow + qr) * FPAD + kb + qc;
                uint32_t a0f = __float_as_uint(ap[0]);
                uint32_t a1f = __float_as_uint(ap[8 * FPAD]);
                uint32_t a2f = __float_as_uint(ap[4]);
                uint32_t a3f = __float_as_uint(ap[8 * FPAD + 4]);
                #pragma unroll
                for (int j = 0; j < 8; j++) {
                    const float* bp = Vt + (j * 8 + qr) * FPAD + kb + qc;
                    uint32_t b0 = __float_as_uint(bp[0]);
                    uint32_t b1 = __float_as_uint(bp[4]);
                    asm volatile(
                        "mma.sync.aligned.m16n8k8.row.col.f32.tf32.tf32.f32 "
                        "{%0,%1,%2,%3}, {%4,%5,%6,%7}, {%8,%9}, {%0,%1,%2,%3};"
                        : "+f"(o[j][0]), "+f"(o[j][1]), "+f"(o[j][2]), "+f"(o[j][3])
                        : "r"(a0f), "r"(a1f), "r"(a2f), "r"(a3f), "r"(b0), "r"(b1));
                }
            }
        }
    }

    // ---- normalize + write O as [b, s, h*64 + c] ----
    float inv0 = 1.f / l0, inv1 = 1.f / l1;
    #pragma unroll
    for (int j = 0; j < 8; j++) {
        int col = h * HDq + j * 8 + 2 * qc;
        size_t o0 = ((size_t)(b * Sq + row0)) * Dq + col;
        size_t o1 = ((size_t)(b * Sq + row1)) * Dq + col;
        *(float2*)&O[o0] = make_float2(o[j][0] * inv0, o[j][1] * inv0);
        *(float2*)&O[o1] = make_float2(o[j][2] * inv1, o[j][3] * inv1);
    }
}

// ---------------- launch --------------------------------------------------
extern "C" void kernel_launch(void* const* d_in, const int* in_sizes, int n_in,
                              void* d_out, int out_size)
{
    const float* x          = (const float*)d_in[0];
    const float* gamma_attn = (const float*)d_in[2];
    const float* w_qkv      = (const float*)d_in[3];
    const float* b_qkv      = (const float*)d_in[4];
    const float* w_out      = (const float*)d_in[5];
    const float* b_out      = (const float*)d_in[6];
    const float* gamma_ffn  = (const float*)d_in[7];
    const float* w1         = (const float*)d_in[8];
    const float* b1         = (const float*)d_in[9];
    const float* w2         = (const float*)d_in[10];
    const float* b2         = (const float*)d_in[11];
    const float* w3         = (const float*)d_in[12];
    const float* b3         = (const float*)d_in[13];
    float* out = (float*)d_out;

    float *xn, *qkv, *q, *k, *v, *attn, *h, *hn, *ff1, *ff2;
    cudaGetSymbolAddress((void**)&xn,   g_xn);
    cudaGetSymbolAddress((void**)&qkv,  g_qkv);
    cudaGetSymbolAddress((void**)&q,    g_q);
    cudaGetSymbolAddress((void**)&k,    g_k);
    cudaGetSymbolAddress((void**)&v,    g_v);
    cudaGetSymbolAddress((void**)&attn, g_attn);
    cudaGetSymbolAddress((void**)&h,    g_h);
    cudaGetSymbolAddress((void**)&hn,   g_hn);
    cudaGetSymbolAddress((void**)&ff1,  g_ff1);
    cudaGetSymbolAddress((void**)&ff2,  g_ff2);

    const int smem = 4 * GBM * GPAD * (int)sizeof(float);   // 73728 B
    cudaFuncSetAttribute(gemm_tf32<0>, cudaFuncAttributeMaxDynamicSharedMemorySize, smem);
    cudaFuncSetAttribute(gemm_tf32<1>, cudaFuncAttributeMaxDynamicSharedMemorySize, smem);
    cudaFuncSetAttribute(gemm_tf32<2>, cudaFuncAttributeMaxDynamicSharedMemorySize, smem);
    cudaFuncSetAttribute(gemm_tf32<3>, cudaFuncAttributeMaxDynamicSharedMemorySize, smem);
    cudaFuncSetAttribute(flash_attn_tf32, cudaFuncAttributeMaxDynamicSharedMemorySize, FA_SMEM);

    // 1) xn = rmsnorm(x, gamma_attn)
    rmsnorm_k<<<BSq, 256>>>(x, gamma_attn, xn);

    // 2) qkv = xn @ w_qkv^T + b_qkv            [4096, 3072]
    gemm_tf32<0><<<dim3(3*Dq/128, BSq/128), 256, smem>>>(
        xn, w_qkv, b_qkv, nullptr, qkv, BSq, 3*Dq, Dq, Dq, 3*Dq);

    // 3) rope(q), rope(k), transpose v -> [b,h,s,64]
    rope_split<<<(Bq*Sq*Hq*32)/256, 256>>>(qkv, q, k, v);

    // 4) causal flash attention (tensor cores) -> attn [b,s,1024]
    flash_attn_tf32<<<dim3(Sq/FA_BM, Hq, Bq), 256, FA_SMEM>>>(q, k, v, attn);

    // 5) h = xn + attn @ w_out^T + b_out
    gemm_tf32<3><<<dim3(Dq/128, BSq/128), 256, smem>>>(
        attn, w_out, b_out, xn, h, BSq, Dq, Dq, Dq, Dq);

    // 6) hn = rmsnorm(h, gamma_ffn)
    rmsnorm_k<<<BSq, 256>>>(h, gamma_ffn, hn);

    // 7) gate = silu(hn @ w2^T + b2)           [4096, 2730] (stride 2736)
    gemm_tf32<1><<<dim3((DIq+127)/128, BSq/128), 256, smem>>>(
        hn, w2, b2, nullptr, ff2, BSq, DIq, Dq, Dq, DIpad);

    // 8) ff = (hn @ w1^T + b1) * gate
    gemm_tf32<2><<<dim3((DIq+127)/128, BSq/128), 256, smem>>>(
        hn, w1, b1, ff2, ff1, BSq, DIq, Dq, Dq, DIpad);

    // 9) out = hn + ff @ w3^T + b3
    gemm_tf32<3><<<dim3(Dq/128, BSq/128), 256, smem>>>(
        ff1, w3, b3, hn, out, BSq, Dq, DIq, DIpad, Dq);
}

// round 6
// speedup vs baseline: 4.4800x; 1.2528x over previous
#include <cuda_runtime.h>
#include <math.h>
#include <stdint.h>

// Problem constants
#define Bq  2
#define Sq  2048
#define Dq  1024
#define Hq  16
#define HDq 64
#define DIq 2730            // int(8/3 * 1024)
#define DIpad 2736          // padded row stride
#define BSq (Bq*Sq)         // 4096 rows

// ---------------- scratch (device globals; no allocation allowed) -----------
__device__ float g_xn  [(size_t)BSq*Dq];
__device__ float g_xnr [(size_t)BSq*Dq];      // tf32-rounded xn
__device__ float g_qkv [(size_t)BSq*3*Dq];
__device__ float g_q   [(size_t)Bq*Hq*Sq*HDq];
__device__ float g_k   [(size_t)Bq*Hq*Sq*HDq];
__device__ float g_v   [(size_t)Bq*Hq*Sq*HDq];
__device__ float g_attn[(size_t)BSq*Dq];      // rounded at flash epilogue
__device__ float g_h   [(size_t)BSq*Dq];
__device__ float g_hn  [(size_t)BSq*Dq];
__device__ float g_hnr [(size_t)BSq*Dq];      // tf32-rounded hn
__device__ float g_ff1 [(size_t)BSq*DIpad];   // rounded at producer epilogue
__device__ float g_ff2 [(size_t)BSq*DIpad];
// tf32-rounded weight copies
__device__ float g_wqkv[(size_t)3*Dq*Dq];
__device__ float g_wout[(size_t)Dq*Dq];
__device__ float g_w1  [(size_t)DIq*Dq];
__device__ float g_w2  [(size_t)DIq*Dq];
__device__ float g_w3  [(size_t)Dq*DIq];

__device__ __forceinline__ float tf32_rna(float x) {
    float r;
    asm("cvt.rna.tf32.f32 %0, %1;" : "=f"(r) : "f"(x));
    return r;
}

// ---------------- weight pre-rounding (float4 vectorized) -------------------
__global__ void __launch_bounds__(256) round_copy(const float* __restrict__ src,
                                                  float* __restrict__ dst, int n4)
{
    int i = blockIdx.x * 256 + threadIdx.x;
    if (i < n4) {
        float4 v = ((const float4*)src)[i];
        v.x = tf32_rna(v.x); v.y = tf32_rna(v.y);
        v.z = tf32_rna(v.z); v.w = tf32_rna(v.w);
        ((float4*)dst)[i] = v;
    }
}

// ---------------- RMSNorm: one block per row; dual output (full + tf32) -----
__global__ void __launch_bounds__(256) rmsnorm_k(const float* __restrict__ x,
                                                 const float* __restrict__ gamma,
                                                 float* __restrict__ out,
                                                 float* __restrict__ out_r)
{
    const size_t row = blockIdx.x;
    const float* xr = x + row * Dq;
    float ss = 0.f;
    for (int c = threadIdx.x; c < Dq; c += 256) { float v = xr[c]; ss += v * v; }
    #pragma unroll
    for (int d = 16; d > 0; d >>= 1) ss += __shfl_xor_sync(0xffffffffu, ss, d);
    __shared__ float red[8];
    __shared__ float s_inv;
    if ((threadIdx.x & 31) == 0) red[threadIdx.x >> 5] = ss;
    __syncthreads();
    if (threadIdx.x == 0) {
        float t = 0.f;
        #pragma unroll
        for (int i = 0; i < 8; i++) t += red[i];
        s_inv = rsqrtf(t / (float)Dq + 1e-5f);
    }
    __syncthreads();
    const float inv = s_inv;
    for (int c = threadIdx.x; c < Dq; c += 256) {
        float v = xr[c] * inv * gamma[c];
        out[row * Dq + c]   = v;
        out_r[row * Dq + c] = tf32_rna(v);
    }
}

// ---------------- cp.async helpers ------------------------------------------
__device__ __forceinline__ void cp8(uint32_t dst, const void* src, bool pred) {
    int sz = pred ? 8 : 0;
    asm volatile("cp.async.ca.shared.global [%0], [%1], 8, %2;"
                 :: "r"(dst), "l"(src), "r"(sz));
}
__device__ __forceinline__ void cp_commit() {
    asm volatile("cp.async.commit_group;");
}
template <int N>
__device__ __forceinline__ void cp_wait() {
    asm volatile("cp.async.wait_group %0;" :: "n"(N));
}

// ---------------- TF32 GEMM, cp.async 3-stage:  C = A @ W^T -----------------
// Operands MUST already be tf32-rounded.
// MODE 0: +bias | 1: silu(+bias) | 2: (+bias)*extra | 3: (+bias)+extra
// RND 1: round output to tf32 (for outputs feeding another GEMM)
#define GBM 128
#define GBN 128
#define GBK 32
#define GPAD 36
#define GSTG 3
#define GSTAGE_F (GBM * GPAD)

template <int MODE, int RND>
__global__ void __launch_bounds__(256, 1) gemm_tf32(const float* __restrict__ A,
                                                    const float* __restrict__ W,
                                                    const float* __restrict__ bias,
                                                    const float* __restrict__ extra,
                                                    float* __restrict__ C,
                                                    int M, int N, int K,
                                                    int lda, int ldc)
{
    extern __shared__ float smem[];
    float* As = smem;                        // [GSTG][128][36]
    float* Bs = smem + GSTG * GSTAGE_F;      // [GSTG][128][36]

    const int tid  = threadIdx.x;
    const int lane = tid & 31;
    const int w    = tid >> 5;
    const int wm   = (w >> 2) * 64;
    const int wn   = (w & 3) * 32;
    const int m0   = blockIdx.y * GBM;
    const int n0   = blockIdx.x * GBN;
    const int qr   = lane >> 2;
    const int qc   = lane & 3;

    const uint32_t sA = (uint32_t)__cvta_generic_to_shared(As);
    const uint32_t sB = (uint32_t)__cvta_generic_to_shared(Bs);

    float acc[4][4][4];
    #pragma unroll
    for (int i = 0; i < 4; i++)
        #pragma unroll
        for (int j = 0; j < 4; j++)
            #pragma unroll
            for (int t = 0; t < 4; t++) acc[i][j][t] = 0.f;

    const int kt = (K + GBK - 1) / GBK;

    auto issue_stage = [&](int t, int buf) {
        const int k0 = t * GBK;
        const uint32_t aOff = sA + buf * GSTAGE_F * 4;
        const uint32_t bOff = sB + buf * GSTAGE_F * 4;
        #pragma unroll
        for (int i = 0; i < 8; i++) {
            int c    = tid + i * 256;
            int row  = c >> 4;
            int col2 = (c & 15) * 2;
            int gk   = k0 + col2;
            bool pk  = (gk < K);
            cp8(aOff + (row * GPAD + col2) * 4,
                &A[(size_t)(m0 + row) * lda + gk], pk);
            int gn = n0 + row;
            cp8(bOff + (row * GPAD + col2) * 4,
                &W[(size_t)gn * K + gk], pk && (gn < N));
        }
        cp_commit();
    };

    auto compute = [&](int buf) {
        const float* as = As + buf * GSTAGE_F;
        const float* bs = Bs + buf * GSTAGE_F;
        #pragma unroll
        for (int kk = 0; kk < 4; kk++) {
            const int kb = kk * 8;
            uint32_t af[4][4], bf[4][2];
            #pragma unroll
            for (int mt = 0; mt < 4; mt++) {
                const float* p = as + (wm + mt * 16 + qr) * GPAD + kb + qc;
                af[mt][0] = __float_as_uint(p[0]);
                af[mt][1] = __float_as_uint(p[8 * GPAD]);
                af[mt][2] = __float_as_uint(p[4]);
                af[mt][3] = __float_as_uint(p[8 * GPAD + 4]);
            }
            #pragma unroll
            for (int nt = 0; nt < 4; nt++) {
                const float* p = bs + (wn + nt * 8 + qr) * GPAD + kb + qc;
                bf[nt][0] = __float_as_uint(p[0]);
                bf[nt][1] = __float_as_uint(p[4]);
            }
            #pragma unroll
            for (int mt = 0; mt < 4; mt++)
                #pragma unroll
                for (int nt = 0; nt < 4; nt++) {
                    asm volatile(
                        "mma.sync.aligned.m16n8k8.row.col.f32.tf32.tf32.f32 "
                        "{%0,%1,%2,%3}, {%4,%5,%6,%7}, {%8,%9}, {%0,%1,%2,%3};"
                        : "+f"(acc[mt][nt][0]), "+f"(acc[mt][nt][1]),
                          "+f"(acc[mt][nt][2]), "+f"(acc[mt][nt][3])
                        : "r"(af[mt][0]), "r"(af[mt][1]),
                          "r"(af[mt][2]), "r"(af[mt][3]),
                          "r"(bf[nt][0]), "r"(bf[nt][1]));
                }
        }
    };

    // Prefetch
    const int pre = (kt < GSTG) ? kt : GSTG;
    for (int t = 0; t < pre; t++) issue_stage(t, t);

    for (int t = 0; t < kt; t++) {
        cp_wait<GSTG - 1>();          // stage t landed
        __syncthreads();
        compute(t % GSTG);
        __syncthreads();              // all warps done reading stage t
        if (t + GSTG < kt) issue_stage(t + GSTG, t % GSTG);
    }

    // Epilogue
    #pragma unroll
    for (int mt = 0; mt < 4; mt++) {
        int r0 = m0 + wm + mt * 16 + qr;
        int r1 = r0 + 8;
        #pragma unroll
        for (int nt = 0; nt < 4; nt++) {
            int col = n0 + wn + nt * 8 + qc * 2;
            if (col < N) {
                float bv0 = bias[col], bv1 = bias[col + 1];
                float v00 = acc[mt][nt][0] + bv0;
                float v01 = acc[mt][nt][1] + bv1;
                float v10 = acc[mt][nt][2] + bv0;
                float v11 = acc[mt][nt][3] + bv1;
                if (MODE == 1) {
                    v00 = v00 / (1.f + expf(-v00));
                    v01 = v01 / (1.f + expf(-v01));
                    v10 = v10 / (1.f + expf(-v10));
                    v11 = v11 / (1.f + expf(-v11));
                }
                if (MODE == 2 || MODE == 3) {
                    float2 e0 = *(const float2*)&extra[(size_t)r0 * ldc + col];
                    float2 e1 = *(const float2*)&extra[(size_t)r1 * ldc + col];
                    if (MODE == 2) { v00 *= e0.x; v01 *= e0.y; v10 *= e1.x; v11 *= e1.y; }
                    else           { v00 += e0.x; v01 += e0.y; v10 += e1.x; v11 += e1.y; }
                }
                if (RND) {
                    v00 = tf32_rna(v00); v01 = tf32_rna(v01);
                    v10 = tf32_rna(v10); v11 = tf32_rna(v11);
                }
                *(float2*)&C[(size_t)r0 * ldc + col] = make_float2(v00, v01);
                *(float2*)&C[(size_t)r1 * ldc + col] = make_float2(v10, v11);
            }
        }
    }
}

// ---------------- RoPE + split/transpose ------------------------------------
__global__ void __launch_bounds__(256) rope_split(const float* __restrict__ qkv,
                                                  float* __restrict__ q,
                                                  float* __restrict__ k,
                                                  float* __restrict__ v)
{
    int idx = blockIdx.x * 256 + threadIdx.x;
    int i = idx & 31;
    int h = (idx >> 5) & 15;
    int s = (idx >> 9) & 2047;
    int b = idx >> 20;

    const size_t row = ((size_t)(b * Sq + s)) * (3 * Dq);
    const int off = h * HDq;

    float theta = powf(10000.f, -((float)(2 * i)) / 64.f);
    float sn, cs;
    sincosf((float)s * theta, &sn, &cs);

    float q1 = qkv[row + off + 2*i], q2 = qkv[row + off + 2*i + 1];
    float k1 = qkv[row + Dq + off + 2*i], k2 = qkv[row + Dq + off + 2*i + 1];
    float v1 = qkv[row + 2*Dq + off + 2*i], v2 = qkv[row + 2*Dq + off + 2*i + 1];

    size_t orow = ((size_t)(b * Hq + h) * Sq + s) * HDq;
    q[orow + i]      = q1 * cs - q2 * sn;
    q[orow + 32 + i] = q1 * sn + q2 * cs;
    k[orow + i]      = k1 * cs - k2 * sn;
    k[orow + 32 + i] = k1 * sn + k2 * cs;
    v[orow + 2*i]     = v1;
    v[orow + 2*i + 1] = v2;
}

// ---------------- TF32 tensor-core causal flash attention -------------------
#define FA_BM 128
#define FA_BN 64
#define FPAD 68
#define FA_SMEM ((FA_BM*FPAD + FA_BN*FPAD + FA_BN*FPAD + FA_BM*FPAD) * 4)

__global__ void __launch_bounds__(256, 2) flash_attn_tf32(const float* __restrict__ Q,
                                                          const float* __restrict__ K,
                                                          const float* __restrict__ V,
                                                          float* __restrict__ O)
{
    extern __shared__ float fs[];
    float* Qs = fs;
    float* Ks = Qs + FA_BM * FPAD;
    float* Vt = Ks + FA_BN * FPAD;
    float* Ps = Vt + FA_BN * FPAD;

    const int qt = gridDim.x - 1 - blockIdx.x;
    const int h = blockIdx.y, b = blockIdx.z;
    const int qm0 = qt * FA_BM;
    const size_t base = ((size_t)(b * Hq + h)) * Sq * HDq;
    const float* Qb = Q + base;
    const float* Kb = K + base;
    const float* Vb = V + base;

    const int tid  = threadIdx.x;
    const int lane = tid & 31;
    const int w    = tid >> 5;
    const int qr   = lane >> 2;
    const int qc   = lane & 3;
    const int wrow = w * 16;

    for (int i = tid; i < FA_BM * HDq; i += 256) {
        int r = i >> 6, c = i & 63;
        Qs[r * FPAD + c] = tf32_rna(Qb[(size_t)(qm0 + r) * HDq + c]);
    }

    float o[8][4];
    #pragma unroll
    for (int j = 0; j < 8; j++)
        #pragma unroll
        for (int t = 0; t < 4; t++) o[j][t] = 0.f;
    float m0 = -1e30f, m1 = -1e30f, l0 = 0.f, l1 = 0.f;

    const int row0 = qm0 + wrow + qr;
    const int row1 = row0 + 8;
    const int nkt = (qm0 + FA_BM) / FA_BN;

    for (int kt = 0; kt < nkt; kt++) {
        const int kn0 = kt * FA_BN;
        __syncthreads();
        for (int i = tid; i < FA_BN * HDq; i += 256) {
            int r = i >> 6, c = i & 63;
            float kv = Kb[(size_t)(kn0 + r) * HDq + c];
            float vv = Vb[(size_t)(kn0 + r) * HDq + c];
            Ks[r * FPAD + c] = tf32_rna(kv);
            Vt[c * FPAD + r] = tf32_rna(vv);
        }
        __syncthreads();

        const bool active = (kn0 <= qm0 + wrow + 15);
        if (active) {
            float s[8][4];
            #pragma unroll
            for (int j = 0; j < 8; j++)
                #pragma unroll
                for (int t = 0; t < 4; t++) s[j][t] = 0.f;

            #pragma unroll
            for (int kb = 0; kb < 64; kb += 8) {
                const float* ap = Qs + (wrow + qr) * FPAD + kb + qc;
                uint32_t a0 = __float_as_uint(ap[0]);
                uint32_t a1 = __float_as_uint(ap[8 * FPAD]);
                uint32_t a2 = __float_as_uint(ap[4]);
                uint32_t a3 = __float_as_uint(ap[8 * FPAD + 4]);
                #pragma unroll
                for (int j = 0; j < 8; j++) {
                    const float* bp = Ks + (j * 8 + qr) * FPAD + kb + qc;
                    uint32_t b0 = __float_as_uint(bp[0]);
                    uint32_t b1 = __float_as_uint(bp[4]);
                    asm volatile(
                        "mma.sync.aligned.m16n8k8.row.col.f32.tf32.tf32.f32 "
                        "{%0,%1,%2,%3}, {%4,%5,%6,%7}, {%8,%9}, {%0,%1,%2,%3};"
                        : "+f"(s[j][0]), "+f"(s[j][1]), "+f"(s[j][2]), "+f"(s[j][3])
                        : "r"(a0), "r"(a1), "r"(a2), "r"(a3), "r"(b0), "r"(b1));
                }
            }

            float rmax0 = -1e30f, rmax1 = -1e30f;
            #pragma unroll
            for (int j = 0; j < 8; j++) {
                int c0 = kn0 + j * 8 + 2 * qc, c1 = c0 + 1;
                s[j][0] = (c0 <= row0) ? s[j][0] * 0.125f : -1e30f;
                s[j][1] = (c1 <= row0) ? s[j][1] * 0.125f : -1e30f;
                s[j][2] = (c0 <= row1) ? s[j][2] * 0.125f : -1e30f;
                s[j][3] = (c1 <= row1) ? s[j][3] * 0.125f : -1e30f;
                rmax0 = fmaxf(rmax0, fmaxf(s[j][0], s[j][1]));
                rmax1 = fmaxf(rmax1, fmaxf(s[j][2], s[j][3]));
            }
            rmax0 = fmaxf(rmax0, __shfl_xor_sync(0xffffffffu, rmax0, 1));
            rmax0 = fmaxf(rmax0, __shfl_xor_sync(0xffffffffu, rmax0, 2));
            rmax1 = fmaxf(rmax1, __shfl_xor_sync(0xffffffffu, rmax1, 1));
            rmax1 = fmaxf(rmax1, __shfl_xor_sync(0xffffffffu, rmax1, 2));

            float mn0 = fmaxf(m0, rmax0), mn1 = fmaxf(m1, rmax1);
            float a0 = __expf(m0 - mn0),  a1 = __expf(m1 - mn1);
            float rs0 = 0.f, rs1 = 0.f;
            float* pr0 = Ps + (wrow + qr) * FPAD;
            float* pr1 = pr0 + 8 * FPAD;
            #pragma unroll
            for (int j = 0; j < 8; j++) {
                float p00 = tf32_rna(__expf(s[j][0] - mn0));
                float p01 = tf32_rna(__expf(s[j][1] - mn0));
                float p10 = tf32_rna(__expf(s[j][2] - mn1));
                float p11 = tf32_rna(__expf(s[j][3] - mn1));
                rs0 += p00 + p01;
                rs1 += p10 + p11;
                *(float2*)&pr0[j * 8 + 2 * qc] = make_float2(p00, p01);
                *(float2*)&pr1[j * 8 + 2 * qc] = make_float2(p10, p11);
            }
            rs0 += __shfl_xor_sync(0xffffffffu, rs0, 1);
            rs0 += __shfl_xor_sync(0xffffffffu, rs0, 2);
            rs1 += __shfl_xor_sync(0xffffffffu, rs1, 1);
            rs1 += __shfl_xor_sync(0xffffffffu, rs1, 2);

            l0 = l0 * a0 + rs0; m0 = mn0;
            l1 = l1 * a1 + rs1; m1 = mn1;
            #pragma unroll
            for (int j = 0; j < 8; j++) {
                o[j][0] *= a0; o[j][1] *= a0;
                o[j][2] *= a1; o[j][3] *= a1;
            }
            __syncwarp();

            #pragma unroll
            for (int kb = 0; kb < 64; kb += 8) {
                const float* ap = Ps + (wrow + qr) * FPAD + kb + qc;
                uint32_t a0f = __float_as_uint(ap[0]);
                uint32_t a1f = __float_as_uint(ap[8 * FPAD]);
                uint32_t a2f = __float_as_uint(ap[4]);
                uint32_t a3f = __float_as_uint(ap[8 * FPAD + 4]);
                #pragma unroll
                for (int j = 0; j < 8; j++) {
                    const float* bp = Vt + (j * 8 + qr) * FPAD + kb + qc;
                    uint32_t b0 = __float_as_uint(bp[0]);
                    uint32_t b1 = __float_as_uint(bp[4]);
                    asm volatile(
                        "mma.sync.aligned.m16n8k8.row.col.f32.tf32.tf32.f32 "
                        "{%0,%1,%2,%3}, {%4,%5,%6,%7}, {%8,%9}, {%0,%1,%2,%3};"
                        : "+f"(o[j][0]), "+f"(o[j][1]), "+f"(o[j][2]), "+f"(o[j][3])
                        : "r"(a0f), "r"(a1f), "r"(a2f), "r"(a3f), "r"(b0), "r"(b1));
                }
            }
        }
    }

    // normalize + tf32-round (output feeds out-proj GEMM directly)
    float inv0 = 1.f / l0, inv1 = 1.f / l1;
    #pragma unroll
    for (int j = 0; j < 8; j++) {
        int col = h * HDq + j * 8 + 2 * qc;
        size_t o0 = ((size_t)(b * Sq + row0)) * Dq + col;
        size_t o1 = ((size_t)(b * Sq + row1)) * Dq + col;
        *(float2*)&O[o0] = make_float2(tf32_rna(o[j][0] * inv0), tf32_rna(o[j][1] * inv0));
        *(float2*)&O[o1] = make_float2(tf32_rna(o[j][2] * inv1), tf32_rna(o[j][3] * inv1));
    }
}

// ---------------- launch --------------------------------------------------
extern "C" void kernel_launch(void* const* d_in, const int* in_sizes, int n_in,
                              void* d_out, int out_size)
{
    const float* x          = (const float*)d_in[0];
    const float* gamma_attn = (const float*)d_in[2];
    const float* w_qkv      = (const float*)d_in[3];
    const float* b_qkv      = (const float*)d_in[4];
    const float* w_out      = (const float*)d_in[5];
    const float* b_out      = (const float*)d_in[6];
    const float* gamma_ffn  = (const float*)d_in[7];
    const float* w1         = (const float*)d_in[8];
    const float* b1         = (const float*)d_in[9];
    const float* w2         = (const float*)d_in[10];
    const float* b2         = (const float*)d_in[11];
    const float* w3         = (const float*)d_in[12];
    const float* b3         = (const float*)d_in[13];
    float* out = (float*)d_out;

    float *xn, *xnr, *qkv, *q, *k, *v, *attn, *h, *hn, *hnr, *ff1, *ff2;
    float *wqkv_r, *wout_r, *w1_r, *w2_r, *w3_r;
    cudaGetSymbolAddress((void**)&xn,   g_xn);
    cudaGetSymbolAddress((void**)&xnr,  g_xnr);
    cudaGetSymbolAddress((void**)&qkv,  g_qkv);
    cudaGetSymbolAddress((void**)&q,    g_q);
    cudaGetSymbolAddress((void**)&k,    g_k);
    cudaGetSymbolAddress((void**)&v,    g_v);
    cudaGetSymbolAddress((void**)&attn, g_attn);
    cudaGetSymbolAddress((void**)&h,    g_h);
    cudaGetSymbolAddress((void**)&hn,   g_hn);
    cudaGetSymbolAddress((void**)&hnr,  g_hnr);
    cudaGetSymbolAddress((void**)&ff1,  g_ff1);
    cudaGetSymbolAddress((void**)&ff2,  g_ff2);
    cudaGetSymbolAddress((void**)&wqkv_r, g_wqkv);
    cudaGetSymbolAddress((void**)&wout_r, g_wout);
    cudaGetSymbolAddress((void**)&w1_r,   g_w1);
    cudaGetSymbolAddress((void**)&w2_r,   g_w2);
    cudaGetSymbolAddress((void**)&w3_r,   g_w3);

    const int smem = 2 * GSTG * GSTAGE_F * (int)sizeof(float);   // 110592 B
    cudaFuncSetAttribute(gemm_tf32<0,0>, cudaFuncAttributeMaxDynamicSharedMemorySize, smem);
    cudaFuncSetAttribute(gemm_tf32<1,0>, cudaFuncAttributeMaxDynamicSharedMemorySize, smem);
    cudaFuncSetAttribute(gemm_tf32<2,1>, cudaFuncAttributeMaxDynamicSharedMemorySize, smem);
    cudaFuncSetAttribute(gemm_tf32<3,0>, cudaFuncAttributeMaxDynamicSharedMemorySize, smem);
    cudaFuncSetAttribute(flash_attn_tf32, cudaFuncAttributeMaxDynamicSharedMemorySize, FA_SMEM);

    // 0) round weights to tf32 once
    {
        int n;
        n = 3*Dq*Dq/4;  round_copy<<<(n+255)/256, 256>>>(w_qkv, wqkv_r, n);
        n = Dq*Dq/4;    round_copy<<<(n+255)/256, 256>>>(w_out, wout_r, n);
        n = DIq*Dq/4;   round_copy<<<(n+255)/256, 256>>>(w1, w1_r, n);
        n = DIq*Dq/4;   round_copy<<<(n+255)/256, 256>>>(w2, w2_r, n);
        n = Dq*DIq/4;   round_copy<<<(n+255)/256, 256>>>(w3, w3_r, n);
    }

    // 1) xn = rmsnorm(x, gamma_attn); also rounded copy
    rmsnorm_k<<<BSq, 256>>>(x, gamma_attn, xn, xnr);

    // 2) qkv = xnr @ wqkv_r^T + b_qkv
    gemm_tf32<0,0><<<dim3(3*Dq/128, BSq/128), 256, smem>>>(
        xnr, wqkv_r, b_qkv, nullptr, qkv, BSq, 3*Dq, Dq, Dq, 3*Dq);

    // 3) rope + split
    rope_split<<<(Bq*Sq*Hq*32)/256, 256>>>(qkv, q, k, v);

    // 4) flash attention -> attn (tf32-rounded)
    flash_attn_tf32<<<dim3(Sq/FA_BM, Hq, Bq), 256, FA_SMEM>>>(q, k, v, attn);

    // 5) h = xn + attn @ wout_r^T + b_out
    gemm_tf32<3,0><<<dim3(Dq/128, BSq/128), 256, smem>>>(
        attn, wout_r, b_out, xn, h, BSq, Dq, Dq, Dq, Dq);

    // 6) hn = rmsnorm(h, gamma_ffn); also rounded copy
    rmsnorm_k<<<BSq, 256>>>(h, gamma_ffn, hn, hnr);

    // 7) gate = silu(hnr @ w2_r^T + b2)
    gemm_tf32<1,0><<<dim3((DIq+127)/128, BSq/128), 256, smem>>>(
        hnr, w2_r, b2, nullptr, ff2, BSq, DIq, Dq, Dq, DIpad);

    // 8) ff1 = (hnr @ w1_r^T + b1) * gate   (tf32-rounded output)
    gemm_tf32<2,1><<<dim3((DIq+127)/128, BSq/128), 256, smem>>>(
        hnr, w1_r, b1, ff2, ff1, BSq, DIq, Dq, Dq, DIpad);

    // 9) out = hn + ff1 @ w3_r^T + b3
    gemm_tf32<3,0><<<dim3(Dq/128, BSq/128), 256, smem>>>(
        ff1, w3_r, b3, hn, out, BSq, Dq, DIq, DIpad, Dq);
}

// round 7
// speedup vs baseline: 4.6051x; 1.0279x over previous
#include <cuda_runtime.h>
#include <math.h>
#include <stdint.h>

// Problem constants
#define Bq  2
#define Sq  2048
#define Dq  1024
#define Hq  16
#define HDq 64
#define DIq 2730            // int(8/3 * 1024)
#define DIpad 2736          // padded row stride
#define BSq (Bq*Sq)         // 4096 rows

// ---------------- scratch (device globals; no allocation allowed) -----------
__device__ float g_xn  [(size_t)BSq*Dq];
__device__ float g_xnr [(size_t)BSq*Dq];      // tf32-rounded xn
__device__ float g_qkv [(size_t)BSq*3*Dq];
__device__ float g_q   [(size_t)Bq*Hq*Sq*HDq];
__device__ float g_k   [(size_t)Bq*Hq*Sq*HDq];
__device__ float g_v   [(size_t)Bq*Hq*Sq*HDq];
__device__ float g_attn[(size_t)BSq*Dq];      // rounded at flash epilogue
__device__ float g_h   [(size_t)BSq*Dq];
__device__ float g_hn  [(size_t)BSq*Dq];
__device__ float g_hnr [(size_t)BSq*Dq];      // tf32-rounded hn
__device__ float g_ff1 [(size_t)BSq*DIpad];   // rounded at producer epilogue
__device__ float g_ff2 [(size_t)BSq*DIpad];
// tf32-rounded weight copies
__device__ float g_wqkv[(size_t)3*Dq*Dq];
__device__ float g_wout[(size_t)Dq*Dq];
__device__ float g_w1  [(size_t)DIq*Dq];
__device__ float g_w2  [(size_t)DIq*Dq];
__device__ float g_w3  [(size_t)Dq*DIq];

__device__ __forceinline__ float tf32_rna(float x) {
    float r;
    asm("cvt.rna.tf32.f32 %0, %1;" : "=f"(r) : "f"(x));
    return r;
}

// ---------------- weight pre-rounding (float4 vectorized) -------------------
__global__ void __launch_bounds__(256) round_copy(const float* __restrict__ src,
                                                  float* __restrict__ dst, int n4)
{
    int i = blockIdx.x * 256 + threadIdx.x;
    if (i < n4) {
        float4 v = ((const float4*)src)[i];
        v.x = tf32_rna(v.x); v.y = tf32_rna(v.y);
        v.z = tf32_rna(v.z); v.w = tf32_rna(v.w);
        ((float4*)dst)[i] = v;
    }
}

// ---------------- RMSNorm: one block per row; dual output (full + tf32) -----
__global__ void __launch_bounds__(256) rmsnorm_k(const float* __restrict__ x,
                                                 const float* __restrict__ gamma,
                                                 float* __restrict__ out,
                                                 float* __restrict__ out_r)
{
    const size_t row = blockIdx.x;
    const float* xr = x + row * Dq;
    float ss = 0.f;
    for (int c = threadIdx.x; c < Dq; c += 256) { float v = xr[c]; ss += v * v; }
    #pragma unroll
    for (int d = 16; d > 0; d >>= 1) ss += __shfl_xor_sync(0xffffffffu, ss, d);
    __shared__ float red[8];
    __shared__ float s_inv;
    if ((threadIdx.x & 31) == 0) red[threadIdx.x >> 5] = ss;
    __syncthreads();
    if (threadIdx.x == 0) {
        float t = 0.f;
        #pragma unroll
        for (int i = 0; i < 8; i++) t += red[i];
        s_inv = rsqrtf(t / (float)Dq + 1e-5f);
    }
    __syncthreads();
    const float inv = s_inv;
    for (int c = threadIdx.x; c < Dq; c += 256) {
        float v = xr[c] * inv * gamma[c];
        out[row * Dq + c]   = v;
        out_r[row * Dq + c] = tf32_rna(v);
    }
}

// ---------------- cp.async helpers ------------------------------------------
__device__ __forceinline__ void cp8(uint32_t dst, const void* src, bool pred) {
    int sz = pred ? 8 : 0;
    asm volatile("cp.async.ca.shared.global [%0], [%1], 8, %2;"
                 :: "r"(dst), "l"(src), "r"(sz));
}
__device__ __forceinline__ void cp_commit() {
    asm volatile("cp.async.commit_group;");
}
template <int N>
__device__ __forceinline__ void cp_wait() {
    asm volatile("cp.async.wait_group %0;" :: "n"(N));
}

// ---------------- TF32 GEMM, double-buffered GBK=64, 1 sync/iter ------------
// Operands MUST already be tf32-rounded.
// MODE 0: +bias | 1: silu(+bias) | 2: (+bias)*extra | 3: (+bias)+extra
// RND 1: round output to tf32
#define GBM 128
#define GBN 128
#define GBK 64
#define GPAD 68
#define GSTAGE_F (GBM * GPAD)     // floats per operand per stage

template <int MODE, int RND>
__global__ void __launch_bounds__(256, 1) gemm_tf32(const float* __restrict__ A,
                                                    const float* __restrict__ W,
                                                    const float* __restrict__ bias,
                                                    const float* __restrict__ extra,
                                                    float* __restrict__ C,
                                                    int M, int N, int K,
                                                    int lda, int ldc)
{
    extern __shared__ float smem[];
    float* As = smem;                        // [2][128][68]
    float* Bs = smem + 2 * GSTAGE_F;         // [2][128][68]

    const int tid  = threadIdx.x;
    const int lane = tid & 31;
    const int w    = tid >> 5;
    const int wm   = (w >> 2) * 64;
    const int wn   = (w & 3) * 32;
    const int m0   = blockIdx.y * GBM;
    const int n0   = blockIdx.x * GBN;
    const int qr   = lane >> 2;
    const int qc   = lane & 3;

    const uint32_t sA = (uint32_t)__cvta_generic_to_shared(As);
    const uint32_t sB = (uint32_t)__cvta_generic_to_shared(Bs);

    float acc[4][4][4];
    #pragma unroll
    for (int i = 0; i < 4; i++)
        #pragma unroll
        for (int j = 0; j < 4; j++)
            #pragma unroll
            for (int t = 0; t < 4; t++) acc[i][j][t] = 0.f;

    const int kt = (K + GBK - 1) / GBK;

    // one stage = 128 rows x 64 cols per operand; 16 cp8 per thread per operand
    auto issue_stage = [&](int t, int buf) {
        const int k0 = t * GBK;
        const uint32_t aOff = sA + buf * GSTAGE_F * 4;
        const uint32_t bOff = sB + buf * GSTAGE_F * 4;
        #pragma unroll
        for (int i = 0; i < 16; i++) {
            int c    = tid + i * 256;          // 0..4095 float2 chunks
            int row  = c >> 5;                 // 0..127
            int col2 = (c & 31) * 2;           // 0,2,..62
            int gk   = k0 + col2;
            bool pk  = (gk < K);               // K even, gk even -> pair ok
            cp8(aOff + (row * GPAD + col2) * 4,
                &A[(size_t)(m0 + row) * lda + gk], pk);
            int gn = n0 + row;
            cp8(bOff + (row * GPAD + col2) * 4,
                &W[(size_t)gn * K + gk], pk && (gn < N));
        }
        cp_commit();
    };

    auto compute = [&](int buf) {
        const float* as = As + buf * GSTAGE_F;
        const float* bs = Bs + buf * GSTAGE_F;
        #pragma unroll
        for (int kk = 0; kk < 8; kk++) {
            const int kb = kk * 8;
            uint32_t af[4][4], bf[4][2];
            #pragma unroll
            for (int mt = 0; mt < 4; mt++) {
                const float* p = as + (wm + mt * 16 + qr) * GPAD + kb + qc;
                af[mt][0] = __float_as_uint(p[0]);
                af[mt][1] = __float_as_uint(p[8 * GPAD]);
                af[mt][2] = __float_as_uint(p[4]);
                af[mt][3] = __float_as_uint(p[8 * GPAD + 4]);
            }
            #pragma unroll
            for (int nt = 0; nt < 4; nt++) {
                const float* p = bs + (wn + nt * 8 + qr) * GPAD + kb + qc;
                bf[nt][0] = __float_as_uint(p[0]);
                bf[nt][1] = __float_as_uint(p[4]);
            }
            #pragma unroll
            for (int mt = 0; mt < 4; mt++)
                #pragma unroll
                for (int nt = 0; nt < 4; nt++) {
                    asm volatile(
                        "mma.sync.aligned.m16n8k8.row.col.f32.tf32.tf32.f32 "
                        "{%0,%1,%2,%3}, {%4,%5,%6,%7}, {%8,%9}, {%0,%1,%2,%3};"
                        : "+f"(acc[mt][nt][0]), "+f"(acc[mt][nt][1]),
                          "+f"(acc[mt][nt][2]), "+f"(acc[mt][nt][3])
                        : "r"(af[mt][0]), "r"(af[mt][1]),
                          "r"(af[mt][2]), "r"(af[mt][3]),
                          "r"(bf[nt][0]), "r"(bf[nt][1]));
                }
        }
    };

    issue_stage(0, 0);
    for (int t = 0; t < kt; t++) {
        cp_wait<0>();               // stage t landed (only pending group)
        __syncthreads();            // also: all warps done reading buf (t+1)&1
        if (t + 1 < kt) issue_stage(t + 1, (t + 1) & 1);
        compute(t & 1);             // overlaps with cp.async of stage t+1
    }

    // Epilogue
    #pragma unroll
    for (int mt = 0; mt < 4; mt++) {
        int r0 = m0 + wm + mt * 16 + qr;
        int r1 = r0 + 8;
        #pragma unroll
        for (int nt = 0; nt < 4; nt++) {
            int col = n0 + wn + nt * 8 + qc * 2;
            if (col < N) {
                float bv0 = bias[col], bv1 = bias[col + 1];
                float v00 = acc[mt][nt][0] + bv0;
                float v01 = acc[mt][nt][1] + bv1;
                float v10 = acc[mt][nt][2] + bv0;
                float v11 = acc[mt][nt][3] + bv1;
                if (MODE == 1) {
                    v00 = v00 / (1.f + expf(-v00));
                    v01 = v01 / (1.f + expf(-v01));
                    v10 = v10 / (1.f + expf(-v10));
                    v11 = v11 / (1.f + expf(-v11));
                }
                if (MODE == 2 || MODE == 3) {
                    float2 e0 = *(const float2*)&extra[(size_t)r0 * ldc + col];
                    float2 e1 = *(const float2*)&extra[(size_t)r1 * ldc + col];
                    if (MODE == 2) { v00 *= e0.x; v01 *= e0.y; v10 *= e1.x; v11 *= e1.y; }
                    else           { v00 += e0.x; v01 += e0.y; v10 += e1.x; v11 += e1.y; }
                }
                if (RND) {
                    v00 = tf32_rna(v00); v01 = tf32_rna(v01);
                    v10 = tf32_rna(v10); v11 = tf32_rna(v11);
                }
                *(float2*)&C[(size_t)r0 * ldc + col] = make_float2(v00, v01);
                *(float2*)&C[(size_t)r1 * ldc + col] = make_float2(v10, v11);
            }
        }
    }
}

// ---------------- RoPE + split/transpose ------------------------------------
__global__ void __launch_bounds__(256) rope_split(const float* __restrict__ qkv,
                                                  float* __restrict__ q,
                                                  float* __restrict__ k,
                                                  float* __restrict__ v)
{
    int idx = blockIdx.x * 256 + threadIdx.x;
    int i = idx & 31;
    int h = (idx >> 5) & 15;
    int s = (idx >> 9) & 2047;
    int b = idx >> 20;

    const size_t row = ((size_t)(b * Sq + s)) * (3 * Dq);
    const int off = h * HDq;

    float theta = powf(10000.f, -((float)(2 * i)) / 64.f);
    float sn, cs;
    sincosf((float)s * theta, &sn, &cs);

    float q1 = qkv[row + off + 2*i], q2 = qkv[row + off + 2*i + 1];
    float k1 = qkv[row + Dq + off + 2*i], k2 = qkv[row + Dq + off + 2*i + 1];
    float v1 = qkv[row + 2*Dq + off + 2*i], v2 = qkv[row + 2*Dq + off + 2*i + 1];

    size_t orow = ((size_t)(b * Hq + h) * Sq + s) * HDq;
    q[orow + i]      = q1 * cs - q2 * sn;
    q[orow + 32 + i] = q1 * sn + q2 * cs;
    k[orow + i]      = k1 * cs - k2 * sn;
    k[orow + 32 + i] = k1 * sn + k2 * cs;
    v[orow + 2*i]     = v1;
    v[orow + 2*i + 1] = v2;
}

// ---------------- TF32 tensor-core causal flash attention -------------------
#define FA_BM 128
#define FA_BN 64
#define FPAD 68
#define FA_SMEM ((FA_BM*FPAD + FA_BN*FPAD + FA_BN*FPAD + FA_BM*FPAD) * 4)

__global__ void __launch_bounds__(256, 2) flash_attn_tf32(const float* __restrict__ Q,
                                                          const float* __restrict__ K,
                                                          const float* __restrict__ V,
                                                          float* __restrict__ O)
{
    extern __shared__ float fs[];
    float* Qs = fs;
    float* Ks = Qs + FA_BM * FPAD;
    float* Vt = Ks + FA_BN * FPAD;
    float* Ps = Vt + FA_BN * FPAD;

    const int qt = gridDim.x - 1 - blockIdx.x;
    const int h = blockIdx.y, b = blockIdx.z;
    const int qm0 = qt * FA_BM;
    const size_t base = ((size_t)(b * Hq + h)) * Sq * HDq;
    const float* Qb = Q + base;
    const float* Kb = K + base;
    const float* Vb = V + base;

    const int tid  = threadIdx.x;
    const int lane = tid & 31;
    const int w    = tid >> 5;
    const int qr   = lane >> 2;
    const int qc   = lane & 3;
    const int wrow = w * 16;

    for (int i = tid; i < FA_BM * HDq; i += 256) {
        int r = i >> 6, c = i & 63;
        Qs[r * FPAD + c] = tf32_rna(Qb[(size_t)(qm0 + r) * HDq + c]);
    }

    float o[8][4];
    #pragma unroll
    for (int j = 0; j < 8; j++)
        #pragma unroll
        for (int t = 0; t < 4; t++) o[j][t] = 0.f;
    float m0 = -1e30f, m1 = -1e30f, l0 = 0.f, l1 = 0.f;

    const int row0 = qm0 + wrow + qr;
    const int row1 = row0 + 8;
    const int nkt = (qm0 + FA_BM) / FA_BN;

    for (int kt = 0; kt < nkt; kt++) {
        const int kn0 = kt * FA_BN;
        __syncthreads();
        for (int i = tid; i < FA_BN * HDq; i += 256) {
            int r = i >> 6, c = i & 63;
            float kv = Kb[(size_t)(kn0 + r) * HDq + c];
            float vv = Vb[(size_t)(kn0 + r) * HDq + c];
            Ks[r * FPAD + c] = tf32_rna(kv);
            Vt[c * FPAD + r] = tf32_rna(vv);
        }
        __syncthreads();

        const bool active = (kn0 <= qm0 + wrow + 15);
        if (active) {
            float s[8][4];
            #pragma unroll
            for (int j = 0; j < 8; j++)
                #pragma unroll
                for (int t = 0; t < 4; t++) s[j][t] = 0.f;

            #pragma unroll
            for (int kb = 0; kb < 64; kb += 8) {
                const float* ap = Qs + (wrow + qr) * FPAD + kb + qc;
                uint32_t a0 = __float_as_uint(ap[0]);
                uint32_t a1 = __float_as_uint(ap[8 * FPAD]);
                uint32_t a2 = __float_as_uint(ap[4]);
                uint32_t a3 = __float_as_uint(ap[8 * FPAD + 4]);
                #pragma unroll
                for (int j = 0; j < 8; j++) {
                    const float* bp = Ks + (j * 8 + qr) * FPAD + kb + qc;
                    uint32_t b0 = __float_as_uint(bp[0]);
                    uint32_t b1 = __float_as_uint(bp[4]);
                    asm volatile(
                        "mma.sync.aligned.m16n8k8.row.col.f32.tf32.tf32.f32 "
                        "{%0,%1,%2,%3}, {%4,%5,%6,%7}, {%8,%9}, {%0,%1,%2,%3};"
                        : "+f"(s[j][0]), "+f"(s[j][1]), "+f"(s[j][2]), "+f"(s[j][3])
                        : "r"(a0), "r"(a1), "r"(a2), "r"(a3), "r"(b0), "r"(b1));
                }
            }

            float rmax0 = -1e30f, rmax1 = -1e30f;
            #pragma unroll
            for (int j = 0; j < 8; j++) {
                int c0 = kn0 + j * 8 + 2 * qc, c1 = c0 + 1;
                s[j][0] = (c0 <= row0) ? s[j][0] * 0.125f : -1e30f;
                s[j][1] = (c1 <= row0) ? s[j][1] * 0.125f : -1e30f;
                s[j][2] = (c0 <= row1) ? s[j][2] * 0.125f : -1e30f;
                s[j][3] = (c1 <= row1) ? s[j][3] * 0.125f : -1e30f;
                rmax0 = fmaxf(rmax0, fmaxf(s[j][0], s[j][1]));
                rmax1 = fmaxf(rmax1, fmaxf(s[j][2], s[j][3]));
            }
            rmax0 = fmaxf(rmax0, __shfl_xor_sync(0xffffffffu, rmax0, 1));
            rmax0 = fmaxf(rmax0, __shfl_xor_sync(0xffffffffu, rmax0, 2));
            rmax1 = fmaxf(rmax1, __shfl_xor_sync(0xffffffffu, rmax1, 1));
            rmax1 = fmaxf(rmax1, __shfl_xor_sync(0xffffffffu, rmax1, 2));

            float mn0 = fmaxf(m0, rmax0), mn1 = fmaxf(m1, rmax1);
            float a0 = __expf(m0 - mn0),  a1 = __expf(m1 - mn1);
            float rs0 = 0.f, rs1 = 0.f;
            float* pr0 = Ps + (wrow + qr) * FPAD;
            float* pr1 = pr0 + 8 * FPAD;
            #pragma unroll
            for (int j = 0; j < 8; j++) {
                float p00 = tf32_rna(__expf(s[j][0] - mn0));
                float p01 = tf32_rna(__expf(s[j][1] - mn0));
                float p10 = tf32_rna(__expf(s[j][2] - mn1));
                float p11 = tf32_rna(__expf(s[j][3] - mn1));
                rs0 += p00 + p01;
                rs1 += p10 + p11;
                *(float2*)&pr0[j * 8 + 2 * qc] = make_float2(p00, p01);
                *(float2*)&pr1[j * 8 + 2 * qc] = make_float2(p10, p11);
            }
            rs0 += __shfl_xor_sync(0xffffffffu, rs0, 1);
            rs0 += __shfl_xor_sync(0xffffffffu, rs0, 2);
            rs1 += __shfl_xor_sync(0xffffffffu, rs1, 1);
            rs1 += __shfl_xor_sync(0xffffffffu, rs1, 2);

            l0 = l0 * a0 + rs0; m0 = mn0;
            l1 = l1 * a1 + rs1; m1 = mn1;
            #pragma unroll
            for (int j = 0; j < 8; j++) {
                o[j][0] *= a0; o[j][1] *= a0;
                o[j][2] *= a1; o[j][3] *= a1;
            }
            __syncwarp();

            #pragma unroll
            for (int kb = 0; kb < 64; kb += 8) {
                const float* ap = Ps + (wrow + qr) * FPAD + kb + qc;
                uint32_t a0f = __float_as_uint(ap[0]);
                uint32_t a1f = __float_as_uint(ap[8 * FPAD]);
                uint32_t a2f = __float_as_uint(ap[4]);
                uint32_t a3f = __float_as_uint(ap[8 * FPAD + 4]);
                #pragma unroll
                for (int j = 0; j < 8; j++) {
                    const float* bp = Vt + (j * 8 + qr) * FPAD + kb + qc;
                    uint32_t b0 = __float_as_uint(bp[0]);
                    uint32_t b1 = __float_as_uint(bp[4]);
                    asm volatile(
                        "mma.sync.aligned.m16n8k8.row.col.f32.tf32.tf32.f32 "
                        "{%0,%1,%2,%3}, {%4,%5,%6,%7}, {%8,%9}, {%0,%1,%2,%3};"
                        : "+f"(o[j][0]), "+f"(o[j][1]), "+f"(o[j][2]), "+f"(o[j][3])
                        : "r"(a0f), "r"(a1f), "r"(a2f), "r"(a3f), "r"(b0), "r"(b1));
                }
            }
        }
    }

    float inv0 = 1.f / l0, inv1 = 1.f / l1;
    #pragma unroll
    for (int j = 0; j < 8; j++) {
        int col = h * HDq + j * 8 + 2 * qc;
        size_t o0 = ((size_t)(b * Sq + row0)) * Dq + col;
        size_t o1 = ((size_t)(b * Sq + row1)) * Dq + col;
        *(float2*)&O[o0] = make_float2(tf32_rna(o[j][0] * inv0), tf32_rna(o[j][1] * inv0));
        *(float2*)&O[o1] = make_float2(tf32_rna(o[j][2] * inv1), tf32_rna(o[j][3] * inv1));
    }
}

// ---------------- launch --------------------------------------------------
extern "C" void kernel_launch(void* const* d_in, const int* in_sizes, int n_in,
                              void* d_out, int out_size)
{
    const float* x          = (const float*)d_in[0];
    const float* gamma_attn = (const float*)d_in[2];
    const float* w_qkv      = (const float*)d_in[3];
    const float* b_qkv      = (const float*)d_in[4];
    const float* w_out      = (const float*)d_in[5];
    const float* b_out      = (const float*)d_in[6];
    const float* gamma_ffn  = (const float*)d_in[7];
    const float* w1         = (const float*)d_in[8];
    const float* b1         = (const float*)d_in[9];
    const float* w2         = (const float*)d_in[10];
    const float* b2         = (const float*)d_in[11];
    const float* w3         = (const float*)d_in[12];
    const float* b3         = (const float*)d_in[13];
    float* out = (float*)d_out;

    float *xn, *xnr, *qkv, *q, *k, *v, *attn, *h, *hn, *hnr, *ff1, *ff2;
    float *wqkv_r, *wout_r, *w1_r, *w2_r, *w3_r;
    cudaGetSymbolAddress((void**)&xn,   g_xn);
    cudaGetSymbolAddress((void**)&xnr,  g_xnr);
    cudaGetSymbolAddress((void**)&qkv,  g_qkv);
    cudaGetSymbolAddress((void**)&q,    g_q);
    cudaGetSymbolAddress((void**)&k,    g_k);
    cudaGetSymbolAddress((void**)&v,    g_v);
    cudaGetSymbolAddress((void**)&attn, g_attn);
    cudaGetSymbolAddress((void**)&h,    g_h);
    cudaGetSymbolAddress((void**)&hn,   g_hn);
    cudaGetSymbolAddress((void**)&hnr,  g_hnr);
    cudaGetSymbolAddress((void**)&ff1,  g_ff1);
    cudaGetSymbolAddress((void**)&ff2,  g_ff2);
    cudaGetSymbolAddress((void**)&wqkv_r, g_wqkv);
    cudaGetSymbolAddress((void**)&wout_r, g_wout);
    cudaGetSymbolAddress((void**)&w1_r,   g_w1);
    cudaGetSymbolAddress((void**)&w2_r,   g_w2);
    cudaGetSymbolAddress((void**)&w3_r,   g_w3);

    const int smem = 4 * GSTAGE_F * (int)sizeof(float);   // 2 bufs x 2 ops = 139264 B
    cudaFuncSetAttribute(gemm_tf32<0,0>, cudaFuncAttributeMaxDynamicSharedMemorySize, smem);
    cudaFuncSetAttribute(gemm_tf32<1,0>, cudaFuncAttributeMaxDynamicSharedMemorySize, smem);
    cudaFuncSetAttribute(gemm_tf32<2,1>, cudaFuncAttributeMaxDynamicSharedMemorySize, smem);
    cudaFuncSetAttribute(gemm_tf32<3,0>, cudaFuncAttributeMaxDynamicSharedMemorySize, smem);
    cudaFuncSetAttribute(flash_attn_tf32, cudaFuncAttributeMaxDynamicSharedMemorySize, FA_SMEM);

    // 0) round weights to tf32 once
    {
        int n;
        n = 3*Dq*Dq/4;  round_copy<<<(n+255)/256, 256>>>(w_qkv, wqkv_r, n);
        n = Dq*Dq/4;    round_copy<<<(n+255)/256, 256>>>(w_out, wout_r, n);
        n = DIq*Dq/4;   round_copy<<<(n+255)/256, 256>>>(w1, w1_r, n);
        n = DIq*Dq/4;   round_copy<<<(n+255)/256, 256>>>(w2, w2_r, n);
        n = Dq*DIq/4;   round_copy<<<(n+255)/256, 256>>>(w3, w3_r, n);
    }

    // 1) xn = rmsnorm(x, gamma_attn); also rounded copy
    rmsnorm_k<<<BSq, 256>>>(x, gamma_attn, xn, xnr);

    // 2) qkv = xnr @ wqkv_r^T + b_qkv
    gemm_tf32<0,0><<<dim3(3*Dq/128, BSq/128), 256, smem>>>(
        xnr, wqkv_r, b_qkv, nullptr, qkv, BSq, 3*Dq, Dq, Dq, 3*Dq);

    // 3) rope + split
    rope_split<<<(Bq*Sq*Hq*32)/256, 256>>>(qkv, q, k, v);

    // 4) flash attention -> attn (tf32-rounded)
    flash_attn_tf32<<<dim3(Sq/FA_BM, Hq, Bq), 256, FA_SMEM>>>(q, k, v, attn);

    // 5) h = xn + attn @ wout_r^T + b_out
    gemm_tf32<3,0><<<dim3(Dq/128, BSq/128), 256, smem>>>(
        attn, wout_r, b_out, xn, h, BSq, Dq, Dq, Dq, Dq);

    // 6) hn = rmsnorm(h, gamma_ffn); also rounded copy
    rmsnorm_k<<<BSq, 256>>>(h, gamma_ffn, hn, hnr);

    // 7) gate = silu(hnr @ w2_r^T + b2)
    gemm_tf32<1,0><<<dim3((DIq+127)/128, BSq/128), 256, smem>>>(
        hnr, w2_r, b2, nullptr, ff2, BSq, DIq, Dq, Dq, DIpad);

    // 8) ff1 = (hnr @ w1_r^T + b1) * gate   (tf32-rounded output)
    gemm_tf32<2,1><<<dim3((DIq+127)/128, BSq/128), 256, smem>>>(
        hnr, w1_r, b1, ff2, ff1, BSq, DIq, Dq, Dq, DIpad);

    // 9) out = hn + ff1 @ w3_r^T + b3
    gemm_tf32<3,0><<<dim3(Dq/128, BSq/128), 256, smem>>>(
        ff1, w3_r, b3, hn, out, BSq, Dq, DIq, DIpad, Dq);
}

// round 9
// speedup vs baseline: 7.0587x; 1.5328x over previous
#include <cuda_runtime.h>
#include <cuda_fp16.h>
#include <math.h>
#include <stdint.h>

// Problem constants
#define Bq  2
#define Sq  2048
#define Dq  1024
#define Hq  16
#define HDq 64
#define DIq 2730            // int(8/3 * 1024)
#define DIpad 2736          // padded row stride
#define BSq (Bq*Sq)         // 4096 rows

// ---------------- scratch (device globals; no allocation allowed) -----------
__device__ float  g_xn  [(size_t)BSq*Dq];
__device__ __half g_xnh [(size_t)BSq*Dq];
__device__ float  g_qkv [(size_t)BSq*3*Dq];
__device__ __half g_qh  [(size_t)Bq*Hq*Sq*HDq];
__device__ __half g_kh  [(size_t)Bq*Hq*Sq*HDq];
__device__ __half g_vh  [(size_t)Bq*Hq*Sq*HDq];
__device__ __half g_attnh[(size_t)BSq*Dq];
__device__ float  g_h   [(size_t)BSq*Dq];
__device__ float  g_hn  [(size_t)BSq*Dq];
__device__ __half g_hnh [(size_t)BSq*Dq];
__device__ __half g_ff1h[(size_t)BSq*DIpad];
__device__ float  g_ff2 [(size_t)BSq*DIpad];   // gate, fp32
// fp16 weight copies
__device__ __half g_wqkvh[(size_t)3*Dq*Dq];
__device__ __half g_wouth[(size_t)Dq*Dq];
__device__ __half g_w1h  [(size_t)DIq*Dq];
__device__ __half g_w2h  [(size_t)DIq*Dq];
__device__ __half g_w3ph [(size_t)Dq*DIpad];   // padded [1024][2736], zeros in pad

// ---------------- conversion kernels ----------------------------------------
__global__ void __launch_bounds__(256) conv_half(const float* __restrict__ src,
                                                 __half* __restrict__ dst, int n4)
{
    int i = blockIdx.x * 256 + threadIdx.x;
    if (i < n4) {
        float4 v = ((const float4*)src)[i];
        ((__half2*)dst)[i*2]   = __floats2half2_rn(v.x, v.y);
        ((__half2*)dst)[i*2+1] = __floats2half2_rn(v.z, v.w);
    }
}

__global__ void __launch_bounds__(256) conv_half_pad(const float* __restrict__ src,
                                                     __half* __restrict__ dst,
                                                     int rows, int cin, int cpad)
{
    int i = blockIdx.x * 256 + threadIdx.x;
    if (i < rows * cpad) {
        int r = i / cpad, c = i - r * cpad;
        dst[i] = (c < cin) ? __float2half_rn(src[(size_t)r * cin + c]) : __half(0.f);
    }
}

__global__ void __launch_bounds__(256) zero_pad_ff1(__half* __restrict__ ff1)
{
    int i = blockIdx.x * 256 + threadIdx.x;
    if (i < BSq * (DIpad - DIq)) {
        int r = i / (DIpad - DIq), c = DIq + i % (DIpad - DIq);
        ff1[(size_t)r * DIpad + c] = __half(0.f);
    }
}

// ---------------- RMSNorm: dual output (fp32 + fp16) ------------------------
__global__ void __launch_bounds__(256) rmsnorm_k(const float* __restrict__ x,
                                                 const float* __restrict__ gamma,
                                                 float* __restrict__ out,
                                                 __half* __restrict__ out_h)
{
    const size_t row = blockIdx.x;
    const float* xr = x + row * Dq;
    float ss = 0.f;
    for (int c = threadIdx.x; c < Dq; c += 256) { float v = xr[c]; ss += v * v; }
    #pragma unroll
    for (int d = 16; d > 0; d >>= 1) ss += __shfl_xor_sync(0xffffffffu, ss, d);
    __shared__ float red[8];
    __shared__ float s_inv;
    if ((threadIdx.x & 31) == 0) red[threadIdx.x >> 5] = ss;
    __syncthreads();
    if (threadIdx.x == 0) {
        float t = 0.f;
        #pragma unroll
        for (int i = 0; i < 8; i++) t += red[i];
        s_inv = rsqrtf(t / (float)Dq + 1e-5f);
    }
    __syncthreads();
    const float inv = s_inv;
    for (int c = threadIdx.x; c < Dq; c += 256) {
        float v = xr[c] * inv * gamma[c];
        out[row * Dq + c]   = v;
        out_h[row * Dq + c] = __float2half_rn(v);
    }
}

// ---------------- cp.async helpers ------------------------------------------
__device__ __forceinline__ void cp8(uint32_t dst, const void* src, bool pred) {
    int sz = pred ? 8 : 0;
    asm volatile("cp.async.ca.shared.global [%0], [%1], 8, %2;"
                 :: "r"(dst), "l"(src), "r"(sz));
}
__device__ __forceinline__ void cp_commit() { asm volatile("cp.async.commit_group;"); }
__device__ __forceinline__ void cp_wait0()  { asm volatile("cp.async.wait_group 0;" ::: "memory"); }

// ---------------- FP16 GEMM (mma.m16n8k16), double-buffered ------------------
// C[M,N] = A[M,K] @ W[N,K]^T ; A,W are fp16; acc fp32.
// MODE 0: +bias | 1: silu(+bias) | 2: (+bias)*extra | 3: (+bias)+extra
// OUTH 1: store fp16 to Ch, else fp32 to C.
#define HBK 64                      // halves per k-chunk
#define HPAD 72                     // halves stride (144 B -> conflict-free)
#define HSTG (128 * HPAD)           // halves per operand stage
#define SMEM_H (4 * HSTG * 2)       // 2 bufs x 2 ops x bytes = 73728

template <int MODE, int OUTH>
__global__ void __launch_bounds__(256, 1) gemm_h(const __half* __restrict__ A,
                                                 const __half* __restrict__ W,
                                                 const float* __restrict__ bias,
                                                 const float* __restrict__ extra,
                                                 float* __restrict__ C,
                                                 __half* __restrict__ Ch,
                                                 int M, int N, int K,
                                                 int lda, int ldc)
{
    extern __shared__ __half hs[];
    __half* As = hs;                     // [2][128][72]
    __half* Bs = hs + 2 * HSTG;          // [2][128][72]

    const int tid  = threadIdx.x;
    const int lane = tid & 31;
    const int w    = tid >> 5;
    const int wm   = (w >> 2) * 64;
    const int wn   = (w & 3) * 32;
    const int m0   = blockIdx.y * 128;
    const int n0   = blockIdx.x * 128;
    const int qr   = lane >> 2;
    const int qc   = lane & 3;

    const uint32_t sA = (uint32_t)__cvta_generic_to_shared(As);
    const uint32_t sB = (uint32_t)__cvta_generic_to_shared(Bs);

    float acc[4][4][4];
    #pragma unroll
    for (int i = 0; i < 4; i++)
        #pragma unroll
        for (int j = 0; j < 4; j++)
            #pragma unroll
            for (int t = 0; t < 4; t++) acc[i][j][t] = 0.f;

    const int kt = (K + HBK - 1) / HBK;

    auto issue_stage = [&](int t, int buf) {
        const int k0 = t * HBK;
        const uint32_t aOff = sA + buf * HSTG * 2;
        const uint32_t bOff = sB + buf * HSTG * 2;
        #pragma unroll
        for (int i = 0; i < 8; i++) {
            int idx = tid + i * 256;          // 2048 8B-chunks per operand
            int row = idx >> 4;               // 0..127
            int ch  = idx & 15;               // 16 chunks of 4 halves per row
            int gk  = k0 + ch * 4;
            bool pk = (gk < K);
            cp8(aOff + (row * HPAD + ch * 4) * 2,
                &A[(size_t)(m0 + row) * lda + gk], pk);
            int gn = n0 + row;
            cp8(bOff + (row * HPAD + ch * 4) * 2,
                &W[(size_t)gn * K + gk], pk && (gn < N));
        }
        cp_commit();
    };

    auto compute = [&](int buf) {
        const __half* as = As + buf * HSTG;
        const __half* bs = Bs + buf * HSTG;
        #pragma unroll
        for (int kk = 0; kk < 4; kk++) {
            const int kb = kk * 16;
            uint32_t af[4][4], bf[4][2];
            #pragma unroll
            for (int mt = 0; mt < 4; mt++) {
                const __half* p = as + (wm + mt * 16 + qr) * HPAD + kb + 2 * qc;
                af[mt][0] = *(const uint32_t*)p;
                af[mt][1] = *(const uint32_t*)(p + 8 * HPAD);
                af[mt][2] = *(const uint32_t*)(p + 8);
                af[mt][3] = *(const uint32_t*)(p + 8 * HPAD + 8);
            }
            #pragma unroll
            for (int nt = 0; nt < 4; nt++) {
                const __half* p = bs + (wn + nt * 8 + qr) * HPAD + kb + 2 * qc;
                bf[nt][0] = *(const uint32_t*)p;
                bf[nt][1] = *(const uint32_t*)(p + 8);
            }
            #pragma unroll
            for (int mt = 0; mt < 4; mt++)
                #pragma unroll
                for (int nt = 0; nt < 4; nt++) {
                    asm volatile(
                        "mma.sync.aligned.m16n8k16.row.col.f32.f16.f16.f32 "
                        "{%0,%1,%2,%3}, {%4,%5,%6,%7}, {%8,%9}, {%0,%1,%2,%3};"
                        : "+f"(acc[mt][nt][0]), "+f"(acc[mt][nt][1]),
                          "+f"(acc[mt][nt][2]), "+f"(acc[mt][nt][3])
                        : "r"(af[mt][0]), "r"(af[mt][1]),
                          "r"(af[mt][2]), "r"(af[mt][3]),
                          "r"(bf[nt][0]), "r"(bf[nt][1]));
                }
        }
    };

    issue_stage(0, 0);
    for (int t = 0; t < kt; t++) {
        cp_wait0();
        __syncthreads();
        if (t + 1 < kt) issue_stage(t + 1, (t + 1) & 1);
        compute(t & 1);
    }

    // Epilogue
    #pragma unroll
    for (int mt = 0; mt < 4; mt++) {
        int r0 = m0 + wm + mt * 16 + qr;
        int r1 = r0 + 8;
        #pragma unroll
        for (int nt = 0; nt < 4; nt++) {
            int col = n0 + wn + nt * 8 + qc * 2;
            if (col < N) {
                float bv0 = bias[col], bv1 = bias[col + 1];
                float v00 = acc[mt][nt][0] + bv0;
                float v01 = acc[mt][nt][1] + bv1;
                float v10 = acc[mt][nt][2] + bv0;
                float v11 = acc[mt][nt][3] + bv1;
                if (MODE == 1) {
                    v00 = v00 / (1.f + expf(-v00));
                    v01 = v01 / (1.f + expf(-v01));
                    v10 = v10 / (1.f + expf(-v10));
                    v11 = v11 / (1.f + expf(-v11));
                }
                if (MODE == 2 || MODE == 3) {
                    float2 e0 = *(const float2*)&extra[(size_t)r0 * ldc + col];
                    float2 e1 = *(const float2*)&extra[(size_t)r1 * ldc + col];
                    if (MODE == 2) { v00 *= e0.x; v01 *= e0.y; v10 *= e1.x; v11 *= e1.y; }
                    else           { v00 += e0.x; v01 += e0.y; v10 += e1.x; v11 += e1.y; }
                }
                if (OUTH) {
                    *(__half2*)&Ch[(size_t)r0 * ldc + col] = __floats2half2_rn(v00, v01);
                    *(__half2*)&Ch[(size_t)r1 * ldc + col] = __floats2half2_rn(v10, v11);
                } else {
                    *(float2*)&C[(size_t)r0 * ldc + col] = make_float2(v00, v01);
                    *(float2*)&C[(size_t)r1 * ldc + col] = make_float2(v10, v11);
                }
            }
        }
    }
}

// ---------------- RoPE + split/transpose (fp32 qkv -> fp16 q,k,v) -----------
__global__ void __launch_bounds__(256) rope_split(const float* __restrict__ qkv,
                                                  __half* __restrict__ q,
                                                  __half* __restrict__ k,
                                                  __half* __restrict__ v)
{
    int idx = blockIdx.x * 256 + threadIdx.x;
    int i = idx & 31;
    int h = (idx >> 5) & 15;
    int s = (idx >> 9) & 2047;
    int b = idx >> 20;

    const size_t row = ((size_t)(b * Sq + s)) * (3 * Dq);
    const int off = h * HDq;

    float theta = powf(10000.f, -((float)(2 * i)) / 64.f);
    float sn, cs;
    sincosf((float)s * theta, &sn, &cs);

    float q1 = qkv[row + off + 2*i], q2 = qkv[row + off + 2*i + 1];
    float k1 = qkv[row + Dq + off + 2*i], k2 = qkv[row + Dq + off + 2*i + 1];
    float v1 = qkv[row + 2*Dq + off + 2*i], v2 = qkv[row + 2*Dq + off + 2*i + 1];

    size_t orow = ((size_t)(b * Hq + h) * Sq + s) * HDq;
    q[orow + i]      = __float2half_rn(q1 * cs - q2 * sn);
    q[orow + 32 + i] = __float2half_rn(q1 * sn + q2 * cs);
    k[orow + i]      = __float2half_rn(k1 * cs - k2 * sn);
    k[orow + 32 + i] = __float2half_rn(k1 * sn + k2 * cs);
    v[orow + 2*i]     = __float2half_rn(v1);
    v[orow + 2*i + 1] = __float2half_rn(v2);
}

// ---------------- FP16 tensor-core causal flash attention -------------------
// CTA: 128 q-rows, 8 warps (16 rows each). Key tiles of 64. HD = 64.
#define FA_BM 128
#define FA_BN 64
#define FPH 72
#define FA_SMEMH ((FA_BM*FPH + FA_BN*FPH + FA_BN*FPH + FA_BM*FPH) * 2)

__global__ void __launch_bounds__(256, 2) flash_attn_h(const __half* __restrict__ Q,
                                                       const __half* __restrict__ K,
                                                       const __half* __restrict__ V,
                                                       __half* __restrict__ O)
{
    extern __shared__ __half fh[];
    __half* Qs = fh;                      // [128][72]
    __half* Ks = Qs + FA_BM * FPH;        // [64][72]
    __half* Vt = Ks + FA_BN * FPH;        // [hd 64][key 72]
    __half* Ps = Vt + FA_BN * FPH;        // [128][72]

    const int qt = gridDim.x - 1 - blockIdx.x;
    const int h = blockIdx.y, b = blockIdx.z;
    const int qm0 = qt * FA_BM;
    const size_t base = ((size_t)(b * Hq + h)) * Sq * HDq;
    const __half* Qb = Q + base;
    const __half* Kb = K + base;
    const __half* Vb = V + base;

    const int tid  = threadIdx.x;
    const int lane = tid & 31;
    const int w    = tid >> 5;
    const int qr   = lane >> 2;
    const int qc   = lane & 3;
    const int wrow = w * 16;

    for (int i = tid; i < FA_BM * 32; i += 256) {   // half2 granules
        int r = i >> 5, c2 = i & 31;
        __half2 v = ((const __half2*)Qb)[(size_t)(qm0 + r) * 32 + c2];
        *(__half2*)&Qs[r * FPH + c2 * 2] = v;
    }

    float o[8][4];
    #pragma unroll
    for (int j = 0; j < 8; j++)
        #pragma unroll
        for (int t = 0; t < 4; t++) o[j][t] = 0.f;
    float m0 = -1e30f, m1 = -1e30f, l0 = 0.f, l1 = 0.f;

    const int row0 = qm0 + wrow + qr;
    const int row1 = row0 + 8;
    const int nkt = (qm0 + FA_BM) / FA_BN;

    for (int kt = 0; kt < nkt; kt++) {
        const int kn0 = kt * FA_BN;
        __syncthreads();
        for (int i = tid; i < FA_BN * 32; i += 256) {
            int r = i >> 5, c2 = i & 31;
            __half2 kv = ((const __half2*)Kb)[(size_t)(kn0 + r) * 32 + c2];
            *(__half2*)&Ks[r * FPH + c2 * 2] = kv;
            __half2 vv = ((const __half2*)Vb)[(size_t)(kn0 + r) * 32 + c2];
            Vt[(c2 * 2)     * FPH + r] = __low2half(vv);
            Vt[(c2 * 2 + 1) * FPH + r] = __high2half(vv);
        }
        __syncthreads();

        const bool active = (kn0 <= qm0 + wrow + 15);
        if (active) {
            // ---- S = Q @ K^T ----
            float s[8][4];
            #pragma unroll
            for (int j = 0; j < 8; j++)
                #pragma unroll
                for (int t = 0; t < 4; t++) s[j][t] = 0.f;

            #pragma unroll
            for (int kk = 0; kk < 4; kk++) {
                const int kb = kk * 16;
                const __half* ap = Qs + (wrow + qr) * FPH + kb + 2 * qc;
                uint32_t a0 = *(const uint32_t*)ap;
                uint32_t a1 = *(const uint32_t*)(ap + 8 * FPH);
                uint32_t a2 = *(const uint32_t*)(ap + 8);
                uint32_t a3 = *(const uint32_t*)(ap + 8 * FPH + 8);
                #pragma unroll
                for (int j = 0; j < 8; j++) {
                    const __half* bp = Ks + (j * 8 + qr) * FPH + kb + 2 * qc;
                    uint32_t b0 = *(const uint32_t*)bp;
                    uint32_t b1 = *(const uint32_t*)(bp + 8);
                    asm volatile(
                        "mma.sync.aligned.m16n8k16.row.col.f32.f16.f16.f32 "
                        "{%0,%1,%2,%3}, {%4,%5,%6,%7}, {%8,%9}, {%0,%1,%2,%3};"
                        : "+f"(s[j][0]), "+f"(s[j][1]), "+f"(s[j][2]), "+f"(s[j][3])
                        : "r"(a0), "r"(a1), "r"(a2), "r"(a3), "r"(b0), "r"(b1));
                }
            }

            // ---- causal mask + online softmax ----
            float rmax0 = -1e30f, rmax1 = -1e30f;
            #pragma unroll
            for (int j = 0; j < 8; j++) {
                int c0 = kn0 + j * 8 + 2 * qc, c1 = c0 + 1;
                s[j][0] = (c0 <= row0) ? s[j][0] * 0.125f : -1e30f;
                s[j][1] = (c1 <= row0) ? s[j][1] * 0.125f : -1e30f;
                s[j][2] = (c0 <= row1) ? s[j][2] * 0.125f : -1e30f;
                s[j][3] = (c1 <= row1) ? s[j][3] * 0.125f : -1e30f;
                rmax0 = fmaxf(rmax0, fmaxf(s[j][0], s[j][1]));
                rmax1 = fmaxf(rmax1, fmaxf(s[j][2], s[j][3]));
            }
            rmax0 = fmaxf(rmax0, __shfl_xor_sync(0xffffffffu, rmax0, 1));
            rmax0 = fmaxf(rmax0, __shfl_xor_sync(0xffffffffu, rmax0, 2));
            rmax1 = fmaxf(rmax1, __shfl_xor_sync(0xffffffffu, rmax1, 1));
            rmax1 = fmaxf(rmax1, __shfl_xor_sync(0xffffffffu, rmax1, 2));

            float mn0 = fmaxf(m0, rmax0), mn1 = fmaxf(m1, rmax1);
            float a0 = __expf(m0 - mn0),  a1 = __expf(m1 - mn1);
            float rs0 = 0.f, rs1 = 0.f;
            __half* pr0 = Ps + (wrow + qr) * FPH;
            __half* pr1 = pr0 + 8 * FPH;
            #pragma unroll
            for (int j = 0; j < 8; j++) {
                __half2 h0 = __floats2half2_rn(__expf(s[j][0] - mn0),
                                               __expf(s[j][1] - mn0));
                __half2 h1 = __floats2half2_rn(__expf(s[j][2] - mn1),
                                               __expf(s[j][3] - mn1));
                *(__half2*)&pr0[j * 8 + 2 * qc] = h0;
                *(__half2*)&pr1[j * 8 + 2 * qc] = h1;
                float2 f0 = __half22float2(h0), f1 = __half22float2(h1);
                rs0 += f0.x + f0.y;
                rs1 += f1.x + f1.y;
            }
            rs0 += __shfl_xor_sync(0xffffffffu, rs0, 1);
            rs0 += __shfl_xor_sync(0xffffffffu, rs0, 2);
            rs1 += __shfl_xor_sync(0xffffffffu, rs1, 1);
            rs1 += __shfl_xor_sync(0xffffffffu, rs1, 2);

            l0 = l0 * a0 + rs0; m0 = mn0;
            l1 = l1 * a1 + rs1; m1 = mn1;
            #pragma unroll
            for (int j = 0; j < 8; j++) {
                o[j][0] *= a0; o[j][1] *= a0;
                o[j][2] *= a1; o[j][3] *= a1;
            }
            __syncwarp();

            // ---- O += P @ V ----
            #pragma unroll
            for (int kk = 0; kk < 4; kk++) {
                const int kb = kk * 16;
                const __half* ap = Ps + (wrow + qr) * FPH + kb + 2 * qc;
                uint32_t a0f = *(const uint32_t*)ap;
                uint32_t a1f = *(const uint32_t*)(ap + 8 * FPH);
                uint32_t a2f = *(const uint32_t*)(ap + 8);
                uint32_t a3f = *(const uint32_t*)(ap + 8 * FPH + 8);
                #pragma unroll
                for (int j = 0; j < 8; j++) {
                    const __half* bp = Vt + (j * 8 + qr) * FPH + kb + 2 * qc;
                    uint32_t b0 = *(const uint32_t*)bp;
                    uint32_t b1 = *(const uint32_t*)(bp + 8);
                    asm volatile(
                        "mma.sync.aligned.m16n8k16.row.col.f32.f16.f16.f32 "
                        "{%0,%1,%2,%3}, {%4,%5,%6,%7}, {%8,%9}, {%0,%1,%2,%3};"
                        : "+f"(o[j][0]), "+f"(o[j][1]), "+f"(o[j][2]), "+f"(o[j][3])
                        : "r"(a0f), "r"(a1f), "r"(a2f), "r"(a3f), "r"(b0), "r"(b1));
                }
            }
        }
    }

    // ---- normalize + write O (fp16) as [b, s, h*64 + c] ----
    float inv0 = 1.f / l0, inv1 = 1.f / l1;
    #pragma unroll
    for (int j = 0; j < 8; j++) {
        int col = h * HDq + j * 8 + 2 * qc;
        size_t o0 = ((size_t)(b * Sq + row0)) * Dq + col;
        size_t o1 = ((size_t)(b * Sq + row1)) * Dq + col;
        *(__half2*)&O[o0] = __floats2half2_rn(o[j][0] * inv0, o[j][1] * inv0);
        *(__half2*)&O[o1] = __floats2half2_rn(o[j][2] * inv1, o[j][3] * inv1);
    }
}

// ---------------- launch --------------------------------------------------
extern "C" void kernel_launch(void* const* d_in, const int* in_sizes, int n_in,
                              void* d_out, int out_size)
{
    const float* x          = (const float*)d_in[0];
    const float* gamma_attn = (const float*)d_in[2];
    const float* w_qkv      = (const float*)d_in[3];
    const float* b_qkv      = (const float*)d_in[4];
    const float* w_out      = (const float*)d_in[5];
    const float* b_out      = (const float*)d_in[6];
    const float* gamma_ffn  = (const float*)d_in[7];
    const float* w1         = (const float*)d_in[8];
    const float* b1         = (const float*)d_in[9];
    const float* w2         = (const float*)d_in[10];
    const float* b2         = (const float*)d_in[11];
    const float* w3         = (const float*)d_in[12];
    const float* b3         = (const float*)d_in[13];
    float* out = (float*)d_out;

    float  *xn, *qkv, *h, *hn, *ff2;
    __half *xnh, *qh, *kh, *vh, *attnh, *hnh, *ff1h;
    __half *wqkvh, *wouth, *w1h, *w2h, *w3ph;
    cudaGetSymbolAddress((void**)&xn,    g_xn);
    cudaGetSymbolAddress((void**)&xnh,   g_xnh);
    cudaGetSymbolAddress((void**)&qkv,   g_qkv);
    cudaGetSymbolAddress((void**)&qh,    g_qh);
    cudaGetSymbolAddress((void**)&kh,    g_kh);
    cudaGetSymbolAddress((void**)&vh,    g_vh);
    cudaGetSymbolAddress((void**)&attnh, g_attnh);
    cudaGetSymbolAddress((void**)&h,     g_h);
    cudaGetSymbolAddress((void**)&hn,    g_hn);
    cudaGetSymbolAddress((void**)&hnh,   g_hnh);
    cudaGetSymbolAddress((void**)&ff1h,  g_ff1h);
    cudaGetSymbolAddress((void**)&ff2,   g_ff2);
    cudaGetSymbolAddress((void**)&wqkvh, g_wqkvh);
    cudaGetSymbolAddress((void**)&wouth, g_wouth);
    cudaGetSymbolAddress((void**)&w1h,   g_w1h);
    cudaGetSymbolAddress((void**)&w2h,   g_w2h);
    cudaGetSymbolAddress((void**)&w3ph,  g_w3ph);

    cudaFuncSetAttribute(gemm_h<0,0>, cudaFuncAttributeMaxDynamicSharedMemorySize, SMEM_H);
    cudaFuncSetAttribute(gemm_h<1,0>, cudaFuncAttributeMaxDynamicSharedMemorySize, SMEM_H);
    cudaFuncSetAttribute(gemm_h<2,1>, cudaFuncAttributeMaxDynamicSharedMemorySize, SMEM_H);
    cudaFuncSetAttribute(gemm_h<3,0>, cudaFuncAttributeMaxDynamicSharedMemorySize, SMEM_H);
    cudaFuncSetAttribute(flash_attn_h, cudaFuncAttributeMaxDynamicSharedMemorySize, FA_SMEMH);

    // 0) convert weights to fp16 once; zero ff1 pads
    {
        int n;
        n = 3*Dq*Dq/4;  conv_half<<<(n+255)/256, 256>>>(w_qkv, wqkvh, n);
        n = Dq*Dq/4;    conv_half<<<(n+255)/256, 256>>>(w_out, wouth, n);
        n = DIq*Dq/4;   conv_half<<<(n+255)/256, 256>>>(w1, w1h, n);
        n = DIq*Dq/4;   conv_half<<<(n+255)/256, 256>>>(w2, w2h, n);
        n = Dq*DIpad;   conv_half_pad<<<(n+255)/256, 256>>>(w3, w3ph, Dq, DIq, DIpad);
        n = BSq*(DIpad-DIq); zero_pad_ff1<<<(n+255)/256, 256>>>(ff1h);
    }

    // 1) xn = rmsnorm(x, gamma_attn)  (fp32 + fp16)
    rmsnorm_k<<<BSq, 256>>>(x, gamma_attn, xn, xnh);

    // 2) qkv = xnh @ wqkvh^T + b_qkv           [4096, 3072] fp32 out
    gemm_h<0,0><<<dim3(3*Dq/128, BSq/128), 256, SMEM_H>>>(
        xnh, wqkvh, b_qkv, nullptr, qkv, nullptr, BSq, 3*Dq, Dq, Dq, 3*Dq);

    // 3) rope + split -> fp16 q,k,v
    rope_split<<<(Bq*Sq*Hq*32)/256, 256>>>(qkv, qh, kh, vh);

    // 4) flash attention -> attnh (fp16)
    flash_attn_h<<<dim3(Sq/FA_BM, Hq, Bq), 256, FA_SMEMH>>>(qh, kh, vh, attnh);

    // 5) h = xn + attnh @ wouth^T + b_out      (fp32 out)
    gemm_h<3,0><<<dim3(Dq/128, BSq/128), 256, SMEM_H>>>(
        attnh, wouth, b_out, xn, h, nullptr, BSq, Dq, Dq, Dq, Dq);

    // 6) hn = rmsnorm(h, gamma_ffn)  (fp32 + fp16)
    rmsnorm_k<<<BSq, 256>>>(h, gamma_ffn, hn, hnh);

    // 7) gate = silu(hnh @ w2h^T + b2)         (fp32 out, stride DIpad)
    gemm_h<1,0><<<dim3((DIq+127)/128, BSq/128), 256, SMEM_H>>>(
        hnh, w2h, b2, nullptr, ff2, nullptr, BSq, DIq, Dq, Dq, DIpad);

    // 8) ff1 = (hnh @ w1h^T + b1) * gate       (fp16 out)
    gemm_h<2,1><<<dim3((DIq+127)/128, BSq/128), 256, SMEM_H>>>(
        hnh, w1h, b1, ff2, nullptr, ff1h, BSq, DIq, Dq, Dq, DIpad);

    // 9) out = hn + ff1h @ w3ph^T + b3         (K padded to 2736, pads zero)
    gemm_h<3,0><<<dim3(Dq/128, BSq/128), 256, SMEM_H>>>(
        ff1h, w3ph, b3, hn, out, nullptr, BSq, Dq, DIpad, DIpad, Dq);
}

// round 10
// speedup vs baseline: 7.4225x; 1.0515x over previous
#include <cuda_runtime.h>
#include <cuda_fp16.h>
#include <math.h>
#include <stdint.h>

// Problem constants
#define Bq  2
#define Sq  2048
#define Dq  1024
#define Hq  16
#define HDq 64
#define DIq 2730            // int(8/3 * 1024)
#define DIpad 2736          // padded row stride
#define BSq (Bq*Sq)         // 4096 rows

// ---------------- scratch (device globals; no allocation allowed) -----------
__device__ float  g_xn  [(size_t)BSq*Dq];
__device__ __half g_xnh [(size_t)BSq*Dq];
__device__ __half g_qkvh[(size_t)BSq*3*Dq];
__device__ __half g_qh  [(size_t)Bq*Hq*Sq*HDq];
__device__ __half g_kh  [(size_t)Bq*Hq*Sq*HDq];
__device__ __half g_vh  [(size_t)Bq*Hq*Sq*HDq];
__device__ __half g_attnh[(size_t)BSq*Dq];
__device__ float  g_h   [(size_t)BSq*Dq];
__device__ float  g_hn  [(size_t)BSq*Dq];
__device__ __half g_hnh [(size_t)BSq*Dq];
__device__ __half g_ff1h[(size_t)BSq*DIpad];
__device__ float  g_ff2 [(size_t)BSq*DIpad];   // gate, fp32
// fp16 weight copies
__device__ __half g_wqkvh[(size_t)3*Dq*Dq];
__device__ __half g_wouth[(size_t)Dq*Dq];
__device__ __half g_w1h  [(size_t)DIq*Dq];
__device__ __half g_w2h  [(size_t)DIq*Dq];
__device__ __half g_w3ph [(size_t)Dq*DIpad];   // padded [1024][2736], zeros in pad

// ---------------- conversion kernels ----------------------------------------
__global__ void __launch_bounds__(256) conv_half(const float* __restrict__ src,
                                                 __half* __restrict__ dst, int n4)
{
    int i = blockIdx.x * 256 + threadIdx.x;
    if (i < n4) {
        float4 v = ((const float4*)src)[i];
        ((__half2*)dst)[i*2]   = __floats2half2_rn(v.x, v.y);
        ((__half2*)dst)[i*2+1] = __floats2half2_rn(v.z, v.w);
    }
}

__global__ void __launch_bounds__(256) conv_half_pad(const float* __restrict__ src,
                                                     __half* __restrict__ dst,
                                                     int rows, int cin, int cpad)
{
    int i = blockIdx.x * 256 + threadIdx.x;
    if (i < rows * cpad) {
        int r = i / cpad, c = i - r * cpad;
        dst[i] = (c < cin) ? __float2half_rn(src[(size_t)r * cin + c]) : __half(0.f);
    }
}

__global__ void __launch_bounds__(256) zero_pad_ff1(__half* __restrict__ ff1)
{
    int i = blockIdx.x * 256 + threadIdx.x;
    if (i < BSq * (DIpad - DIq)) {
        int r = i / (DIpad - DIq), c = DIq + i % (DIpad - DIq);
        ff1[(size_t)r * DIpad + c] = __half(0.f);
    }
}

// ---------------- RMSNorm: dual output (fp32 + fp16) ------------------------
__global__ void __launch_bounds__(256) rmsnorm_k(const float* __restrict__ x,
                                                 const float* __restrict__ gamma,
                                                 float* __restrict__ out,
                                                 __half* __restrict__ out_h)
{
    const size_t row = blockIdx.x;
    const float* xr = x + row * Dq;
    float ss = 0.f;
    for (int c = threadIdx.x; c < Dq; c += 256) { float v = xr[c]; ss += v * v; }
    #pragma unroll
    for (int d = 16; d > 0; d >>= 1) ss += __shfl_xor_sync(0xffffffffu, ss, d);
    __shared__ float red[8];
    __shared__ float s_inv;
    if ((threadIdx.x & 31) == 0) red[threadIdx.x >> 5] = ss;
    __syncthreads();
    if (threadIdx.x == 0) {
        float t = 0.f;
        #pragma unroll
        for (int i = 0; i < 8; i++) t += red[i];
        s_inv = rsqrtf(t / (float)Dq + 1e-5f);
    }
    __syncthreads();
    const float inv = s_inv;
    for (int c = threadIdx.x; c < Dq; c += 256) {
        float v = xr[c] * inv * gamma[c];
        out[row * Dq + c]   = v;
        out_h[row * Dq + c] = __float2half_rn(v);
    }
}

// ---------------- cp.async / ldmatrix helpers --------------------------------
__device__ __forceinline__ void cp16(uint32_t dst, const void* src, int sz) {
    asm volatile("cp.async.cg.shared.global [%0], [%1], 16, %2;"
                 :: "r"(dst), "l"(src), "r"(sz));
}
__device__ __forceinline__ void cp_commit() { asm volatile("cp.async.commit_group;"); }
__device__ __forceinline__ void cp_wait0()  { asm volatile("cp.async.wait_group 0;" ::: "memory"); }

#define LDSM4(r0, r1, r2, r3, a) \
    asm volatile("ldmatrix.sync.aligned.m8n8.x4.shared.b16 {%0,%1,%2,%3}, [%4];" \
                 : "=r"(r0), "=r"(r1), "=r"(r2), "=r"(r3) : "r"(a))

#define MMA_H(d0,d1,d2,d3, a0,a1,a2,a3, b0,b1) \
    asm volatile("mma.sync.aligned.m16n8k16.row.col.f32.f16.f16.f32 " \
                 "{%0,%1,%2,%3}, {%4,%5,%6,%7}, {%8,%9}, {%0,%1,%2,%3};" \
                 : "+f"(d0), "+f"(d1), "+f"(d2), "+f"(d3) \
                 : "r"(a0), "r"(a1), "r"(a2), "r"(a3), "r"(b0), "r"(b1))

// ---------------- FP16 GEMM (mma.m16n8k16 + ldmatrix), double-buffered ------
// C[M,N] = A[M,K] @ W[N,K]^T ; A,W fp16; acc fp32.
// MODE 0: +bias | 1: silu(+bias) | 2: (+bias)*extra | 3: (+bias)+extra
// OUTH 1: store fp16 to Ch, else fp32 to C.
#define HBK 64                      // halves per k-chunk
#define HPAD 72                     // halves stride (144 B -> conflict-free)
#define HSTG (128 * HPAD)           // halves per operand stage
#define SMEM_H (4 * HSTG * 2)       // 2 bufs x 2 ops x bytes = 73728

template <int MODE, int OUTH>
__global__ void __launch_bounds__(256, 1) gemm_h(const __half* __restrict__ A,
                                                 const __half* __restrict__ W,
                                                 const float* __restrict__ bias,
                                                 const float* __restrict__ extra,
                                                 float* __restrict__ C,
                                                 __half* __restrict__ Ch,
                                                 int M, int N, int K,
                                                 int lda, int ldc)
{
    extern __shared__ __half hs[];
    const uint32_t sAll = (uint32_t)__cvta_generic_to_shared(hs);
    const uint32_t sA = sAll;                    // [2][128][72]
    const uint32_t sB = sAll + 2 * HSTG * 2;     // [2][128][72]

    const int tid  = threadIdx.x;
    const int lane = tid & 31;
    const int w    = tid >> 5;
    const int wm   = (w >> 2) * 64;
    const int wn   = (w & 3) * 32;
    const int m0   = blockIdx.y * 128;
    const int n0   = blockIdx.x * 128;
    const int qr   = lane >> 2;
    const int qc   = lane & 3;

    // per-lane ldmatrix row/k offsets
    const int laneRowA = lane & 15;
    const int laneKA   = (lane >> 4) << 3;
    const int laneRowB = (lane & 7) + ((lane >> 4) << 3);
    const int laneKB   = ((lane >> 3) & 1) << 3;

    float acc[4][4][4];
    #pragma unroll
    for (int i = 0; i < 4; i++)
        #pragma unroll
        for (int j = 0; j < 4; j++)
            #pragma unroll
            for (int t = 0; t < 4; t++) acc[i][j][t] = 0.f;

    const int kt = (K + HBK - 1) / HBK;

    auto issue_stage = [&](int t, int buf) {
        const int k0 = t * HBK;
        const uint32_t aOff = sA + buf * HSTG * 2;
        const uint32_t bOff = sB + buf * HSTG * 2;
        #pragma unroll
        for (int i = 0; i < 4; i++) {             // 1024 16B-granules / operand
            int idx = tid + i * 256;
            int row = idx >> 3;                   // 0..127
            int g   = idx & 7;                    // 8 granules of 8 halves
            int gk  = k0 + g * 8;
            int sz  = (gk < K) ? 16 : 0;
            int cs  = sz ? gk : 0;
            cp16(aOff + (row * HPAD + g * 8) * 2,
                 &A[(size_t)(m0 + row) * lda + cs], sz);
            int gn = n0 + row;
            int szb = (gn < N) ? sz : 0;
            cp16(bOff + (row * HPAD + g * 8) * 2,
                 &W[(size_t)((gn < N) ? gn : 0) * K + cs], szb);
        }
        cp_commit();
    };

    auto compute = [&](int buf) {
        const uint32_t aOff = sA + buf * HSTG * 2;
        const uint32_t bOff = sB + buf * HSTG * 2;
        #pragma unroll
        for (int kk = 0; kk < 4; kk++) {
            const int kb = kk * 16;
            uint32_t af[4][4], bf[4][2];
            #pragma unroll
            for (int mt = 0; mt < 4; mt++) {
                uint32_t a = aOff + (((wm + mt * 16 + laneRowA) * HPAD) + kb + laneKA) * 2;
                LDSM4(af[mt][0], af[mt][1], af[mt][2], af[mt][3], a);
            }
            #pragma unroll
            for (int nt = 0; nt < 4; nt += 2) {
                uint32_t a = bOff + (((wn + nt * 8 + laneRowB) * HPAD) + kb + laneKB) * 2;
                LDSM4(bf[nt][0], bf[nt][1], bf[nt+1][0], bf[nt+1][1], a);
            }
            #pragma unroll
            for (int mt = 0; mt < 4; mt++)
                #pragma unroll
                for (int nt = 0; nt < 4; nt++)
                    MMA_H(acc[mt][nt][0], acc[mt][nt][1], acc[mt][nt][2], acc[mt][nt][3],
                          af[mt][0], af[mt][1], af[mt][2], af[mt][3],
                          bf[nt][0], bf[nt][1]);
        }
    };

    issue_stage(0, 0);
    for (int t = 0; t < kt; t++) {
        cp_wait0();
        __syncthreads();
        if (t + 1 < kt) issue_stage(t + 1, (t + 1) & 1);
        compute(t & 1);
    }

    // Epilogue
    #pragma unroll
    for (int mt = 0; mt < 4; mt++) {
        int r0 = m0 + wm + mt * 16 + qr;
        int r1 = r0 + 8;
        #pragma unroll
        for (int nt = 0; nt < 4; nt++) {
            int col = n0 + wn + nt * 8 + qc * 2;
            if (col < N) {
                float bv0 = bias[col], bv1 = bias[col + 1];
                float v00 = acc[mt][nt][0] + bv0;
                float v01 = acc[mt][nt][1] + bv1;
                float v10 = acc[mt][nt][2] + bv0;
                float v11 = acc[mt][nt][3] + bv1;
                if (MODE == 1) {
                    v00 = v00 / (1.f + expf(-v00));
                    v01 = v01 / (1.f + expf(-v01));
                    v10 = v10 / (1.f + expf(-v10));
                    v11 = v11 / (1.f + expf(-v11));
                }
                if (MODE == 2 || MODE == 3) {
                    float2 e0 = *(const float2*)&extra[(size_t)r0 * ldc + col];
                    float2 e1 = *(const float2*)&extra[(size_t)r1 * ldc + col];
                    if (MODE == 2) { v00 *= e0.x; v01 *= e0.y; v10 *= e1.x; v11 *= e1.y; }
                    else           { v00 += e0.x; v01 += e0.y; v10 += e1.x; v11 += e1.y; }
                }
                if (OUTH) {
                    *(__half2*)&Ch[(size_t)r0 * ldc + col] = __floats2half2_rn(v00, v01);
                    *(__half2*)&Ch[(size_t)r1 * ldc + col] = __floats2half2_rn(v10, v11);
                } else {
                    *(float2*)&C[(size_t)r0 * ldc + col] = make_float2(v00, v01);
                    *(float2*)&C[(size_t)r1 * ldc + col] = make_float2(v10, v11);
                }
            }
        }
    }
}

// ---------------- RoPE + split/transpose (fp16 qkv -> fp16 q,k,v) -----------
__global__ void __launch_bounds__(256) rope_split(const __half* __restrict__ qkv,
                                                  __half* __restrict__ q,
                                                  __half* __restrict__ k,
                                                  __half* __restrict__ v)
{
    int idx = blockIdx.x * 256 + threadIdx.x;
    int i = idx & 31;
    int h = (idx >> 5) & 15;
    int s = (idx >> 9) & 2047;
    int b = idx >> 20;

    const size_t row = ((size_t)(b * Sq + s)) * (3 * Dq);
    const int off = h * HDq;

    float theta = powf(10000.f, -((float)(2 * i)) / 64.f);
    float sn, cs;
    sincosf((float)s * theta, &sn, &cs);

    float q1 = __half2float(qkv[row + off + 2*i]);
    float q2 = __half2float(qkv[row + off + 2*i + 1]);
    float k1 = __half2float(qkv[row + Dq + off + 2*i]);
    float k2 = __half2float(qkv[row + Dq + off + 2*i + 1]);
    __half v1 = qkv[row + 2*Dq + off + 2*i];
    __half v2 = qkv[row + 2*Dq + off + 2*i + 1];

    size_t orow = ((size_t)(b * Hq + h) * Sq + s) * HDq;
    q[orow + i]      = __float2half_rn(q1 * cs - q2 * sn);
    q[orow + 32 + i] = __float2half_rn(q1 * sn + q2 * cs);
    k[orow + i]      = __float2half_rn(k1 * cs - k2 * sn);
    k[orow + 32 + i] = __float2half_rn(k1 * sn + k2 * cs);
    v[orow + 2*i]     = v1;
    v[orow + 2*i + 1] = v2;
}

// ---------------- FP16 tensor-core causal flash attention (ldmatrix) --------
#define FA_BM 128
#define FA_BN 64
#define FPH 72
#define FA_SMEMH ((FA_BM*FPH + FA_BN*FPH + FA_BN*FPH + FA_BM*FPH) * 2)

__global__ void __launch_bounds__(256, 2) flash_attn_h(const __half* __restrict__ Q,
                                                       const __half* __restrict__ K,
                                                       const __half* __restrict__ V,
                                                       __half* __restrict__ O)
{
    extern __shared__ __half fh[];
    __half* Qs = fh;                      // [128][72]
    __half* Ks = Qs + FA_BM * FPH;        // [64][72]
    __half* Vt = Ks + FA_BN * FPH;        // [hd 64][key 72]
    __half* Ps = Vt + FA_BN * FPH;        // [128][72]
    const uint32_t sQs = (uint32_t)__cvta_generic_to_shared(Qs);
    const uint32_t sKs = (uint32_t)__cvta_generic_to_shared(Ks);
    const uint32_t sVt = (uint32_t)__cvta_generic_to_shared(Vt);
    const uint32_t sPs = (uint32_t)__cvta_generic_to_shared(Ps);

    const int qt = gridDim.x - 1 - blockIdx.x;
    const int h = blockIdx.y, b = blockIdx.z;
    const int qm0 = qt * FA_BM;
    const size_t base = ((size_t)(b * Hq + h)) * Sq * HDq;
    const __half* Qb = Q + base;
    const __half* Kb = K + base;
    const __half* Vb = V + base;

    const int tid  = threadIdx.x;
    const int lane = tid & 31;
    const int w    = tid >> 5;
    const int qr   = lane >> 2;
    const int qc   = lane & 3;
    const int wrow = w * 16;

    const int laneRowA = lane & 15;
    const int laneKA   = (lane >> 4) << 3;
    const int laneRowB = (lane & 7) + ((lane >> 4) << 3);
    const int laneKB   = ((lane >> 3) & 1) << 3;

    for (int i = tid; i < FA_BM * 32; i += 256) {   // half2 granules
        int r = i >> 5, c2 = i & 31;
        __half2 v = ((const __half2*)Qb)[(size_t)(qm0 + r) * 32 + c2];
        *(__half2*)&Qs[r * FPH + c2 * 2] = v;
    }

    float o[8][4];
    #pragma unroll
    for (int j = 0; j < 8; j++)
        #pragma unroll
        for (int t = 0; t < 4; t++) o[j][t] = 0.f;
    float m0 = -1e30f, m1 = -1e30f, l0 = 0.f, l1 = 0.f;

    const int row0 = qm0 + wrow + qr;
    const int row1 = row0 + 8;
    const int nkt = (qm0 + FA_BM) / FA_BN;

    for (int kt = 0; kt < nkt; kt++) {
        const int kn0 = kt * FA_BN;
        __syncthreads();
        for (int i = tid; i < FA_BN * 32; i += 256) {
            int r = i >> 5, c2 = i & 31;
            __half2 kv = ((const __half2*)Kb)[(size_t)(kn0 + r) * 32 + c2];
            *(__half2*)&Ks[r * FPH + c2 * 2] = kv;
            __half2 vv = ((const __half2*)Vb)[(size_t)(kn0 + r) * 32 + c2];
            Vt[(c2 * 2)     * FPH + r] = __low2half(vv);
            Vt[(c2 * 2 + 1) * FPH + r] = __high2half(vv);
        }
        __syncthreads();

        const bool active = (kn0 <= qm0 + wrow + 15);
        if (active) {
            // ---- S = Q @ K^T ----
            float s[8][4];
            #pragma unroll
            for (int j = 0; j < 8; j++)
                #pragma unroll
                for (int t = 0; t < 4; t++) s[j][t] = 0.f;

            #pragma unroll
            for (int kk = 0; kk < 4; kk++) {
                const int kb = kk * 16;
                uint32_t a0, a1, a2, a3;
                LDSM4(a0, a1, a2, a3,
                      sQs + (((wrow + laneRowA) * FPH) + kb + laneKA) * 2);
                #pragma unroll
                for (int j = 0; j < 8; j += 2) {
                    uint32_t b0, b1, b2, b3;
                    LDSM4(b0, b1, b2, b3,
                          sKs + (((j * 8 + laneRowB) * FPH) + kb + laneKB) * 2);
                    MMA_H(s[j][0],   s[j][1],   s[j][2],   s[j][3],   a0,a1,a2,a3, b0,b1);
                    MMA_H(s[j+1][0], s[j+1][1], s[j+1][2], s[j+1][3], a0,a1,a2,a3, b2,b3);
                }
            }

            // ---- causal mask + online softmax ----
            float rmax0 = -1e30f, rmax1 = -1e30f;
            #pragma unroll
            for (int j = 0; j < 8; j++) {
                int c0 = kn0 + j * 8 + 2 * qc, c1 = c0 + 1;
                s[j][0] = (c0 <= row0) ? s[j][0] * 0.125f : -1e30f;
                s[j][1] = (c1 <= row0) ? s[j][1] * 0.125f : -1e30f;
                s[j][2] = (c0 <= row1) ? s[j][2] * 0.125f : -1e30f;
                s[j][3] = (c1 <= row1) ? s[j][3] * 0.125f : -1e30f;
                rmax0 = fmaxf(rmax0, fmaxf(s[j][0], s[j][1]));
                rmax1 = fmaxf(rmax1, fmaxf(s[j][2], s[j][3]));
            }
            rmax0 = fmaxf(rmax0, __shfl_xor_sync(0xffffffffu, rmax0, 1));
            rmax0 = fmaxf(rmax0, __shfl_xor_sync(0xffffffffu, rmax0, 2));
            rmax1 = fmaxf(rmax1, __shfl_xor_sync(0xffffffffu, rmax1, 1));
            rmax1 = fmaxf(rmax1, __shfl_xor_sync(0xffffffffu, rmax1, 2));

            float mn0 = fmaxf(m0, rmax0), mn1 = fmaxf(m1, rmax1);
            float a0 = __expf(m0 - mn0),  a1 = __expf(m1 - mn1);
            float rs0 = 0.f, rs1 = 0.f;
            __half* pr0 = Ps + (wrow + qr) * FPH;
            __half* pr1 = pr0 + 8 * FPH;
            #pragma unroll
            for (int j = 0; j < 8; j++) {
                __half2 h0 = __floats2half2_rn(__expf(s[j][0] - mn0),
                                               __expf(s[j][1] - mn0));
                __half2 h1 = __floats2half2_rn(__expf(s[j][2] - mn1),
                                               __expf(s[j][3] - mn1));
                *(__half2*)&pr0[j * 8 + 2 * qc] = h0;
                *(__half2*)&pr1[j * 8 + 2 * qc] = h1;
                float2 f0 = __half22float2(h0), f1 = __half22float2(h1);
                rs0 += f0.x + f0.y;
                rs1 += f1.x + f1.y;
            }
            rs0 += __shfl_xor_sync(0xffffffffu, rs0, 1);
            rs0 += __shfl_xor_sync(0xffffffffu, rs0, 2);
            rs1 += __shfl_xor_sync(0xffffffffu, rs1, 1);
            rs1 += __shfl_xor_sync(0xffffffffu, rs1, 2);

            l0 = l0 * a0 + rs0; m0 = mn0;
            l1 = l1 * a1 + rs1; m1 = mn1;
            #pragma unroll
            for (int j = 0; j < 8; j++) {
                o[j][0] *= a0; o[j][1] *= a0;
                o[j][2] *= a1; o[j][3] *= a1;
            }
            __syncwarp();

            // ---- O += P @ V ----
            #pragma unroll
            for (int kk = 0; kk < 4; kk++) {
                const int kb = kk * 16;
                uint32_t a0f, a1f, a2f, a3f;
                LDSM4(a0f, a1f, a2f, a3f,
                      sPs + (((wrow + laneRowA) * FPH) + kb + laneKA) * 2);
                #pragma unroll
                for (int j = 0; j < 8; j += 2) {
                    uint32_t b0, b1, b2, b3;
                    LDSM4(b0, b1, b2, b3,
                          sVt + (((j * 8 + laneRowB) * FPH) + kb + laneKB) * 2);
                    MMA_H(o[j][0],   o[j][1],   o[j][2],   o[j][3],   a0f,a1f,a2f,a3f, b0,b1);
                    MMA_H(o[j+1][0], o[j+1][1], o[j+1][2], o[j+1][3], a0f,a1f,a2f,a3f, b2,b3);
                }
            }
        }
    }

    // ---- normalize + write O (fp16) as [b, s, h*64 + c] ----
    float inv0 = 1.f / l0, inv1 = 1.f / l1;
    #pragma unroll
    for (int j = 0; j < 8; j++) {
        int col = h * HDq + j * 8 + 2 * qc;
        size_t o0 = ((size_t)(b * Sq + row0)) * Dq + col;
        size_t o1 = ((size_t)(b * Sq + row1)) * Dq + col;
        *(__half2*)&O[o0] = __floats2half2_rn(o[j][0] * inv0, o[j][1] * inv0);
        *(__half2*)&O[o1] = __floats2half2_rn(o[j][2] * inv1, o[j][3] * inv1);
    }
}

// ---------------- launch --------------------------------------------------
extern "C" void kernel_launch(void* const* d_in, const int* in_sizes, int n_in,
                              void* d_out, int out_size)
{
    const float* x          = (const float*)d_in[0];
    const float* gamma_attn = (const float*)d_in[2];
    const float* w_qkv      = (const float*)d_in[3];
    const float* b_qkv      = (const float*)d_in[4];
    const float* w_out      = (const float*)d_in[5];
    const float* b_out      = (const float*)d_in[6];
    const float* gamma_ffn  = (const float*)d_in[7];
    const float* w1         = (const float*)d_in[8];
    const float* b1         = (const float*)d_in[9];
    const float* w2         = (const float*)d_in[10];
    const float* b2         = (const float*)d_in[11];
    const float* w3         = (const float*)d_in[12];
    const float* b3         = (const float*)d_in[13];
    float* out = (float*)d_out;

    float  *xn, *h, *hn, *ff2;
    __half *xnh, *qkvh, *qh, *kh, *vh, *attnh, *hnh, *ff1h;
    __half *wqkvh, *wouth, *w1h, *w2h, *w3ph;
    cudaGetSymbolAddress((void**)&xn,    g_xn);
    cudaGetSymbolAddress((void**)&xnh,   g_xnh);
    cudaGetSymbolAddress((void**)&qkvh,  g_qkvh);
    cudaGetSymbolAddress((void**)&qh,    g_qh);
    cudaGetSymbolAddress((void**)&kh,    g_kh);
    cudaGetSymbolAddress((void**)&vh,    g_vh);
    cudaGetSymbolAddress((void**)&attnh, g_attnh);
    cudaGetSymbolAddress((void**)&h,     g_h);
    cudaGetSymbolAddress((void**)&hn,    g_hn);
    cudaGetSymbolAddress((void**)&hnh,   g_hnh);
    cudaGetSymbolAddress((void**)&ff1h,  g_ff1h);
    cudaGetSymbolAddress((void**)&ff2,   g_ff2);
    cudaGetSymbolAddress((void**)&wqkvh, g_wqkvh);
    cudaGetSymbolAddress((void**)&wouth, g_wouth);
    cudaGetSymbolAddress((void**)&w1h,   g_w1h);
    cudaGetSymbolAddress((void**)&w2h,   g_w2h);
    cudaGetSymbolAddress((void**)&w3ph,  g_w3ph);

    cudaFuncSetAttribute(gemm_h<0,1>, cudaFuncAttributeMaxDynamicSharedMemorySize, SMEM_H);
    cudaFuncSetAttribute(gemm_h<1,0>, cudaFuncAttributeMaxDynamicSharedMemorySize, SMEM_H);
    cudaFuncSetAttribute(gemm_h<2,1>, cudaFuncAttributeMaxDynamicSharedMemorySize, SMEM_H);
    cudaFuncSetAttribute(gemm_h<3,0>, cudaFuncAttributeMaxDynamicSharedMemorySize, SMEM_H);
    cudaFuncSetAttribute(flash_attn_h, cudaFuncAttributeMaxDynamicSharedMemorySize, FA_SMEMH);

    // 0) convert weights to fp16 once; zero ff1 pads
    {
        int n;
        n = 3*Dq*Dq/4;  conv_half<<<(n+255)/256, 256>>>(w_qkv, wqkvh, n);
        n = Dq*Dq/4;    conv_half<<<(n+255)/256, 256>>>(w_out, wouth, n);
        n = DIq*Dq/4;   conv_half<<<(n+255)/256, 256>>>(w1, w1h, n);
        n = DIq*Dq/4;   conv_half<<<(n+255)/256, 256>>>(w2, w2h, n);
        n = Dq*DIpad;   conv_half_pad<<<(n+255)/256, 256>>>(w3, w3ph, Dq, DIq, DIpad);
        n = BSq*(DIpad-DIq); zero_pad_ff1<<<(n+255)/256, 256>>>(ff1h);
    }

    // 1) xn = rmsnorm(x, gamma_attn)  (fp32 + fp16)
    rmsnorm_k<<<BSq, 256>>>(x, gamma_attn, xn, xnh);

    // 2) qkvh = xnh @ wqkvh^T + b_qkv          [4096, 3072] fp16 out
    gemm_h<0,1><<<dim3(3*Dq/128, BSq/128), 256, SMEM_H>>>(
        xnh, wqkvh, b_qkv, nullptr, nullptr, qkvh, BSq, 3*Dq, Dq, Dq, 3*Dq);

    // 3) rope + split -> fp16 q,k,v
    rope_split<<<(Bq*Sq*Hq*32)/256, 256>>>(qkvh, qh, kh, vh);

    // 4) flash attention -> attnh (fp16)
    flash_attn_h<<<dim3(Sq/FA_BM, Hq, Bq), 256, FA_SMEMH>>>(qh, kh, vh, attnh);

    // 5) h = xn + attnh @ wouth^T + b_out      (fp32 out)
    gemm_h<3,0><<<dim3(Dq/128, BSq/128), 256, SMEM_H>>>(
        attnh, wouth, b_out, xn, h, nullptr, BSq, Dq, Dq, Dq, Dq);

    // 6) hn = rmsnorm(h, gamma_ffn)  (fp32 + fp16)
    rmsnorm_k<<<BSq, 256>>>(h, gamma_ffn, hn, hnh);

    // 7) gate = silu(hnh @ w2h^T + b2)         (fp32 out, stride DIpad)
    gemm_h<1,0><<<dim3((DIq+127)/128, BSq/128), 256, SMEM_H>>>(
        hnh, w2h, b2, nullptr, ff2, nullptr, BSq, DIq, Dq, Dq, DIpad);

    // 8) ff1 = (hnh @ w1h^T + b1) * gate       (fp16 out)
    gemm_h<2,1><<<dim3((DIq+127)/128, BSq/128), 256, SMEM_H>>>(
        hnh, w1h, b1, ff2, nullptr, ff1h, BSq, DIq, Dq, Dq, DIpad);

    // 9) out = hn + ff1h @ w3ph^T + b3         (K padded to 2736, pads zero)
    gemm_h<3,0><<<dim3(Dq/128, BSq/128), 256, SMEM_H>>>(
        ff1h, w3ph, b3, hn, out, nullptr, BSq, Dq, DIpad, DIpad, Dq);
}

// round 12
// speedup vs baseline: 8.6610x; 1.1669x over previous
#include <cuda_runtime.h>
#include <cuda_fp16.h>
#include <math.h>
#include <stdint.h>

// Problem constants
#define Bq  2
#define Sq  2048
#define Dq  1024
#define Hq  16
#define HDq 64
#define DIq 2730            // int(8/3 * 1024)
#define DIpad 2736          // padded row stride
#define BSq (Bq*Sq)         // 4096 rows

// ---------------- scratch (device globals; no allocation allowed) -----------
__device__ float  g_xn  [(size_t)BSq*Dq];
__device__ __half g_xnh [(size_t)BSq*Dq];
__device__ __half g_qkvh[(size_t)BSq*3*Dq];
__device__ __half g_qh  [(size_t)Bq*Hq*Sq*HDq];
__device__ __half g_kh  [(size_t)Bq*Hq*Sq*HDq];
__device__ __half g_vh  [(size_t)Bq*Hq*Sq*HDq];
__device__ __half g_attnh[(size_t)BSq*Dq];
__device__ float  g_h   [(size_t)BSq*Dq];
__device__ float  g_hn  [(size_t)BSq*Dq];
__device__ __half g_hnh [(size_t)BSq*Dq];
__device__ __half g_ff1h[(size_t)BSq*DIpad];
__device__ float  g_ff2 [(size_t)BSq*DIpad];   // gate, fp32
// fp16 weight copies
__device__ __half g_wqkvh[(size_t)3*Dq*Dq];
__device__ __half g_wouth[(size_t)Dq*Dq];
__device__ __half g_w1h  [(size_t)DIq*Dq];
__device__ __half g_w2h  [(size_t)DIq*Dq];
__device__ __half g_w3ph [(size_t)Dq*DIpad];   // padded [1024][2736], zeros in pad

// ---------------- conversion kernels (4x ILP, grid-stride) ------------------
__global__ void __launch_bounds__(256) conv_half(const float* __restrict__ src,
                                                 __half* __restrict__ dst, int n4)
{
    int i0 = (blockIdx.x * 256 + threadIdx.x) * 4;
    int stride = gridDim.x * 256 * 4;
    for (int i = i0; i < n4 + 3; i += stride) {
        float4 v[4];
        #pragma unroll
        for (int u = 0; u < 4; u++)
            if (i + u < n4) v[u] = ((const float4*)src)[i + u];
        #pragma unroll
        for (int u = 0; u < 4; u++)
            if (i + u < n4) {
                ((__half2*)dst)[(i+u)*2]   = __floats2half2_rn(v[u].x, v[u].y);
                ((__half2*)dst)[(i+u)*2+1] = __floats2half2_rn(v[u].z, v[u].w);
            }
    }
}

__global__ void __launch_bounds__(256) conv_half_pad(const float* __restrict__ src,
                                                     __half* __restrict__ dst,
                                                     int rows, int cin, int cpad)
{
    int i = blockIdx.x * 256 + threadIdx.x;
    if (i < rows * cpad) {
        int r = i / cpad, c = i - r * cpad;
        dst[i] = (c < cin) ? __float2half_rn(src[(size_t)r * cin + c]) : __half(0.f);
    }
}

__global__ void __launch_bounds__(256) zero_pad_ff1(__half* __restrict__ ff1)
{
    int i = blockIdx.x * 256 + threadIdx.x;
    if (i < BSq * (DIpad - DIq)) {
        int r = i / (DIpad - DIq), c = DIq + i % (DIpad - DIq);
        ff1[(size_t)r * DIpad + c] = __half(0.f);
    }
}

// ---------------- RMSNorm: dual output (fp32 + fp16) ------------------------
__global__ void __launch_bounds__(256) rmsnorm_k(const float* __restrict__ x,
                                                 const float* __restrict__ gamma,
                                                 float* __restrict__ out,
                                                 __half* __restrict__ out_h)
{
    const size_t row = blockIdx.x;
    const float* xr = x + row * Dq;
    float ss = 0.f;
    for (int c = threadIdx.x; c < Dq; c += 256) { float v = xr[c]; ss += v * v; }
    #pragma unroll
    for (int d = 16; d > 0; d >>= 1) ss += __shfl_xor_sync(0xffffffffu, ss, d);
    __shared__ float red[8];
    __shared__ float s_inv;
    if ((threadIdx.x & 31) == 0) red[threadIdx.x >> 5] = ss;
    __syncthreads();
    if (threadIdx.x == 0) {
        float t = 0.f;
        #pragma unroll
        for (int i = 0; i < 8; i++) t += red[i];
        s_inv = rsqrtf(t / (float)Dq + 1e-5f);
    }
    __syncthreads();
    const float inv = s_inv;
    for (int c = threadIdx.x; c < Dq; c += 256) {
        float v = xr[c] * inv * gamma[c];
        out[row * Dq + c]   = v;
        out_h[row * Dq + c] = __float2half_rn(v);
    }
}

// ---------------- cp.async / ldmatrix helpers --------------------------------
__device__ __forceinline__ void cp16(uint32_t dst, const void* src, int sz) {
    asm volatile("cp.async.cg.shared.global [%0], [%1], 16, %2;"
                 :: "r"(dst), "l"(src), "r"(sz));
}
__device__ __forceinline__ void cp_commit() { asm volatile("cp.async.commit_group;"); }
__device__ __forceinline__ void cp_wait0()  { asm volatile("cp.async.wait_group 0;" ::: "memory"); }

#define LDSM4(r0, r1, r2, r3, a) \
    asm volatile("ldmatrix.sync.aligned.m8n8.x4.shared.b16 {%0,%1,%2,%3}, [%4];" \
                 : "=r"(r0), "=r"(r1), "=r"(r2), "=r"(r3) : "r"(a))

#define MMA_H(d0,d1,d2,d3, a0,a1,a2,a3, b0,b1) \
    asm volatile("mma.sync.aligned.m16n8k16.row.col.f32.f16.f16.f32 " \
                 "{%0,%1,%2,%3}, {%4,%5,%6,%7}, {%8,%9}, {%0,%1,%2,%3};" \
                 : "+f"(d0), "+f"(d1), "+f"(d2), "+f"(d3) \
                 : "r"(a0), "r"(a1), "r"(a2), "r"(a3), "r"(b0), "r"(b1))

// ---------------- FP16 GEMM (mma.m16n8k16 + ldmatrix), 2 CTA/SM -------------
// C[M,N] = A[M,K] @ W[N,K]^T ; A,W fp16; acc fp32.
// MODE 0: +bias | 1: silu(+bias) | 2: (+bias)*extra | 3: (+bias)+extra
// OUTH 1: store fp16 to Ch, else fp32 to C.
#define HBK 64                      // halves per k-chunk
#define HPAD 72                     // halves stride (144 B -> conflict-free)
#define HSTG (128 * HPAD)           // halves per operand stage
#define SMEM_H (4 * HSTG * 2)       // 2 bufs x 2 ops x bytes = 73728

template <int MODE, int OUTH>
__global__ void __launch_bounds__(256, 2) gemm_h(const __half* __restrict__ A,
                                                 const __half* __restrict__ W,
                                                 const float* __restrict__ bias,
                                                 const float* __restrict__ extra,
                                                 float* __restrict__ C,
                                                 __half* __restrict__ Ch,
                                                 int M, int N, int K,
                                                 int lda, int ldc)
{
    extern __shared__ __half hs[];
    const uint32_t sAll = (uint32_t)__cvta_generic_to_shared(hs);
    const uint32_t sA = sAll;                    // [2][128][72]
    const uint32_t sB = sAll + 2 * HSTG * 2;     // [2][128][72]

    const int tid  = threadIdx.x;
    const int lane = tid & 31;
    const int w    = tid >> 5;
    const int wm   = (w >> 2) * 64;
    const int wn   = (w & 3) * 32;
    const int m0   = blockIdx.y * 128;
    const int n0   = blockIdx.x * 128;
    const int qr   = lane >> 2;
    const int qc   = lane & 3;

    const int laneRowA = lane & 15;
    const int laneKA   = (lane >> 4) << 3;
    const int laneRowB = (lane & 7) + ((lane >> 4) << 3);
    const int laneKB   = ((lane >> 3) & 1) << 3;

    float acc[4][4][4];
    #pragma unroll
    for (int i = 0; i < 4; i++)
        #pragma unroll
        for (int j = 0; j < 4; j++)
            #pragma unroll
            for (int t = 0; t < 4; t++) acc[i][j][t] = 0.f;

    const int kt = (K + HBK - 1) / HBK;

    auto issue_stage = [&](int t, int buf) {
        const int k0 = t * HBK;
        const uint32_t aOff = sA + buf * HSTG * 2;
        const uint32_t bOff = sB + buf * HSTG * 2;
        #pragma unroll
        for (int i = 0; i < 4; i++) {             // 1024 16B-granules / operand
            int idx = tid + i * 256;
            int row = idx >> 3;                   // 0..127
            int g   = idx & 7;                    // 8 granules of 8 halves
            int gk  = k0 + g * 8;
            int sz  = (gk < K) ? 16 : 0;
            int cs  = sz ? gk : 0;
            cp16(aOff + (row * HPAD + g * 8) * 2,
                 &A[(size_t)(m0 + row) * lda + cs], sz);
            int gn = n0 + row;
            int szb = (gn < N) ? sz : 0;
            cp16(bOff + (row * HPAD + g * 8) * 2,
                 &W[(size_t)((gn < N) ? gn : 0) * K + cs], szb);
        }
        cp_commit();
    };

    auto compute = [&](int buf) {
        const uint32_t aOff = sA + buf * HSTG * 2;
        const uint32_t bOff = sB + buf * HSTG * 2;
        #pragma unroll
        for (int kk = 0; kk < 4; kk++) {
            const int kb = kk * 16;
            uint32_t af[4][4], bf[4][2];
            #pragma unroll
            for (int mt = 0; mt < 4; mt++) {
                uint32_t a = aOff + (((wm + mt * 16 + laneRowA) * HPAD) + kb + laneKA) * 2;
                LDSM4(af[mt][0], af[mt][1], af[mt][2], af[mt][3], a);
            }
            #pragma unroll
            for (int nt = 0; nt < 4; nt += 2) {
                uint32_t a = bOff + (((wn + nt * 8 + laneRowB) * HPAD) + kb + laneKB) * 2;
                LDSM4(bf[nt][0], bf[nt][1], bf[nt+1][0], bf[nt+1][1], a);
            }
            #pragma unroll
            for (int mt = 0; mt < 4; mt++)
                #pragma unroll
                for (int nt = 0; nt < 4; nt++)
                    MMA_H(acc[mt][nt][0], acc[mt][nt][1], acc[mt][nt][2], acc[mt][nt][3],
                          af[mt][0], af[mt][1], af[mt][2], af[mt][3],
                          bf[nt][0], bf[nt][1]);
        }
    };

    issue_stage(0, 0);
    for (int t = 0; t < kt; t++) {
        cp_wait0();
        __syncthreads();
        if (t + 1 < kt) issue_stage(t + 1, (t + 1) & 1);
        compute(t & 1);
    }

    // Epilogue
    #pragma unroll
    for (int mt = 0; mt < 4; mt++) {
        int r0 = m0 + wm + mt * 16 + qr;
        int r1 = r0 + 8;
        #pragma unroll
        for (int nt = 0; nt < 4; nt++) {
            int col = n0 + wn + nt * 8 + qc * 2;
            if (col < N) {
                float bv0 = bias[col], bv1 = bias[col + 1];
                float v00 = acc[mt][nt][0] + bv0;
                float v01 = acc[mt][nt][1] + bv1;
                float v10 = acc[mt][nt][2] + bv0;
                float v11 = acc[mt][nt][3] + bv1;
                if (MODE == 1) {
                    v00 = v00 / (1.f + expf(-v00));
                    v01 = v01 / (1.f + expf(-v01));
                    v10 = v10 / (1.f + expf(-v10));
                    v11 = v11 / (1.f + expf(-v11));
                }
                if (MODE == 2 || MODE == 3) {
                    float2 e0 = *(const float2*)&extra[(size_t)r0 * ldc + col];
                    float2 e1 = *(const float2*)&extra[(size_t)r1 * ldc + col];
                    if (MODE == 2) { v00 *= e0.x; v01 *= e0.y; v10 *= e1.x; v11 *= e1.y; }
                    else           { v00 += e0.x; v01 += e0.y; v10 += e1.x; v11 += e1.y; }
                }
                if (OUTH) {
                    *(__half2*)&Ch[(size_t)r0 * ldc + col] = __floats2half2_rn(v00, v01);
                    *(__half2*)&Ch[(size_t)r1 * ldc + col] = __floats2half2_rn(v10, v11);
                } else {
                    *(float2*)&C[(size_t)r0 * ldc + col] = make_float2(v00, v01);
                    *(float2*)&C[(size_t)r1 * ldc + col] = make_float2(v10, v11);
                }
            }
        }
    }
}

// ---------------- RoPE + split/transpose (fp16 qkv -> fp16 q,k,v) -----------
__global__ void __launch_bounds__(256) rope_split(const __half* __restrict__ qkv,
                                                  __half* __restrict__ q,
                                                  __half* __restrict__ k,
                                                  __half* __restrict__ v)
{
    int idx = blockIdx.x * 256 + threadIdx.x;
    int i = idx & 31;
    int h = (idx >> 5) & 15;
    int s = (idx >> 9) & 2047;
    int b = idx >> 20;

    const size_t row = ((size_t)(b * Sq + s)) * (3 * Dq);
    const int off = h * HDq;

    float theta = powf(10000.f, -((float)(2 * i)) / 64.f);
    float sn, cs;
    sincosf((float)s * theta, &sn, &cs);

    float q1 = __half2float(qkv[row + off + 2*i]);
    float q2 = __half2float(qkv[row + off + 2*i + 1]);
    float k1 = __half2float(qkv[row + Dq + off + 2*i]);
    float k2 = __half2float(qkv[row + Dq + off + 2*i + 1]);
    __half v1 = qkv[row + 2*Dq + off + 2*i];
    __half v2 = qkv[row + 2*Dq + off + 2*i + 1];

    size_t orow = ((size_t)(b * Hq + h) * Sq + s) * HDq;
    q[orow + i]      = __float2half_rn(q1 * cs - q2 * sn);
    q[orow + 32 + i] = __float2half_rn(q1 * sn + q2 * cs);
    k[orow + i]      = __float2half_rn(k1 * cs - k2 * sn);
    k[orow + 32 + i] = __float2half_rn(k1 * sn + k2 * cs);
    v[orow + 2*i]     = v1;
    v[orow + 2*i + 1] = v2;
}

// ---------------- FP16 tensor-core causal flash attention (ldmatrix) --------
#define FA_BM 128
#define FA_BN 64
#define FPH 72
#define FA_SMEMH ((FA_BM*FPH + FA_BN*FPH + FA_BN*FPH + FA_BM*FPH) * 2)

__global__ void __launch_bounds__(256, 2) flash_attn_h(const __half* __restrict__ Q,
                                                       const __half* __restrict__ K,
                                                       const __half* __restrict__ V,
                                                       __half* __restrict__ O)
{
    extern __shared__ __half fh[];
    __half* Qs = fh;                      // [128][72]
    __half* Ks = Qs + FA_BM * FPH;        // [64][72]
    __half* Vt = Ks + FA_BN * FPH;        // [hd 64][key 72]
    __half* Ps = Vt + FA_BN * FPH;        // [128][72]
    const uint32_t sQs = (uint32_t)__cvta_generic_to_shared(Qs);
    const uint32_t sKs = (uint32_t)__cvta_generic_to_shared(Ks);
    const uint32_t sVt = (uint32_t)__cvta_generic_to_shared(Vt);
    const uint32_t sPs = (uint32_t)__cvta_generic_to_shared(Ps);

    const int qt = gridDim.x - 1 - blockIdx.x;
    const int h = blockIdx.y, b = blockIdx.z;
    const int qm0 = qt * FA_BM;
    const size_t base = ((size_t)(b * Hq + h)) * Sq * HDq;
    const __half* Qb = Q + base;
    const __half* Kb = K + base;
    const __half* Vb = V + base;

    const int tid  = threadIdx.x;
    const int lane = tid & 31;
    const int w    = tid >> 5;
    const int qr   = lane >> 2;
    const int qc   = lane & 3;
    const int wrow = w * 16;

    const int laneRowA = lane & 15;
    const int laneKA   = (lane >> 4) << 3;
    const int laneRowB = (lane & 7) + ((lane >> 4) << 3);
    const int laneKB   = ((lane >> 3) & 1) << 3;

    for (int i = tid; i < FA_BM * 32; i += 256) {   // half2 granules
        int r = i >> 5, c2 = i & 31;
        __half2 v = ((const __half2*)Qb)[(size_t)(qm0 + r) * 32 + c2];
        *(__half2*)&Qs[r * FPH + c2 * 2] = v;
    }

    float o[8][4];
    #pragma unroll
    for (int j = 0; j < 8; j++)
        #pragma unroll
        for (int t = 0; t < 4; t++) o[j][t] = 0.f;
    float m0 = -1e30f, m1 = -1e30f, l0 = 0.f, l1 = 0.f;

    const int row0 = qm0 + wrow + qr;
    const int row1 = row0 + 8;
    const int nkt = (qm0 + FA_BM) / FA_BN;

    for (int kt = 0; kt < nkt; kt++) {
        const int kn0 = kt * FA_BN;
        __syncthreads();
        for (int i = tid; i < FA_BN * 32; i += 256) {
            int r = i >> 5, c2 = i & 31;
            __half2 kv = ((const __half2*)Kb)[(size_t)(kn0 + r) * 32 + c2];
            *(__half2*)&Ks[r * FPH + c2 * 2] = kv;
            __half2 vv = ((const __half2*)Vb)[(size_t)(kn0 + r) * 32 + c2];
            Vt[(c2 * 2)     * FPH + r] = __low2half(vv);
            Vt[(c2 * 2 + 1) * FPH + r] = __high2half(vv);
        }
        __syncthreads();

        const bool active = (kn0 <= qm0 + wrow + 15);
        if (active) {
            // ---- S = Q @ K^T ----
            float s[8][4];
            #pragma unroll
            for (int j = 0; j < 8; j++)
                #pragma unroll
                for (int t = 0; t < 4; t++) s[j][t] = 0.f;

            #pragma unroll
            for (int kk = 0; kk < 4; kk++) {
                const int kb = kk * 16;
                uint32_t a0, a1, a2, a3;
                LDSM4(a0, a1, a2, a3,
                      sQs + (((wrow + laneRowA) * FPH) + kb + laneKA) * 2);
                #pragma unroll
                for (int j = 0; j < 8; j += 2) {
                    uint32_t b0, b1, b2, b3;
                    LDSM4(b0, b1, b2, b3,
                          sKs + (((j * 8 + laneRowB) * FPH) + kb + laneKB) * 2);
                    MMA_H(s[j][0],   s[j][1],   s[j][2],   s[j][3],   a0,a1,a2,a3, b0,b1);
                    MMA_H(s[j+1][0], s[j+1][1], s[j+1][2], s[j+1][3], a0,a1,a2,a3, b2,b3);
                }
            }

            // ---- causal mask + online softmax ----
            float rmax0 = -1e30f, rmax1 = -1e30f;
            #pragma unroll
            for (int j = 0; j < 8; j++) {
                int c0 = kn0 + j * 8 + 2 * qc, c1 = c0 + 1;
                s[j][0] = (c0 <= row0) ? s[j][0] * 0.125f : -1e30f;
                s[j][1] = (c1 <= row0) ? s[j][1] * 0.125f : -1e30f;
                s[j][2] = (c0 <= row1) ? s[j][2] * 0.125f : -1e30f;
                s[j][3] = (c1 <= row1) ? s[j][3] * 0.125f : -1e30f;
                rmax0 = fmaxf(rmax0, fmaxf(s[j][0], s[j][1]));
                rmax1 = fmaxf(rmax1, fmaxf(s[j][2], s[j][3]));
            }
            rmax0 = fmaxf(rmax0, __shfl_xor_sync(0xffffffffu, rmax0, 1));
            rmax0 = fmaxf(rmax0, __shfl_xor_sync(0xffffffffu, rmax0, 2));
            rmax1 = fmaxf(rmax1, __shfl_xor_sync(0xffffffffu, rmax1, 1));
            rmax1 = fmaxf(rmax1, __shfl_xor_sync(0xffffffffu, rmax1, 2));

            float mn0 = fmaxf(m0, rmax0), mn1 = fmaxf(m1, rmax1);
            float a0 = __expf(m0 - mn0),  a1 = __expf(m1 - mn1);
            float rs0 = 0.f, rs1 = 0.f;
            __half* pr0 = Ps + (wrow + qr) * FPH;
            __half* pr1 = pr0 + 8 * FPH;
            #pragma unroll
            for (int j = 0; j < 8; j++) {
                __half2 h0 = __floats2half2_rn(__expf(s[j][0] - mn0),
                                               __expf(s[j][1] - mn0));
                __half2 h1 = __floats2half2_rn(__expf(s[j][2] - mn1),
                                               __expf(s[j][3] - mn1));
                *(__half2*)&pr0[j * 8 + 2 * qc] = h0;
                *(__half2*)&pr1[j * 8 + 2 * qc] = h1;
                float2 f0 = __half22float2(h0), f1 = __half22float2(h1);
                rs0 += f0.x + f0.y;
                rs1 += f1.x + f1.y;
            }
            rs0 += __shfl_xor_sync(0xffffffffu, rs0, 1);
            rs0 += __shfl_xor_sync(0xffffffffu, rs0, 2);
            rs1 += __shfl_xor_sync(0xffffffffu, rs1, 1);
            rs1 += __shfl_xor_sync(0xffffffffu, rs1, 2);

            l0 = l0 * a0 + rs0; m0 = mn0;
            l1 = l1 * a1 + rs1; m1 = mn1;
            #pragma unroll
            for (int j = 0; j < 8; j++) {
                o[j][0] *= a0; o[j][1] *= a0;
                o[j][2] *= a1; o[j][3] *= a1;
            }
            __syncwarp();

            // ---- O += P @ V ----
            #pragma unroll
            for (int kk = 0; kk < 4; kk++) {
                const int kb = kk * 16;
                uint32_t a0f, a1f, a2f, a3f;
                LDSM4(a0f, a1f, a2f, a3f,
                      sPs + (((wrow + laneRowA) * FPH) + kb + laneKA) * 2);
                #pragma unroll
                for (int j = 0; j < 8; j += 2) {
                    uint32_t b0, b1, b2, b3;
                    LDSM4(b0, b1, b2, b3,
                          sVt + (((j * 8 + laneRowB) * FPH) + kb + laneKB) * 2);
                    MMA_H(o[j][0],   o[j][1],   o[j][2],   o[j][3],   a0f,a1f,a2f,a3f, b0,b1);
                    MMA_H(o[j+1][0], o[j+1][1], o[j+1][2], o[j+1][3], a0f,a1f,a2f,a3f, b2,b3);
                }
            }
        }
    }

    // ---- normalize + write O (fp16) as [b, s, h*64 + c] ----
    float inv0 = 1.f / l0, inv1 = 1.f / l1;
    #pragma unroll
    for (int j = 0; j < 8; j++) {
        int col = h * HDq + j * 8 + 2 * qc;
        size_t o0 = ((size_t)(b * Sq + row0)) * Dq + col;
        size_t o1 = ((size_t)(b * Sq + row1)) * Dq + col;
        *(__half2*)&O[o0] = __floats2half2_rn(o[j][0] * inv0, o[j][1] * inv0);
        *(__half2*)&O[o1] = __floats2half2_rn(o[j][2] * inv1, o[j][3] * inv1);
    }
}

// ---------------- launch --------------------------------------------------
extern "C" void kernel_launch(void* const* d_in, const int* in_sizes, int n_in,
                              void* d_out, int out_size)
{
    const float* x          = (const float*)d_in[0];
    const float* gamma_attn = (const float*)d_in[2];
    const float* w_qkv      = (const float*)d_in[3];
    const float* b_qkv      = (const float*)d_in[4];
    const float* w_out      = (const float*)d_in[5];
    const float* b_out      = (const float*)d_in[6];
    const float* gamma_ffn  = (const float*)d_in[7];
    const float* w1         = (const float*)d_in[8];
    const float* b1         = (const float*)d_in[9];
    const float* w2         = (const float*)d_in[10];
    const float* b2         = (const float*)d_in[11];
    const float* w3         = (const float*)d_in[12];
    const float* b3         = (const float*)d_in[13];
    float* out = (float*)d_out;

    float  *xn, *h, *hn, *ff2;
    __half *xnh, *qkvh, *qh, *kh, *vh, *attnh, *hnh, *ff1h;
    __half *wqkvh, *wouth, *w1h, *w2h, *w3ph;
    cudaGetSymbolAddress((void**)&xn,    g_xn);
    cudaGetSymbolAddress((void**)&xnh,   g_xnh);
    cudaGetSymbolAddress((void**)&qkvh,  g_qkvh);
    cudaGetSymbolAddress((void**)&qh,    g_qh);
    cudaGetSymbolAddress((void**)&kh,    g_kh);
    cudaGetSymbolAddress((void**)&vh,    g_vh);
    cudaGetSymbolAddress((void**)&attnh, g_attnh);
    cudaGetSymbolAddress((void**)&h,     g_h);
    cudaGetSymbolAddress((void**)&hn,    g_hn);
    cudaGetSymbolAddress((void**)&hnh,   g_hnh);
    cudaGetSymbolAddress((void**)&ff1h,  g_ff1h);
    cudaGetSymbolAddress((void**)&ff2,   g_ff2);
    cudaGetSymbolAddress((void**)&wqkvh, g_wqkvh);
    cudaGetSymbolAddress((void**)&wouth, g_wouth);
    cudaGetSymbolAddress((void**)&w1h,   g_w1h);
    cudaGetSymbolAddress((void**)&w2h,   g_w2h);
    cudaGetSymbolAddress((void**)&w3ph,  g_w3ph);

    cudaFuncSetAttribute(gemm_h<0,1>, cudaFuncAttributeMaxDynamicSharedMemorySize, SMEM_H);
    cudaFuncSetAttribute(gemm_h<1,0>, cudaFuncAttributeMaxDynamicSharedMemorySize, SMEM_H);
    cudaFuncSetAttribute(gemm_h<2,1>, cudaFuncAttributeMaxDynamicSharedMemorySize, SMEM_H);
    cudaFuncSetAttribute(gemm_h<3,0>, cudaFuncAttributeMaxDynamicSharedMemorySize, SMEM_H);
    cudaFuncSetAttribute(flash_attn_h, cudaFuncAttributeMaxDynamicSharedMemorySize, FA_SMEMH);

    // 0) convert weights to fp16 once; zero ff1 pads
    {
        int n;
        n = 3*Dq*Dq/4;  conv_half<<<296, 256>>>(w_qkv, wqkvh, n);
        n = Dq*Dq/4;    conv_half<<<296, 256>>>(w_out, wouth, n);
        n = DIq*Dq/4;   conv_half<<<296, 256>>>(w1, w1h, n);
        n = DIq*Dq/4;   conv_half<<<296, 256>>>(w2, w2h, n);
        n = Dq*DIpad;   conv_half_pad<<<(n+255)/256, 256>>>(w3, w3ph, Dq, DIq, DIpad);
        n = BSq*(DIpad-DIq); zero_pad_ff1<<<(n+255)/256, 256>>>(ff1h);
    }

    // 1) xn = rmsnorm(x, gamma_attn)  (fp32 + fp16)
    rmsnorm_k<<<BSq, 256>>>(x, gamma_attn, xn, xnh);

    // 2) qkvh = xnh @ wqkvh^T + b_qkv          [4096, 3072] fp16 out
    gemm_h<0,1><<<dim3(3*Dq/128, BSq/128), 256, SMEM_H>>>(
        xnh, wqkvh, b_qkv, nullptr, nullptr, qkvh, BSq, 3*Dq, Dq, Dq, 3*Dq);

    // 3) rope + split -> fp16 q,k,v
    rope_split<<<(Bq*Sq*Hq*32)/256, 256>>>(qkvh, qh, kh, vh);

    // 4) flash attention -> attnh (fp16)
    flash_attn_h<<<dim3(Sq/FA_BM, Hq, Bq), 256, FA_SMEMH>>>(qh, kh, vh, attnh);

    // 5) h = xn + attnh @ wouth^T + b_out      (fp32 out)
    gemm_h<3,0><<<dim3(Dq/128, BSq/128), 256, SMEM_H>>>(
        attnh, wouth, b_out, xn, h, nullptr, BSq, Dq, Dq, Dq, Dq);

    // 6) hn = rmsnorm(h, gamma_ffn)  (fp32 + fp16)
    rmsnorm_k<<<BSq, 256>>>(h, gamma_ffn, hn, hnh);

    // 7) gate = silu(hnh @ w2h^T + b2)         (fp32 out, stride DIpad)
    gemm_h<1,0><<<dim3((DIq+127)/128, BSq/128), 256, SMEM_H>>>(
        hnh, w2h, b2, nullptr, ff2, nullptr, BSq, DIq, Dq, Dq, DIpad);

    // 8) ff1 = (hnh @ w1h^T + b1) * gate       (fp16 out)
    gemm_h<2,1><<<dim3((DIq+127)/128, BSq/128), 256, SMEM_H>>>(
        hnh, w1h, b1, ff2, nullptr, ff1h, BSq, DIq, Dq, Dq, DIpad);

    // 9) out = hn + ff1h @ w3ph^T + b3         (K padded to 2736, pads zero)
    gemm_h<3,0><<<dim3(Dq/128, BSq/128), 256, SMEM_H>>>(
        ff1h, w3ph, b3, hn, out, nullptr, BSq, Dq, DIpad, DIpad, Dq);
}

// round 14
// speedup vs baseline: 8.7462x; 1.0098x over previous
#include <cuda_runtime.h>
#include <cuda_fp16.h>
#include <math.h>
#include <stdint.h>

// Problem constants
#define Bq  2
#define Sq  2048
#define Dq  1024
#define Hq  16
#define HDq 64
#define DIq 2730            // int(8/3 * 1024)
#define DIpad 2736          // padded row stride
#define BSq (Bq*Sq)         // 4096 rows

// ---------------- scratch (device globals; no allocation allowed) -----------
__device__ float  g_xn  [(size_t)BSq*Dq];
__device__ __half g_xnh [(size_t)BSq*Dq];
__device__ __half g_qh  [(size_t)Bq*Hq*Sq*HDq];
__device__ __half g_kh  [(size_t)Bq*Hq*Sq*HDq];
__device__ __half g_vh  [(size_t)Bq*Hq*Sq*HDq];
__device__ __half g_attnh[(size_t)BSq*Dq];
__device__ float  g_h   [(size_t)BSq*Dq];
__device__ float  g_hn  [(size_t)BSq*Dq];
__device__ __half g_hnh [(size_t)BSq*Dq];
__device__ __half g_ff1h[(size_t)BSq*DIpad];
__device__ __half g_ff2h[(size_t)BSq*DIpad];   // gate, fp16
// fp16 weight copies
__device__ __half g_wqkvh[(size_t)3*Dq*Dq];
__device__ __half g_wouth[(size_t)Dq*Dq];
__device__ __half g_w1h  [(size_t)DIq*Dq];
__device__ __half g_w2h  [(size_t)DIq*Dq];
__device__ __half g_w3ph [(size_t)Dq*DIpad];   // padded [1024][2736], zeros in pad

// ---------------- conversion kernels (4x ILP, grid-stride) ------------------
__global__ void __launch_bounds__(256) conv_half(const float* __restrict__ src,
                                                 __half* __restrict__ dst, int n4)
{
    int i0 = (blockIdx.x * 256 + threadIdx.x) * 4;
    int stride = gridDim.x * 256 * 4;
    for (int i = i0; i < n4 + 3; i += stride) {
        float4 v[4];
        #pragma unroll
        for (int u = 0; u < 4; u++)
            if (i + u < n4) v[u] = ((const float4*)src)[i + u];
        #pragma unroll
        for (int u = 0; u < 4; u++)
            if (i + u < n4) {
                ((__half2*)dst)[(i+u)*2]   = __floats2half2_rn(v[u].x, v[u].y);
                ((__half2*)dst)[(i+u)*2+1] = __floats2half2_rn(v[u].z, v[u].w);
            }
    }
}

__global__ void __launch_bounds__(256) conv_half_pad(const float* __restrict__ src,
                                                     __half* __restrict__ dst,
                                                     int rows, int cin, int cpad)
{
    int i = blockIdx.x * 256 + threadIdx.x;
    if (i < rows * cpad) {
        int r = i / cpad, c = i - r * cpad;
        dst[i] = (c < cin) ? __float2half_rn(src[(size_t)r * cin + c]) : __half(0.f);
    }
}

__global__ void __launch_bounds__(256) zero_pad_ff1(__half* __restrict__ ff1)
{
    int i = blockIdx.x * 256 + threadIdx.x;
    if (i < BSq * (DIpad - DIq)) {
        int r = i / (DIpad - DIq), c = DIq + i % (DIpad - DIq);
        ff1[(size_t)r * DIpad + c] = __half(0.f);
    }
}

// ---------------- RMSNorm: dual output (fp32 + fp16) ------------------------
__global__ void __launch_bounds__(256) rmsnorm_k(const float* __restrict__ x,
                                                 const float* __restrict__ gamma,
                                                 float* __restrict__ out,
                                                 __half* __restrict__ out_h)
{
    const size_t row = blockIdx.x;
    const float* xr = x + row * Dq;
    float ss = 0.f;
    for (int c = threadIdx.x; c < Dq; c += 256) { float v = xr[c]; ss += v * v; }
    #pragma unroll
    for (int d = 16; d > 0; d >>= 1) ss += __shfl_xor_sync(0xffffffffu, ss, d);
    __shared__ float red[8];
    __shared__ float s_inv;
    if ((threadIdx.x & 31) == 0) red[threadIdx.x >> 5] = ss;
    __syncthreads();
    if (threadIdx.x == 0) {
        float t = 0.f;
        #pragma unroll
        for (int i = 0; i < 8; i++) t += red[i];
        s_inv = rsqrtf(t / (float)Dq + 1e-5f);
    }
    __syncthreads();
    const float inv = s_inv;
    for (int c = threadIdx.x; c < Dq; c += 256) {
        float v = xr[c] * inv * gamma[c];
        out[row * Dq + c]   = v;
        out_h[row * Dq + c] = __float2half_rn(v);
    }
}

// ---------------- cp.async / ldmatrix helpers --------------------------------
__device__ __forceinline__ void cp16(uint32_t dst, const void* src, int sz) {
    asm volatile("cp.async.cg.shared.global [%0], [%1], 16, %2;"
                 :: "r"(dst), "l"(src), "r"(sz));
}
__device__ __forceinline__ void cp_commit() { asm volatile("cp.async.commit_group;"); }
__device__ __forceinline__ void cp_wait0()  { asm volatile("cp.async.wait_group 0;" ::: "memory"); }

#define LDSM4(r0, r1, r2, r3, a) \
    asm volatile("ldmatrix.sync.aligned.m8n8.x4.shared.b16 {%0,%1,%2,%3}, [%4];" \
                 : "=r"(r0), "=r"(r1), "=r"(r2), "=r"(r3) : "r"(a))

#define MMA_H(d0,d1,d2,d3, a0,a1,a2,a3, b0,b1) \
    asm volatile("mma.sync.aligned.m16n8k16.row.col.f32.f16.f16.f32 " \
                 "{%0,%1,%2,%3}, {%4,%5,%6,%7}, {%8,%9}, {%0,%1,%2,%3};" \
                 : "+f"(d0), "+f"(d1), "+f"(d2), "+f"(d3) \
                 : "r"(a0), "r"(a1), "r"(a2), "r"(a3), "r"(b0), "r"(b1))

// ---------------- FP16 GEMM (mma.m16n8k16 + ldmatrix), 2 CTA/SM -------------
// C[M,N] = A[M,K] @ W[N,K]^T ; A,W fp16; acc fp32.
// MODE 1: silu(+bias) -> Ch (fp16)
// MODE 2: (+bias) * extrah -> Ch (fp16)
// MODE 3: (+bias) + extraf -> C (fp32)
// MODE 4: qkv fused rope: split cols into q/k/v, rope q&k, write [b,h,s,64] fp16
#define HBK 64                      // halves per k-chunk
#define HPAD 72                     // halves stride (144 B -> conflict-free)
#define HSTG (128 * HPAD)           // halves per operand stage
#define SMEM_H (4 * HSTG * 2)       // 2 bufs x 2 ops x bytes = 73728

template <int MODE>
__global__ void __launch_bounds__(256, 2) gemm_h(const __half* __restrict__ A,
                                                 const __half* __restrict__ W,
                                                 const float* __restrict__ bias,
                                                 const float* __restrict__ extraf,
                                                 const __half* __restrict__ extrah,
                                                 float* __restrict__ C,
                                                 __half* __restrict__ Ch,
                                                 __half* __restrict__ oq,
                                                 __half* __restrict__ ok,
                                                 __half* __restrict__ ov,
                                                 int M, int N, int K,
                                                 int lda, int ldc)
{
    extern __shared__ __half hs[];
    const uint32_t sAll = (uint32_t)__cvta_generic_to_shared(hs);
    const uint32_t sA = sAll;                    // [2][128][72]
    const uint32_t sB = sAll + 2 * HSTG * 2;     // [2][128][72]

    const int tid  = threadIdx.x;
    const int lane = tid & 31;
    const int w    = tid >> 5;
    const int wm   = (w >> 2) * 64;
    const int wn   = (w & 3) * 32;
    const int m0   = blockIdx.y * 128;
    const int n0   = blockIdx.x * 128;
    const int qr   = lane >> 2;
    const int qc   = lane & 3;

    const int laneRowA = lane & 15;
    const int laneKA   = (lane >> 4) << 3;
    const int laneRowB = (lane & 7) + ((lane >> 4) << 3);
    const int laneKB   = ((lane >> 3) & 1) << 3;

    float acc[4][4][4];
    #pragma unroll
    for (int i = 0; i < 4; i++)
        #pragma unroll
        for (int j = 0; j < 4; j++)
            #pragma unroll
            for (int t = 0; t < 4; t++) acc[i][j][t] = 0.f;

    const int kt = (K + HBK - 1) / HBK;

    auto issue_stage = [&](int t, int buf) {
        const int k0 = t * HBK;
        const uint32_t aOff = sA + buf * HSTG * 2;
        const uint32_t bOff = sB + buf * HSTG * 2;
        #pragma unroll
        for (int i = 0; i < 4; i++) {             // 1024 16B-granules / operand
            int idx = tid + i * 256;
            int row = idx >> 3;                   // 0..127
            int g   = idx & 7;                    // 8 granules of 8 halves
            int gk  = k0 + g * 8;
            int sz  = (gk < K) ? 16 : 0;
            int cs  = sz ? gk : 0;
            cp16(aOff + (row * HPAD + g * 8) * 2,
                 &A[(size_t)(m0 + row) * lda + cs], sz);
            int gn = n0 + row;
            int szb = (gn < N) ? sz : 0;
            cp16(bOff + (row * HPAD + g * 8) * 2,
                 &W[(size_t)((gn < N) ? gn : 0) * K + cs], szb);
        }
        cp_commit();
    };

    auto compute = [&](int buf) {
        const uint32_t aOff = sA + buf * HSTG * 2;
        const uint32_t bOff = sB + buf * HSTG * 2;
        #pragma unroll
        for (int kk = 0; kk < 4; kk++) {
            const int kb = kk * 16;
            uint32_t af[4][4], bf[4][2];
            #pragma unroll
            for (int mt = 0; mt < 4; mt++) {
                uint32_t a = aOff + (((wm + mt * 16 + laneRowA) * HPAD) + kb + laneKA) * 2;
                LDSM4(af[mt][0], af[mt][1], af[mt][2], af[mt][3], a);
            }
            #pragma unroll
            for (int nt = 0; nt < 4; nt += 2) {
                uint32_t a = bOff + (((wn + nt * 8 + laneRowB) * HPAD) + kb + laneKB) * 2;
                LDSM4(bf[nt][0], bf[nt][1], bf[nt+1][0], bf[nt+1][1], a);
            }
            #pragma unroll
            for (int mt = 0; mt < 4; mt++)
                #pragma unroll
                for (int nt = 0; nt < 4; nt++)
                    MMA_H(acc[mt][nt][0], acc[mt][nt][1], acc[mt][nt][2], acc[mt][nt][3],
                          af[mt][0], af[mt][1], af[mt][2], af[mt][3],
                          bf[nt][0], bf[nt][1]);
        }
    };

    issue_stage(0, 0);
    for (int t = 0; t < kt; t++) {
        cp_wait0();
        __syncthreads();
        if (t + 1 < kt) issue_stage(t + 1, (t + 1) & 1);
        compute(t & 1);
    }

    // Epilogue
    #pragma unroll
    for (int mt = 0; mt < 4; mt++) {
        int r0 = m0 + wm + mt * 16 + qr;
        int r1 = r0 + 8;
        #pragma unroll
        for (int nt = 0; nt < 4; nt++) {
            int col = n0 + wn + nt * 8 + qc * 2;
            if (col < N) {
                float bv0 = bias[col], bv1 = bias[col + 1];
                float v00 = acc[mt][nt][0] + bv0;
                float v01 = acc[mt][nt][1] + bv1;
                float v10 = acc[mt][nt][2] + bv0;
                float v11 = acc[mt][nt][3] + bv1;
                if (MODE == 1) {
                    v00 = v00 / (1.f + expf(-v00));
                    v01 = v01 / (1.f + expf(-v01));
                    v10 = v10 / (1.f + expf(-v10));
                    v11 = v11 / (1.f + expf(-v11));
                    *(__half2*)&Ch[(size_t)r0 * ldc + col] = __floats2half2_rn(v00, v01);
                    *(__half2*)&Ch[(size_t)r1 * ldc + col] = __floats2half2_rn(v10, v11);
                }
                if (MODE == 2) {
                    float2 e0 = __half22float2(*(const __half2*)&extrah[(size_t)r0 * ldc + col]);
                    float2 e1 = __half22float2(*(const __half2*)&extrah[(size_t)r1 * ldc + col]);
                    v00 *= e0.x; v01 *= e0.y; v10 *= e1.x; v11 *= e1.y;
                    *(__half2*)&Ch[(size_t)r0 * ldc + col] = __floats2half2_rn(v00, v01);
                    *(__half2*)&Ch[(size_t)r1 * ldc + col] = __floats2half2_rn(v10, v11);
                }
                if (MODE == 3) {
                    float2 e0 = *(const float2*)&extraf[(size_t)r0 * ldc + col];
                    float2 e1 = *(const float2*)&extraf[(size_t)r1 * ldc + col];
                    v00 += e0.x; v01 += e0.y; v10 += e1.x; v11 += e1.y;
                    *(float2*)&C[(size_t)r0 * ldc + col] = make_float2(v00, v01);
                    *(float2*)&C[(size_t)r1 * ldc + col] = make_float2(v10, v11);
                }
                if (MODE == 4) {
                    // col in [0,3072): part 0=q, 1=k, 2=v; rows r0/r1 = tokens
                    int part = col >> 10;
                    int cc   = col & 1023;
                    int hh   = cc >> 6;
                    int hd   = cc & 63;          // even
                    int b0 = r0 >> 11, s0 = r0 & 2047;
                    int b1 = r1 >> 11, s1 = r1 & 2047;
                    size_t orow0 = ((size_t)(b0 * Hq + hh) * Sq + s0) * HDq;
                    size_t orow1 = ((size_t)(b1 * Hq + hh) * Sq + s1) * HDq;
                    if (part == 2) {
                        *(__half2*)&ov[orow0 + hd] = __floats2half2_rn(v00, v01);
                        *(__half2*)&ov[orow1 + hd] = __floats2half2_rn(v10, v11);
                    } else {
                        __half* dst = (part == 0) ? oq : ok;
                        int i = hd >> 1;
                        float theta = powf(10000.f, -(float)hd / 64.f);
                        float sn0, cs0, sn1, cs1;
                        sincosf((float)s0 * theta, &sn0, &cs0);
                        sincosf((float)s1 * theta, &sn1, &cs1);
                        dst[orow0 + i]      = __float2half_rn(v00 * cs0 - v01 * sn0);
                        dst[orow0 + 32 + i] = __float2half_rn(v00 * sn0 + v01 * cs0);
                        dst[orow1 + i]      = __float2half_rn(v10 * cs1 - v11 * sn1);
                        dst[orow1 + 32 + i] = __float2half_rn(v10 * sn1 + v11 * cs1);
                    }
                }
            }
        }
    }
}

// ---------------- FP16 tensor-core causal flash attention (ldmatrix) --------
#define FA_BM 128
#define FA_BN 64
#define FPH 72
#define FA_SMEMH ((FA_BM*FPH + FA_BN*FPH + FA_BN*FPH + FA_BM*FPH) * 2)

__global__ void __launch_bounds__(256, 2) flash_attn_h(const __half* __restrict__ Q,
                                                       const __half* __restrict__ K,
                                                       const __half* __restrict__ V,
                                                       __half* __restrict__ O)
{
    extern __shared__ __half fh[];
    __half* Qs = fh;                      // [128][72]
    __half* Ks = Qs + FA_BM * FPH;        // [64][72]
    __half* Vt = Ks + FA_BN * FPH;        // [hd 64][key 72]
    __half* Ps = Vt + FA_BN * FPH;        // [128][72]
    const uint32_t sQs = (uint32_t)__cvta_generic_to_shared(Qs);
    const uint32_t sKs = (uint32_t)__cvta_generic_to_shared(Ks);
    const uint32_t sVt = (uint32_t)__cvta_generic_to_shared(Vt);
    const uint32_t sPs = (uint32_t)__cvta_generic_to_shared(Ps);

    const int qt = gridDim.x - 1 - blockIdx.x;
    const int h = blockIdx.y, b = blockIdx.z;
    const int qm0 = qt * FA_BM;
    const size_t base = ((size_t)(b * Hq + h)) * Sq * HDq;
    const __half* Qb = Q + base;
    const __half* Kb = K + base;
    const __half* Vb = V + base;

    const int tid  = threadIdx.x;
    const int lane = tid & 31;
    const int w    = tid >> 5;
    const int qr   = lane >> 2;
    const int qc   = lane & 3;
    const int wrow = w * 16;

    const int laneRowA = lane & 15;
    const int laneKA   = (lane >> 4) << 3;
    const int laneRowB = (lane & 7) + ((lane >> 4) << 3);
    const int laneKB   = ((lane >> 3) & 1) << 3;

    for (int i = tid; i < FA_BM * 32; i += 256) {   // half2 granules
        int r = i >> 5, c2 = i & 31;
        __half2 v = ((const __half2*)Qb)[(size_t)(qm0 + r) * 32 + c2];
        *(__half2*)&Qs[r * FPH + c2 * 2] = v;
    }

    float o[8][4];
    #pragma unroll
    for (int j = 0; j < 8; j++)
        #pragma unroll
        for (int t = 0; t < 4; t++) o[j][t] = 0.f;
    float m0 = -1e30f, m1 = -1e30f, l0 = 0.f, l1 = 0.f;

    const int row0 = qm0 + wrow + qr;
    const int row1 = row0 + 8;
    const int nkt = (qm0 + FA_BM) / FA_BN;

    for (int kt = 0; kt < nkt; kt++) {
        const int kn0 = kt * FA_BN;
        __syncthreads();
        for (int i = tid; i < FA_BN * 32; i += 256) {
            int r = i >> 5, c2 = i & 31;
            __half2 kv = ((const __half2*)Kb)[(size_t)(kn0 + r) * 32 + c2];
            *(__half2*)&Ks[r * FPH + c2 * 2] = kv;
            __half2 vv = ((const __half2*)Vb)[(size_t)(kn0 + r) * 32 + c2];
            Vt[(c2 * 2)     * FPH + r] = __low2half(vv);
            Vt[(c2 * 2 + 1) * FPH + r] = __high2half(vv);
        }
        __syncthreads();

        const bool active = (kn0 <= qm0 + wrow + 15);
        if (active) {
            // ---- S = Q @ K^T ----
            float s[8][4];
            #pragma unroll
            for (int j = 0; j < 8; j++)
                #pragma unroll
                for (int t = 0; t < 4; t++) s[j][t] = 0.f;

            #pragma unroll
            for (int kk = 0; kk < 4; kk++) {
                const int kb = kk * 16;
                uint32_t a0, a1, a2, a3;
                LDSM4(a0, a1, a2, a3,
                      sQs + (((wrow + laneRowA) * FPH) + kb + laneKA) * 2);
                #pragma unroll
                for (int j = 0; j < 8; j += 2) {
                    uint32_t b0, b1, b2, b3;
                    LDSM4(b0, b1, b2, b3,
                          sKs + (((j * 8 + laneRowB) * FPH) + kb + laneKB) * 2);
                    MMA_H(s[j][0],   s[j][1],   s[j][2],   s[j][3],   a0,a1,a2,a3, b0,b1);
                    MMA_H(s[j+1][0], s[j+1][1], s[j+1][2], s[j+1][3], a0,a1,a2,a3, b2,b3);
                }
            }

            // ---- causal mask + online softmax ----
            float rmax0 = -1e30f, rmax1 = -1e30f;
            #pragma unroll
            for (int j = 0; j < 8; j++) {
                int c0 = kn0 + j * 8 + 2 * qc, c1 = c0 + 1;
                s[j][0] = (c0 <= row0) ? s[j][0] * 0.125f : -1e30f;
                s[j][1] = (c1 <= row0) ? s[j][1] * 0.125f : -1e30f;
                s[j][2] = (c0 <= row1) ? s[j][2] * 0.125f : -1e30f;
                s[j][3] = (c1 <= row1) ? s[j][3] * 0.125f : -1e30f;
                rmax0 = fmaxf(rmax0, fmaxf(s[j][0], s[j][1]));
                rmax1 = fmaxf(rmax1, fmaxf(s[j][2], s[j][3]));
            }
            rmax0 = fmaxf(rmax0, __shfl_xor_sync(0xffffffffu, rmax0, 1));
            rmax0 = fmaxf(rmax0, __shfl_xor_sync(0xffffffffu, rmax0, 2));
            rmax1 = fmaxf(rmax1, __shfl_xor_sync(0xffffffffu, rmax1, 1));
            rmax1 = fmaxf(rmax1, __shfl_xor_sync(0xffffffffu, rmax1, 2));

            float mn0 = fmaxf(m0, rmax0), mn1 = fmaxf(m1, rmax1);
            float a0 = __expf(m0 - mn0),  a1 = __expf(m1 - mn1);
            float rs0 = 0.f, rs1 = 0.f;
            __half* pr0 = Ps + (wrow + qr) * FPH;
            __half* pr1 = pr0 + 8 * FPH;
            #pragma unroll
            for (int j = 0; j < 8; j++) {
                __half2 h0 = __floats2half2_rn(__expf(s[j][0] - mn0),
                                               __expf(s[j][1] - mn0));
                __half2 h1 = __floats2half2_rn(__expf(s[j][2] - mn1),
                                               __expf(s[j][3] - mn1));
                *(__half2*)&pr0[j * 8 + 2 * qc] = h0;
                *(__half2*)&pr1[j * 8 + 2 * qc] = h1;
                float2 f0 = __half22float2(h0), f1 = __half22float2(h1);
                rs0 += f0.x + f0.y;
                rs1 += f1.x + f1.y;
            }
            rs0 += __shfl_xor_sync(0xffffffffu, rs0, 1);
            rs0 += __shfl_xor_sync(0xffffffffu, rs0, 2);
            rs1 += __shfl_xor_sync(0xffffffffu, rs1, 1);
            rs1 += __shfl_xor_sync(0xffffffffu, rs1, 2);

            l0 = l0 * a0 + rs0; m0 = mn0;
            l1 = l1 * a1 + rs1; m1 = mn1;
            #pragma unroll
            for (int j = 0; j < 8; j++) {
                o[j][0] *= a0; o[j][1] *= a0;
                o[j][2] *= a1; o[j][3] *= a1;
            }
            __syncwarp();

            // ---- O += P @ V ----
            #pragma unroll
            for (int kk = 0; kk < 4; kk++) {
                const int kb = kk * 16;
                uint32_t a0f, a1f, a2f, a3f;
                LDSM4(a0f, a1f, a2f, a3f,
                      sPs + (((wrow + laneRowA) * FPH) + kb + laneKA) * 2);
                #pragma unroll
                for (int j = 0; j < 8; j += 2) {
                    uint32_t b0, b1, b2, b3;
                    LDSM4(b0, b1, b2, b3,
                          sVt + (((j * 8 + laneRowB) * FPH) + kb + laneKB) * 2);
                    MMA_H(o[j][0],   o[j][1],   o[j][2],   o[j][3],   a0f,a1f,a2f,a3f, b0,b1);
                    MMA_H(o[j+1][0], o[j+1][1], o[j+1][2], o[j+1][3], a0f,a1f,a2f,a3f, b2,b3);
                }
            }
        }
    }

    // ---- normalize + write O (fp16) as [b, s, h*64 + c] ----
    float inv0 = 1.f / l0, inv1 = 1.f / l1;
    #pragma unroll
    for (int j = 0; j < 8; j++) {
        int col = h * HDq + j * 8 + 2 * qc;
        size_t o0 = ((size_t)(b * Sq + row0)) * Dq + col;
        size_t o1 = ((size_t)(b * Sq + row1)) * Dq + col;
        *(__half2*)&O[o0] = __floats2half2_rn(o[j][0] * inv0, o[j][1] * inv0);
        *(__half2*)&O[o1] = __floats2half2_rn(o[j][2] * inv1, o[j][3] * inv1);
    }
}

// ---------------- launch --------------------------------------------------
extern "C" void kernel_launch(void* const* d_in, const int* in_sizes, int n_in,
                              void* d_out, int out_size)
{
    const float* x          = (const float*)d_in[0];
    const float* gamma_attn = (const float*)d_in[2];
    const float* w_qkv      = (const float*)d_in[3];
    const float* b_qkv      = (const float*)d_in[4];
    const float* w_out      = (const float*)d_in[5];
    const float* b_out      = (const float*)d_in[6];
    const float* gamma_ffn  = (const float*)d_in[7];
    const float* w1         = (const float*)d_in[8];
    const float* b1         = (const float*)d_in[9];
    const float* w2         = (const float*)d_in[10];
    const float* b2         = (const float*)d_in[11];
    const float* w3         = (const float*)d_in[12];
    const float* b3         = (const float*)d_in[13];
    float* out = (float*)d_out;

    float  *xn, *h, *hn;
    __half *xnh, *qh, *kh, *vh, *attnh, *hnh, *ff1h, *ff2h;
    __half *wqkvh, *wouth, *w1h, *w2h, *w3ph;
    cudaGetSymbolAddress((void**)&xn,    g_xn);
    cudaGetSymbolAddress((void**)&xnh,   g_xnh);
    cudaGetSymbolAddress((void**)&qh,    g_qh);
    cudaGetSymbolAddress((void**)&kh,    g_kh);
    cudaGetSymbolAddress((void**)&vh,    g_vh);
    cudaGetSymbolAddress((void**)&attnh, g_attnh);
    cudaGetSymbolAddress((void**)&h,     g_h);
    cudaGetSymbolAddress((void**)&hn,    g_hn);
    cudaGetSymbolAddress((void**)&hnh,   g_hnh);
    cudaGetSymbolAddress((void**)&ff1h,  g_ff1h);
    cudaGetSymbolAddress((void**)&ff2h,  g_ff2h);
    cudaGetSymbolAddress((void**)&wqkvh, g_wqkvh);
    cudaGetSymbolAddress((void**)&wouth, g_wouth);
    cudaGetSymbolAddress((void**)&w1h,   g_w1h);
    cudaGetSymbolAddress((void**)&w2h,   g_w2h);
    cudaGetSymbolAddress((void**)&w3ph,  g_w3ph);

    cudaFuncSetAttribute(gemm_h<1>, cudaFuncAttributeMaxDynamicSharedMemorySize, SMEM_H);
    cudaFuncSetAttribute(gemm_h<2>, cudaFuncAttributeMaxDynamicSharedMemorySize, SMEM_H);
    cudaFuncSetAttribute(gemm_h<3>, cudaFuncAttributeMaxDynamicSharedMemorySize, SMEM_H);
    cudaFuncSetAttribute(gemm_h<4>, cudaFuncAttributeMaxDynamicSharedMemorySize, SMEM_H);
    cudaFuncSetAttribute(flash_attn_h, cudaFuncAttributeMaxDynamicSharedMemorySize, FA_SMEMH);

    // 0) convert weights to fp16 once; zero ff1 pads
    {
        int n, g;
        n = 3*Dq*Dq/4;  g = (n/4 + 255)/256;  conv_half<<<g, 256>>>(w_qkv, wqkvh, n);
        n = Dq*Dq/4;    g = (n/4 + 255)/256;  conv_half<<<g, 256>>>(w_out, wouth, n);
        n = DIq*Dq/4;   g = (n/4 + 255)/256;  conv_half<<<g, 256>>>(w1, w1h, n);
        n = DIq*Dq/4;   g = (n/4 + 255)/256;  conv_half<<<g, 256>>>(w2, w2h, n);
        n = Dq*DIpad;   conv_half_pad<<<(n+255)/256, 256>>>(w3, w3ph, Dq, DIq, DIpad);
        n = BSq*(DIpad-DIq); zero_pad_ff1<<<(n+255)/256, 256>>>(ff1h);
    }

    // 1) xn = rmsnorm(x, gamma_attn)  (fp32 + fp16)
    rmsnorm_k<<<BSq, 256>>>(x, gamma_attn, xn, xnh);

    // 2) q,k,v = rope(split(xnh @ wqkvh^T + b_qkv))   [fused epilogue]
    gemm_h<4><<<dim3(3*Dq/128, BSq/128), 256, SMEM_H>>>(
        xnh, wqkvh, b_qkv, nullptr, nullptr, nullptr, nullptr,
        qh, kh, vh, BSq, 3*Dq, Dq, Dq, 0);

    // 3) flash attention -> attnh (fp16)
    flash_attn_h<<<dim3(Sq/FA_BM, Hq, Bq), 256, FA_SMEMH>>>(qh, kh, vh, attnh);

    // 4) h = xn + attnh @ wouth^T + b_out      (fp32 out)
    gemm_h<3><<<dim3(Dq/128, BSq/128), 256, SMEM_H>>>(
        attnh, wouth, b_out, xn, nullptr, h, nullptr,
        nullptr, nullptr, nullptr, BSq, Dq, Dq, Dq, Dq);

    // 5) hn = rmsnorm(h, gamma_ffn)  (fp32 + fp16)
    rmsnorm_k<<<BSq, 256>>>(h, gamma_ffn, hn, hnh);

    // 6) gate = silu(hnh @ w2h^T + b2)         (fp16 out, stride DIpad)
    gemm_h<1><<<dim3((DIq+127)/128, BSq/128), 256, SMEM_H>>>(
        hnh, w2h, b2, nullptr, nullptr, nullptr, ff2h,
        nullptr, nullptr, nullptr, BSq, DIq, Dq, Dq, DIpad);

    // 7) ff1 = (hnh @ w1h^T + b1) * gate       (fp16 out)
    gemm_h<2><<<dim3((DIq+127)/128, BSq/128), 256, SMEM_H>>>(
        hnh, w1h, b1, nullptr, ff2h, nullptr, ff1h,
        nullptr, nullptr, nullptr, BSq, DIq, Dq, Dq, DIpad);

    // 8) out = hn + ff1h @ w3ph^T + b3         (K padded to 2736, pads zero)
    gemm_h<3><<<dim3(Dq/128, BSq/128), 256, SMEM_H>>>(
        ff1h, w3ph, b3, hn, nullptr, out, nullptr,
        nullptr, nullptr, nullptr, BSq, Dq, DIpad, DIpad, Dq);
}

// round 15
// speedup vs baseline: 8.8494x; 1.0118x over previous
#include <cuda_runtime.h>
#include <cuda_fp16.h>
#include <math.h>
#include <stdint.h>

// Problem constants
#define Bq  2
#define Sq  2048
#define Dq  1024
#define Hq  16
#define HDq 64
#define DIq 2730            // int(8/3 * 1024)
#define DIpad 2736          // padded row stride
#define BSq (Bq*Sq)         // 4096 rows

// ---------------- scratch (device globals; no allocation allowed) -----------
__device__ float  g_xn  [(size_t)BSq*Dq];
__device__ __half g_xnh [(size_t)BSq*Dq];
__device__ __half g_qh  [(size_t)Bq*Hq*Sq*HDq];
__device__ __half g_kh  [(size_t)Bq*Hq*Sq*HDq];
__device__ __half g_vh  [(size_t)Bq*Hq*Sq*HDq];
__device__ __half g_attnh[(size_t)BSq*Dq];
__device__ float  g_h   [(size_t)BSq*Dq];
__device__ float  g_hn  [(size_t)BSq*Dq];
__device__ __half g_hnh [(size_t)BSq*Dq];
__device__ __half g_ff1h[(size_t)BSq*DIpad];
__device__ __half g_ff2h[(size_t)BSq*DIpad];   // gate, fp16
__device__ float2 g_rope[(size_t)Sq*32];       // (cos, sin) per (s, pair)
// fp16 weight copies
__device__ __half g_wqkvh[(size_t)3*Dq*Dq];
__device__ __half g_wouth[(size_t)Dq*Dq];
__device__ __half g_w1h  [(size_t)DIq*Dq];
__device__ __half g_w2h  [(size_t)DIq*Dq];
__device__ __half g_w3ph [(size_t)Dq*DIpad];   // padded [1024][2736], zeros in pad

// ---------------- rope LUT fill ----------------------------------------------
__global__ void __launch_bounds__(256) rope_lut_k(float2* __restrict__ lut)
{
    int idx = blockIdx.x * 256 + threadIdx.x;   // Sq*32 threads
    int i = idx & 31;
    int s = idx >> 5;
    float theta = powf(10000.f, -((float)(2 * i)) / 64.f);
    float sn, cs;
    sincosf((float)s * theta, &sn, &cs);
    lut[idx] = make_float2(cs, sn);
}

// ---------------- conversion kernels (4x ILP, grid-stride) ------------------
__global__ void __launch_bounds__(256) conv_half(const float* __restrict__ src,
                                                 __half* __restrict__ dst, int n4)
{
    int i0 = (blockIdx.x * 256 + threadIdx.x) * 4;
    int stride = gridDim.x * 256 * 4;
    for (int i = i0; i < n4 + 3; i += stride) {
        float4 v[4];
        #pragma unroll
        for (int u = 0; u < 4; u++)
            if (i + u < n4) v[u] = ((const float4*)src)[i + u];
        #pragma unroll
        for (int u = 0; u < 4; u++)
            if (i + u < n4) {
                ((__half2*)dst)[(i+u)*2]   = __floats2half2_rn(v[u].x, v[u].y);
                ((__half2*)dst)[(i+u)*2+1] = __floats2half2_rn(v[u].z, v[u].w);
            }
    }
}

__global__ void __launch_bounds__(256) conv_half_pad(const float* __restrict__ src,
                                                     __half* __restrict__ dst,
                                                     int rows, int cin, int cpad)
{
    int i = blockIdx.x * 256 + threadIdx.x;
    if (i < rows * cpad) {
        int r = i / cpad, c = i - r * cpad;
        dst[i] = (c < cin) ? __float2half_rn(src[(size_t)r * cin + c]) : __half(0.f);
    }
}

__global__ void __launch_bounds__(256) zero_pad_ff1(__half* __restrict__ ff1)
{
    int i = blockIdx.x * 256 + threadIdx.x;
    if (i < BSq * (DIpad - DIq)) {
        int r = i / (DIpad - DIq), c = DIq + i % (DIpad - DIq);
        ff1[(size_t)r * DIpad + c] = __half(0.f);
    }
}

// ---------------- RMSNorm: dual output (fp32 + fp16) ------------------------
__global__ void __launch_bounds__(256) rmsnorm_k(const float* __restrict__ x,
                                                 const float* __restrict__ gamma,
                                                 float* __restrict__ out,
                                                 __half* __restrict__ out_h)
{
    const size_t row = blockIdx.x;
    const float* xr = x + row * Dq;
    float ss = 0.f;
    for (int c = threadIdx.x; c < Dq; c += 256) { float v = xr[c]; ss += v * v; }
    #pragma unroll
    for (int d = 16; d > 0; d >>= 1) ss += __shfl_xor_sync(0xffffffffu, ss, d);
    __shared__ float red[8];
    __shared__ float s_inv;
    if ((threadIdx.x & 31) == 0) red[threadIdx.x >> 5] = ss;
    __syncthreads();
    if (threadIdx.x == 0) {
        float t = 0.f;
        #pragma unroll
        for (int i = 0; i < 8; i++) t += red[i];
        s_inv = rsqrtf(t / (float)Dq + 1e-5f);
    }
    __syncthreads();
    const float inv = s_inv;
    for (int c = threadIdx.x; c < Dq; c += 256) {
        float v = xr[c] * inv * gamma[c];
        out[row * Dq + c]   = v;
        out_h[row * Dq + c] = __float2half_rn(v);
    }
}

// ---------------- cp.async / ldmatrix helpers --------------------------------
__device__ __forceinline__ void cp16(uint32_t dst, const void* src, int sz) {
    asm volatile("cp.async.cg.shared.global [%0], [%1], 16, %2;"
                 :: "r"(dst), "l"(src), "r"(sz));
}
__device__ __forceinline__ void cp_commit() { asm volatile("cp.async.commit_group;"); }
__device__ __forceinline__ void cp_wait0()  { asm volatile("cp.async.wait_group 0;" ::: "memory"); }

#define LDSM4(r0, r1, r2, r3, a) \
    asm volatile("ldmatrix.sync.aligned.m8n8.x4.shared.b16 {%0,%1,%2,%3}, [%4];" \
                 : "=r"(r0), "=r"(r1), "=r"(r2), "=r"(r3) : "r"(a))

#define MMA_H(d0,d1,d2,d3, a0,a1,a2,a3, b0,b1) \
    asm volatile("mma.sync.aligned.m16n8k16.row.col.f32.f16.f16.f32 " \
                 "{%0,%1,%2,%3}, {%4,%5,%6,%7}, {%8,%9}, {%0,%1,%2,%3};" \
                 : "+f"(d0), "+f"(d1), "+f"(d2), "+f"(d3) \
                 : "r"(a0), "r"(a1), "r"(a2), "r"(a3), "r"(b0), "r"(b1))

// ---------------- FP16 GEMM (mma.m16n8k16 + ldmatrix), 2 CTA/SM -------------
// C[M,N] = A[M,K] @ W[N,K]^T ; A,W fp16; acc fp32.
// MODE 1: silu(+bias) -> Ch (fp16)
// MODE 2: (+bias) * extrah -> Ch (fp16)
// MODE 3: (+bias) + extraf -> C (fp32)
// MODE 4: qkv fused rope (LUT): split into q/k/v, rope q&k, write [b,h,s,64]
#define HBK 64                      // halves per k-chunk
#define HPAD 72                     // halves stride (144 B -> conflict-free)
#define HSTG (128 * HPAD)           // halves per operand stage
#define SMEM_H (4 * HSTG * 2)       // 2 bufs x 2 ops x bytes = 73728

template <int MODE>
__global__ void __launch_bounds__(256, 2) gemm_h(const __half* __restrict__ A,
                                                 const __half* __restrict__ W,
                                                 const float* __restrict__ bias,
                                                 const float* __restrict__ extraf,
                                                 const __half* __restrict__ extrah,
                                                 float* __restrict__ C,
                                                 __half* __restrict__ Ch,
                                                 __half* __restrict__ oq,
                                                 __half* __restrict__ ok,
                                                 __half* __restrict__ ov,
                                                 const float2* __restrict__ rope,
                                                 int M, int N, int K,
                                                 int lda, int ldc)
{
    extern __shared__ __half hs[];
    const uint32_t sAll = (uint32_t)__cvta_generic_to_shared(hs);
    const uint32_t sA = sAll;                    // [2][128][72]
    const uint32_t sB = sAll + 2 * HSTG * 2;     // [2][128][72]

    const int tid  = threadIdx.x;
    const int lane = tid & 31;
    const int w    = tid >> 5;
    const int wm   = (w >> 2) * 64;
    const int wn   = (w & 3) * 32;
    const int m0   = blockIdx.y * 128;
    const int n0   = blockIdx.x * 128;
    const int qr   = lane >> 2;
    const int qc   = lane & 3;

    const int laneRowA = lane & 15;
    const int laneKA   = (lane >> 4) << 3;
    const int laneRowB = (lane & 7) + ((lane >> 4) << 3);
    const int laneKB   = ((lane >> 3) & 1) << 3;

    float acc[4][4][4];
    #pragma unroll
    for (int i = 0; i < 4; i++)
        #pragma unroll
        for (int j = 0; j < 4; j++)
            #pragma unroll
            for (int t = 0; t < 4; t++) acc[i][j][t] = 0.f;

    const int kt = (K + HBK - 1) / HBK;

    auto issue_stage = [&](int t, int buf) {
        const int k0 = t * HBK;
        const uint32_t aOff = sA + buf * HSTG * 2;
        const uint32_t bOff = sB + buf * HSTG * 2;
        #pragma unroll
        for (int i = 0; i < 4; i++) {             // 1024 16B-granules / operand
            int idx = tid + i * 256;
            int row = idx >> 3;                   // 0..127
            int g   = idx & 7;                    // 8 granules of 8 halves
            int gk  = k0 + g * 8;
            int sz  = (gk < K) ? 16 : 0;
            int cs  = sz ? gk : 0;
            cp16(aOff + (row * HPAD + g * 8) * 2,
                 &A[(size_t)(m0 + row) * lda + cs], sz);
            int gn = n0 + row;
            int szb = (gn < N) ? sz : 0;
            cp16(bOff + (row * HPAD + g * 8) * 2,
                 &W[(size_t)((gn < N) ? gn : 0) * K + cs], szb);
        }
        cp_commit();
    };

    auto compute = [&](int buf) {
        const uint32_t aOff = sA + buf * HSTG * 2;
        const uint32_t bOff = sB + buf * HSTG * 2;
        #pragma unroll
        for (int kk = 0; kk < 4; kk++) {
            const int kb = kk * 16;
            uint32_t af[4][4], bf[4][2];
            #pragma unroll
            for (int mt = 0; mt < 4; mt++) {
                uint32_t a = aOff + (((wm + mt * 16 + laneRowA) * HPAD) + kb + laneKA) * 2;
                LDSM4(af[mt][0], af[mt][1], af[mt][2], af[mt][3], a);
            }
            #pragma unroll
            for (int nt = 0; nt < 4; nt += 2) {
                uint32_t a = bOff + (((wn + nt * 8 + laneRowB) * HPAD) + kb + laneKB) * 2;
                LDSM4(bf[nt][0], bf[nt][1], bf[nt+1][0], bf[nt+1][1], a);
            }
            #pragma unroll
            for (int mt = 0; mt < 4; mt++)
                #pragma unroll
                for (int nt = 0; nt < 4; nt++)
                    MMA_H(acc[mt][nt][0], acc[mt][nt][1], acc[mt][nt][2], acc[mt][nt][3],
                          af[mt][0], af[mt][1], af[mt][2], af[mt][3],
                          bf[nt][0], bf[nt][1]);
        }
    };

    issue_stage(0, 0);
    for (int t = 0; t < kt; t++) {
        cp_wait0();
        __syncthreads();
        if (t + 1 < kt) issue_stage(t + 1, (t + 1) & 1);
        compute(t & 1);
    }

    // Epilogue
    #pragma unroll
    for (int mt = 0; mt < 4; mt++) {
        int r0 = m0 + wm + mt * 16 + qr;
        int r1 = r0 + 8;
        #pragma unroll
        for (int nt = 0; nt < 4; nt++) {
            int col = n0 + wn + nt * 8 + qc * 2;
            if (col < N) {
                float bv0 = bias[col], bv1 = bias[col + 1];
                float v00 = acc[mt][nt][0] + bv0;
                float v01 = acc[mt][nt][1] + bv1;
                float v10 = acc[mt][nt][2] + bv0;
                float v11 = acc[mt][nt][3] + bv1;
                if (MODE == 1) {
                    v00 = v00 / (1.f + expf(-v00));
                    v01 = v01 / (1.f + expf(-v01));
                    v10 = v10 / (1.f + expf(-v10));
                    v11 = v11 / (1.f + expf(-v11));
                    *(__half2*)&Ch[(size_t)r0 * ldc + col] = __floats2half2_rn(v00, v01);
                    *(__half2*)&Ch[(size_t)r1 * ldc + col] = __floats2half2_rn(v10, v11);
                }
                if (MODE == 2) {
                    float2 e0 = __half22float2(*(const __half2*)&extrah[(size_t)r0 * ldc + col]);
                    float2 e1 = __half22float2(*(const __half2*)&extrah[(size_t)r1 * ldc + col]);
                    v00 *= e0.x; v01 *= e0.y; v10 *= e1.x; v11 *= e1.y;
                    *(__half2*)&Ch[(size_t)r0 * ldc + col] = __floats2half2_rn(v00, v01);
                    *(__half2*)&Ch[(size_t)r1 * ldc + col] = __floats2half2_rn(v10, v11);
                }
                if (MODE == 3) {
                    float2 e0 = *(const float2*)&extraf[(size_t)r0 * ldc + col];
                    float2 e1 = *(const float2*)&extraf[(size_t)r1 * ldc + col];
                    v00 += e0.x; v01 += e0.y; v10 += e1.x; v11 += e1.y;
                    *(float2*)&C[(size_t)r0 * ldc + col] = make_float2(v00, v01);
                    *(float2*)&C[(size_t)r1 * ldc + col] = make_float2(v10, v11);
                }
                if (MODE == 4) {
                    // col in [0,3072): part 0=q, 1=k, 2=v; rows r0/r1 = tokens
                    int part = col >> 10;
                    int cc   = col & 1023;
                    int hh   = cc >> 6;
                    int hd   = cc & 63;          // even
                    int b0 = r0 >> 11, s0 = r0 & 2047;
                    int b1 = r1 >> 11, s1 = r1 & 2047;
                    size_t orow0 = ((size_t)(b0 * Hq + hh) * Sq + s0) * HDq;
                    size_t orow1 = ((size_t)(b1 * Hq + hh) * Sq + s1) * HDq;
                    if (part == 2) {
                        *(__half2*)&ov[orow0 + hd] = __floats2half2_rn(v00, v01);
                        *(__half2*)&ov[orow1 + hd] = __floats2half2_rn(v10, v11);
                    } else {
                        __half* dst = (part == 0) ? oq : ok;
                        int i = hd >> 1;
                        float2 r0l = rope[s0 * 32 + i];
                        float2 r1l = rope[s1 * 32 + i];
                        dst[orow0 + i]      = __float2half_rn(v00 * r0l.x - v01 * r0l.y);
                        dst[orow0 + 32 + i] = __float2half_rn(v00 * r0l.y + v01 * r0l.x);
                        dst[orow1 + i]      = __float2half_rn(v10 * r1l.x - v11 * r1l.y);
                        dst[orow1 + 32 + i] = __float2half_rn(v10 * r1l.y + v11 * r1l.x);
                    }
                }
            }
        }
    }
}

// ---------------- FP16 tensor-core causal flash attention (ldmatrix) --------
#define FA_BM 128
#define FA_BN 64
#define FPH 72
#define FA_SMEMH ((FA_BM*FPH + FA_BN*FPH + FA_BN*FPH + FA_BM*FPH) * 2)

__global__ void __launch_bounds__(256, 2) flash_attn_h(const __half* __restrict__ Q,
                                                       const __half* __restrict__ K,
                                                       const __half* __restrict__ V,
                                                       __half* __restrict__ O)
{
    extern __shared__ __half fh[];
    __half* Qs = fh;                      // [128][72]
    __half* Ks = Qs + FA_BM * FPH;        // [64][72]
    __half* Vt = Ks + FA_BN * FPH;        // [hd 64][key 72]
    __half* Ps = Vt + FA_BN * FPH;        // [128][72]
    const uint32_t sQs = (uint32_t)__cvta_generic_to_shared(Qs);
    const uint32_t sKs = (uint32_t)__cvta_generic_to_shared(Ks);
    const uint32_t sVt = (uint32_t)__cvta_generic_to_shared(Vt);
    const uint32_t sPs = (uint32_t)__cvta_generic_to_shared(Ps);

    const int qt = gridDim.x - 1 - blockIdx.x;
    const int h = blockIdx.y, b = blockIdx.z;
    const int qm0 = qt * FA_BM;
    const size_t base = ((size_t)(b * Hq + h)) * Sq * HDq;
    const __half* Qb = Q + base;
    const __half* Kb = K + base;
    const __half* Vb = V + base;

    const int tid  = threadIdx.x;
    const int lane = tid & 31;
    const int w    = tid >> 5;
    const int qr   = lane >> 2;
    const int qc   = lane & 3;
    const int wrow = w * 16;

    const int laneRowA = lane & 15;
    const int laneKA   = (lane >> 4) << 3;
    const int laneRowB = (lane & 7) + ((lane >> 4) << 3);
    const int laneKB   = ((lane >> 3) & 1) << 3;

    for (int i = tid; i < FA_BM * 32; i += 256) {   // half2 granules
        int r = i >> 5, c2 = i & 31;
        __half2 v = ((const __half2*)Qb)[(size_t)(qm0 + r) * 32 + c2];
        *(__half2*)&Qs[r * FPH + c2 * 2] = v;
    }

    float o[8][4];
    #pragma unroll
    for (int j = 0; j < 8; j++)
        #pragma unroll
        for (int t = 0; t < 4; t++) o[j][t] = 0.f;
    float m0 = -1e30f, m1 = -1e30f, l0 = 0.f, l1 = 0.f;

    const int row0 = qm0 + wrow + qr;
    const int row1 = row0 + 8;
    const int nkt = (qm0 + FA_BM) / FA_BN;

    for (int kt = 0; kt < nkt; kt++) {
        const int kn0 = kt * FA_BN;
        __syncthreads();
        for (int i = tid; i < FA_BN * 32; i += 256) {
            int r = i >> 5, c2 = i & 31;
            __half2 kv = ((const __half2*)Kb)[(size_t)(kn0 + r) * 32 + c2];
            *(__half2*)&Ks[r * FPH + c2 * 2] = kv;
            __half2 vv = ((const __half2*)Vb)[(size_t)(kn0 + r) * 32 + c2];
            Vt[(c2 * 2)     * FPH + r] = __low2half(vv);
            Vt[(c2 * 2 + 1) * FPH + r] = __high2half(vv);
        }
        __syncthreads();

        const bool active = (kn0 <= qm0 + wrow + 15);
        if (active) {
            // ---- S = Q @ K^T ----
            float s[8][4];
            #pragma unroll
            for (int j = 0; j < 8; j++)
                #pragma unroll
                for (int t = 0; t < 4; t++) s[j][t] = 0.f;

            #pragma unroll
            for (int kk = 0; kk < 4; kk++) {
                const int kb = kk * 16;
                uint32_t a0, a1, a2, a3;
                LDSM4(a0, a1, a2, a3,
                      sQs + (((wrow + laneRowA) * FPH) + kb + laneKA) * 2);
                #pragma unroll
                for (int j = 0; j < 8; j += 2) {
                    uint32_t b0, b1, b2, b3;
                    LDSM4(b0, b1, b2, b3,
                          sKs + (((j * 8 + laneRowB) * FPH) + kb + laneKB) * 2);
                    MMA_H(s[j][0],   s[j][1],   s[j][2],   s[j][3],   a0,a1,a2,a3, b0,b1);
                    MMA_H(s[j+1][0], s[j+1][1], s[j+1][2], s[j+1][3], a0,a1,a2,a3, b2,b3);
                }
            }

            // ---- causal mask + online softmax ----
            float rmax0 = -1e30f, rmax1 = -1e30f;
            #pragma unroll
            for (int j = 0; j < 8; j++) {
                int c0 = kn0 + j * 8 + 2 * qc, c1 = c0 + 1;
                s[j][0] = (c0 <= row0) ? s[j][0] * 0.125f : -1e30f;
                s[j][1] = (c1 <= row0) ? s[j][1] * 0.125f : -1e30f;
                s[j][2] = (c0 <= row1) ? s[j][2] * 0.125f : -1e30f;
                s[j][3] = (c1 <= row1) ? s[j][3] * 0.125f : -1e30f;
                rmax0 = fmaxf(rmax0, fmaxf(s[j][0], s[j][1]));
                rmax1 = fmaxf(rmax1, fmaxf(s[j][2], s[j][3]));
            }
            rmax0 = fmaxf(rmax0, __shfl_xor_sync(0xffffffffu, rmax0, 1));
            rmax0 = fmaxf(rmax0, __shfl_xor_sync(0xffffffffu, rmax0, 2));
            rmax1 = fmaxf(rmax1, __shfl_xor_sync(0xffffffffu, rmax1, 1));
            rmax1 = fmaxf(rmax1, __shfl_xor_sync(0xffffffffu, rmax1, 2));

            float mn0 = fmaxf(m0, rmax0), mn1 = fmaxf(m1, rmax1);
            float a0 = __expf(m0 - mn0),  a1 = __expf(m1 - mn1);
            float rs0 = 0.f, rs1 = 0.f;
            __half* pr0 = Ps + (wrow + qr) * FPH;
            __half* pr1 = pr0 + 8 * FPH;
            #pragma unroll
            for (int j = 0; j < 8; j++) {
                __half2 h0 = __floats2half2_rn(__expf(s[j][0] - mn0),
                                               __expf(s[j][1] - mn0));
                __half2 h1 = __floats2half2_rn(__expf(s[j][2] - mn1),
                                               __expf(s[j][3] - mn1));
                *(__half2*)&pr0[j * 8 + 2 * qc] = h0;
                *(__half2*)&pr1[j * 8 + 2 * qc] = h1;
                float2 f0 = __half22float2(h0), f1 = __half22float2(h1);
                rs0 += f0.x + f0.y;
                rs1 += f1.x + f1.y;
            }
            rs0 += __shfl_xor_sync(0xffffffffu, rs0, 1);
            rs0 += __shfl_xor_sync(0xffffffffu, rs0, 2);
            rs1 += __shfl_xor_sync(0xffffffffu, rs1, 1);
            rs1 += __shfl_xor_sync(0xffffffffu, rs1, 2);

            l0 = l0 * a0 + rs0; m0 = mn0;
            l1 = l1 * a1 + rs1; m1 = mn1;
            #pragma unroll
            for (int j = 0; j < 8; j++) {
                o[j][0] *= a0; o[j][1] *= a0;
                o[j][2] *= a1; o[j][3] *= a1;
            }
            __syncwarp();

            // ---- O += P @ V ----
            #pragma unroll
            for (int kk = 0; kk < 4; kk++) {
                const int kb = kk * 16;
                uint32_t a0f, a1f, a2f, a3f;
                LDSM4(a0f, a1f, a2f, a3f,
                      sPs + (((wrow + laneRowA) * FPH) + kb + laneKA) * 2);
                #pragma unroll
                for (int j = 0; j < 8; j += 2) {
                    uint32_t b0, b1, b2, b3;
                    LDSM4(b0, b1, b2, b3,
                          sVt + (((j * 8 + laneRowB) * FPH) + kb + laneKB) * 2);
                    MMA_H(o[j][0],   o[j][1],   o[j][2],   o[j][3],   a0f,a1f,a2f,a3f, b0,b1);
                    MMA_H(o[j+1][0], o[j+1][1], o[j+1][2], o[j+1][3], a0f,a1f,a2f,a3f, b2,b3);
                }
            }
        }
    }

    // ---- normalize + write O (fp16) as [b, s, h*64 + c] ----
    float inv0 = 1.f / l0, inv1 = 1.f / l1;
    #pragma unroll
    for (int j = 0; j < 8; j++) {
        int col = h * HDq + j * 8 + 2 * qc;
        size_t o0 = ((size_t)(b * Sq + row0)) * Dq + col;
        size_t o1 = ((size_t)(b * Sq + row1)) * Dq + col;
        *(__half2*)&O[o0] = __floats2half2_rn(o[j][0] * inv0, o[j][1] * inv0);
        *(__half2*)&O[o1] = __floats2half2_rn(o[j][2] * inv1, o[j][3] * inv1);
    }
}

// ---------------- launch --------------------------------------------------
extern "C" void kernel_launch(void* const* d_in, const int* in_sizes, int n_in,
                              void* d_out, int out_size)
{
    const float* x          = (const float*)d_in[0];
    const float* gamma_attn = (const float*)d_in[2];
    const float* w_qkv      = (const float*)d_in[3];
    const float* b_qkv      = (const float*)d_in[4];
    const float* w_out      = (const float*)d_in[5];
    const float* b_out      = (const float*)d_in[6];
    const float* gamma_ffn  = (const float*)d_in[7];
    const float* w1         = (const float*)d_in[8];
    const float* b1         = (const float*)d_in[9];
    const float* w2         = (const float*)d_in[10];
    const float* b2         = (const float*)d_in[11];
    const float* w3         = (const float*)d_in[12];
    const float* b3         = (const float*)d_in[13];
    float* out = (float*)d_out;

    float  *xn, *h, *hn;
    float2 *rope;
    __half *xnh, *qh, *kh, *vh, *attnh, *hnh, *ff1h, *ff2h;
    __half *wqkvh, *wouth, *w1h, *w2h, *w3ph;
    cudaGetSymbolAddress((void**)&xn,    g_xn);
    cudaGetSymbolAddress((void**)&xnh,   g_xnh);
    cudaGetSymbolAddress((void**)&qh,    g_qh);
    cudaGetSymbolAddress((void**)&kh,    g_kh);
    cudaGetSymbolAddress((void**)&vh,    g_vh);
    cudaGetSymbolAddress((void**)&attnh, g_attnh);
    cudaGetSymbolAddress((void**)&h,     g_h);
    cudaGetSymbolAddress((void**)&hn,    g_hn);
    cudaGetSymbolAddress((void**)&hnh,   g_hnh);
    cudaGetSymbolAddress((void**)&ff1h,  g_ff1h);
    cudaGetSymbolAddress((void**)&ff2h,  g_ff2h);
    cudaGetSymbolAddress((void**)&rope,  g_rope);
    cudaGetSymbolAddress((void**)&wqkvh, g_wqkvh);
    cudaGetSymbolAddress((void**)&wouth, g_wouth);
    cudaGetSymbolAddress((void**)&w1h,   g_w1h);
    cudaGetSymbolAddress((void**)&w2h,   g_w2h);
    cudaGetSymbolAddress((void**)&w3ph,  g_w3ph);

    cudaFuncSetAttribute(gemm_h<1>, cudaFuncAttributeMaxDynamicSharedMemorySize, SMEM_H);
    cudaFuncSetAttribute(gemm_h<2>, cudaFuncAttributeMaxDynamicSharedMemorySize, SMEM_H);
    cudaFuncSetAttribute(gemm_h<3>, cudaFuncAttributeMaxDynamicSharedMemorySize, SMEM_H);
    cudaFuncSetAttribute(gemm_h<4>, cudaFuncAttributeMaxDynamicSharedMemorySize, SMEM_H);
    cudaFuncSetAttribute(flash_attn_h, cudaFuncAttributeMaxDynamicSharedMemorySize, FA_SMEMH);

    // ---- fork: side stream converts weights not needed until step 4 --------
    cudaStream_t s2;
    cudaStreamCreateWithFlags(&s2, cudaStreamNonBlocking);
    cudaEvent_t eFork, eJoin;
    cudaEventCreateWithFlags(&eFork, cudaEventDisableTiming);
    cudaEventCreateWithFlags(&eJoin, cudaEventDisableTiming);

    cudaEventRecord(eFork, 0);
    cudaStreamWaitEvent(s2, eFork, 0);
    {
        int n, g;
        n = Dq*Dq/4;    g = (n/4 + 255)/256;  conv_half<<<g, 256, 0, s2>>>(w_out, wouth, n);
        n = DIq*Dq/4;   g = (n/4 + 255)/256;  conv_half<<<g, 256, 0, s2>>>(w1, w1h, n);
        n = DIq*Dq/4;   g = (n/4 + 255)/256;  conv_half<<<g, 256, 0, s2>>>(w2, w2h, n);
        n = Dq*DIpad;   conv_half_pad<<<(n+255)/256, 256, 0, s2>>>(w3, w3ph, Dq, DIq, DIpad);
        n = BSq*(DIpad-DIq); zero_pad_ff1<<<(n+255)/256, 256, 0, s2>>>(ff1h);
    }
    cudaEventRecord(eJoin, s2);

    // ---- main chain ---------------------------------------------------------
    // 0) qkv weights + rope LUT (needed by step 2)
    {
        int n = 3*Dq*Dq/4, g = (n/4 + 255)/256;
        conv_half<<<g, 256>>>(w_qkv, wqkvh, n);
        rope_lut_k<<<(Sq*32)/256, 256>>>(rope);
    }

    // 1) xn = rmsnorm(x, gamma_attn)  (fp32 + fp16)
    rmsnorm_k<<<BSq, 256>>>(x, gamma_attn, xn, xnh);

    // 2) q,k,v = rope(split(xnh @ wqkvh^T + b_qkv))   [fused epilogue, LUT]
    gemm_h<4><<<dim3(3*Dq/128, BSq/128), 256, SMEM_H>>>(
        xnh, wqkvh, b_qkv, nullptr, nullptr, nullptr, nullptr,
        qh, kh, vh, rope, BSq, 3*Dq, Dq, Dq, 0);

    // 3) flash attention -> attnh (fp16)
    flash_attn_h<<<dim3(Sq/FA_BM, Hq, Bq), 256, FA_SMEMH>>>(qh, kh, vh, attnh);

    // join side-stream conversions before they are consumed
    cudaStreamWaitEvent(0, eJoin, 0);

    // 4) h = xn + attnh @ wouth^T + b_out      (fp32 out)
    gemm_h<3><<<dim3(Dq/128, BSq/128), 256, SMEM_H>>>(
        attnh, wouth, b_out, xn, nullptr, h, nullptr,
        nullptr, nullptr, nullptr, nullptr, BSq, Dq, Dq, Dq, Dq);

    // 5) hn = rmsnorm(h, gamma_ffn)  (fp32 + fp16)
    rmsnorm_k<<<BSq, 256>>>(h, gamma_ffn, hn, hnh);

    // 6) gate = silu(hnh @ w2h^T + b2)         (fp16 out, stride DIpad)
    gemm_h<1><<<dim3((DIq+127)/128, BSq/128), 256, SMEM_H>>>(
        hnh, w2h, b2, nullptr, nullptr, nullptr, ff2h,
        nullptr, nullptr, nullptr, nullptr, BSq, DIq, Dq, Dq, DIpad);

    // 7) ff1 = (hnh @ w1h^T + b1) * gate       (fp16 out)
    gemm_h<2><<<dim3((DIq+127)/128, BSq/128), 256, SMEM_H>>>(
        hnh, w1h, b1, nullptr, ff2h, nullptr, ff1h,
        nullptr, nullptr, nullptr, nullptr, BSq, DIq, Dq, Dq, DIpad);

    // 8) out = hn + ff1h @ w3ph^T + b3         (K padded to 2736, pads zero)
    gemm_h<3><<<dim3(Dq/128, BSq/128), 256, SMEM_H>>>(
        ff1h, w3ph, b3, hn, nullptr, out, nullptr,
        nullptr, nullptr, nullptr, nullptr, BSq, Dq, DIpad, DIpad, Dq);
}

// round 16
// speedup vs baseline: 9.6640x; 1.0921x over previous
#include <cuda_runtime.h>
#include <cuda_fp16.h>
#include <math.h>
#include <stdint.h>

// Problem constants
#define Bq  2
#define Sq  2048
#define Dq  1024
#define Hq  16
#define HDq 64
#define DIq 2730            // int(8/3 * 1024)
#define DIpad 2736          // padded row stride
#define BSq (Bq*Sq)         // 4096 rows

// ---------------- scratch (device globals; no allocation allowed) -----------
__device__ float  g_xn  [(size_t)BSq*Dq];
__device__ __half g_xnh [(size_t)BSq*Dq];
__device__ __half g_qh  [(size_t)Bq*Hq*Sq*HDq];
__device__ __half g_kh  [(size_t)Bq*Hq*Sq*HDq];
__device__ __half g_vh  [(size_t)Bq*Hq*Sq*HDq];
__device__ __half g_attnh[(size_t)BSq*Dq];
__device__ float  g_h   [(size_t)BSq*Dq];
__device__ float  g_hn  [(size_t)BSq*Dq];
__device__ __half g_hnh [(size_t)BSq*Dq];
__device__ __half g_ff1h[(size_t)BSq*DIpad];
__device__ __half g_ff2h[(size_t)BSq*DIpad];   // gate, fp16
__device__ float2 g_rope[(size_t)Sq*32];       // (cos, sin) per (s, pair)
// fp16 weight copies
__device__ __half g_wqkvh[(size_t)3*Dq*Dq];
__device__ __half g_wouth[(size_t)Dq*Dq];
__device__ __half g_w1h  [(size_t)DIq*Dq];
__device__ __half g_w2h  [(size_t)DIq*Dq];
__device__ __half g_w3ph [(size_t)Dq*DIpad];   // padded [1024][2736], zeros in pad

// ---------------- rope LUT fill ----------------------------------------------
__global__ void __launch_bounds__(256) rope_lut_k(float2* __restrict__ lut)
{
    int idx = blockIdx.x * 256 + threadIdx.x;   // Sq*32 threads
    int i = idx & 31;
    int s = idx >> 5;
    float theta = powf(10000.f, -((float)(2 * i)) / 64.f);
    float sn, cs;
    sincosf((float)s * theta, &sn, &cs);
    lut[idx] = make_float2(cs, sn);
}

// ---------------- conversion kernels -----------------------------------------
__global__ void __launch_bounds__(256) conv_half(const float* __restrict__ src,
                                                 __half* __restrict__ dst, int n4)
{
    int i0 = (blockIdx.x * 256 + threadIdx.x) * 4;
    int stride = gridDim.x * 256 * 4;
    for (int i = i0; i < n4 + 3; i += stride) {
        float4 v[4];
        #pragma unroll
        for (int u = 0; u < 4; u++)
            if (i + u < n4) v[u] = ((const float4*)src)[i + u];
        #pragma unroll
        for (int u = 0; u < 4; u++)
            if (i + u < n4) {
                ((__half2*)dst)[(i+u)*2]   = __floats2half2_rn(v[u].x, v[u].y);
                ((__half2*)dst)[(i+u)*2+1] = __floats2half2_rn(v[u].z, v[u].w);
            }
    }
}

// 2-D grid: y = row, x covers columns; no div/mod
__global__ void __launch_bounds__(256) conv_half_pad(const float* __restrict__ src,
                                                     __half* __restrict__ dst,
                                                     int cin, int cpad)
{
    int c = blockIdx.x * 256 + threadIdx.x;
    int r = blockIdx.y;
    if (c < cpad)
        dst[(size_t)r * cpad + c] =
            (c < cin) ? __float2half_rn(src[(size_t)r * cin + c]) : __half(0.f);
}

__global__ void __launch_bounds__(256) zero_pad_ff1(__half* __restrict__ ff1)
{
    int i = blockIdx.x * 256 + threadIdx.x;
    if (i < BSq * (DIpad - DIq)) {
        int r = i / (DIpad - DIq), c = DIq + i % (DIpad - DIq);
        ff1[(size_t)r * DIpad + c] = __half(0.f);
    }
}

// ---------------- RMSNorm: dual output (fp32 + fp16) ------------------------
__global__ void __launch_bounds__(256) rmsnorm_k(const float* __restrict__ x,
                                                 const float* __restrict__ gamma,
                                                 float* __restrict__ out,
                                                 __half* __restrict__ out_h)
{
    const size_t row = blockIdx.x;
    const float* xr = x + row * Dq;
    float ss = 0.f;
    for (int c = threadIdx.x; c < Dq; c += 256) { float v = xr[c]; ss += v * v; }
    #pragma unroll
    for (int d = 16; d > 0; d >>= 1) ss += __shfl_xor_sync(0xffffffffu, ss, d);
    __shared__ float red[8];
    __shared__ float s_inv;
    if ((threadIdx.x & 31) == 0) red[threadIdx.x >> 5] = ss;
    __syncthreads();
    if (threadIdx.x == 0) {
        float t = 0.f;
        #pragma unroll
        for (int i = 0; i < 8; i++) t += red[i];
        s_inv = rsqrtf(t / (float)Dq + 1e-5f);
    }
    __syncthreads();
    const float inv = s_inv;
    for (int c = threadIdx.x; c < Dq; c += 256) {
        float v = xr[c] * inv * gamma[c];
        out[row * Dq + c]   = v;
        out_h[row * Dq + c] = __float2half_rn(v);
    }
}

// ---------------- cp.async / ldmatrix helpers --------------------------------
__device__ __forceinline__ void cp16(uint32_t dst, const void* src, int sz) {
    asm volatile("cp.async.cg.shared.global [%0], [%1], 16, %2;"
                 :: "r"(dst), "l"(src), "r"(sz));
}
__device__ __forceinline__ void cp_commit() { asm volatile("cp.async.commit_group;"); }
__device__ __forceinline__ void cp_wait0()  { asm volatile("cp.async.wait_group 0;" ::: "memory"); }

#define LDSM4(r0, r1, r2, r3, a) \
    asm volatile("ldmatrix.sync.aligned.m8n8.x4.shared.b16 {%0,%1,%2,%3}, [%4];" \
                 : "=r"(r0), "=r"(r1), "=r"(r2), "=r"(r3) : "r"(a))

#define LDSM4T(r0, r1, r2, r3, a) \
    asm volatile("ldmatrix.sync.aligned.m8n8.x4.trans.shared.b16 {%0,%1,%2,%3}, [%4];" \
                 : "=r"(r0), "=r"(r1), "=r"(r2), "=r"(r3) : "r"(a))

#define MMA_H(d0,d1,d2,d3, a0,a1,a2,a3, b0,b1) \
    asm volatile("mma.sync.aligned.m16n8k16.row.col.f32.f16.f16.f32 " \
                 "{%0,%1,%2,%3}, {%4,%5,%6,%7}, {%8,%9}, {%0,%1,%2,%3};" \
                 : "+f"(d0), "+f"(d1), "+f"(d2), "+f"(d3) \
                 : "r"(a0), "r"(a1), "r"(a2), "r"(a3), "r"(b0), "r"(b1))

// ---------------- FP16 GEMM (mma.m16n8k16 + ldmatrix), 2 CTA/SM -------------
// MODE 1: silu(+bias) -> Ch | 2: (+bias)*extrah -> Ch | 3: (+bias)+extraf -> C
// MODE 4: qkv fused rope (LUT)
#define HBK 64
#define HPAD 72
#define HSTG (128 * HPAD)
#define SMEM_H (4 * HSTG * 2)       // 73728 B

template <int MODE>
__global__ void __launch_bounds__(256, 2) gemm_h(const __half* __restrict__ A,
                                                 const __half* __restrict__ W,
                                                 const float* __restrict__ bias,
                                                 const float* __restrict__ extraf,
                                                 const __half* __restrict__ extrah,
                                                 float* __restrict__ C,
                                                 __half* __restrict__ Ch,
                                                 __half* __restrict__ oq,
                                                 __half* __restrict__ ok,
                                                 __half* __restrict__ ov,
                                                 const float2* __restrict__ rope,
                                                 int M, int N, int K,
                                                 int lda, int ldc)
{
    extern __shared__ __half hs[];
    const uint32_t sAll = (uint32_t)__cvta_generic_to_shared(hs);
    const uint32_t sA = sAll;
    const uint32_t sB = sAll + 2 * HSTG * 2;

    const int tid  = threadIdx.x;
    const int lane = tid & 31;
    const int w    = tid >> 5;
    const int wm   = (w >> 2) * 64;
    const int wn   = (w & 3) * 32;
    const int m0   = blockIdx.y * 128;
    const int n0   = blockIdx.x * 128;
    const int qr   = lane >> 2;
    const int qc   = lane & 3;

    const int laneRowA = lane & 15;
    const int laneKA   = (lane >> 4) << 3;
    const int laneRowB = (lane & 7) + ((lane >> 4) << 3);
    const int laneKB   = ((lane >> 3) & 1) << 3;

    float acc[4][4][4];
    #pragma unroll
    for (int i = 0; i < 4; i++)
        #pragma unroll
        for (int j = 0; j < 4; j++)
            #pragma unroll
            for (int t = 0; t < 4; t++) acc[i][j][t] = 0.f;

    const int kt = (K + HBK - 1) / HBK;

    auto issue_stage = [&](int t, int buf) {
        const int k0 = t * HBK;
        const uint32_t aOff = sA + buf * HSTG * 2;
        const uint32_t bOff = sB + buf * HSTG * 2;
        #pragma unroll
        for (int i = 0; i < 4; i++) {
            int idx = tid + i * 256;
            int row = idx >> 3;
            int g   = idx & 7;
            int gk  = k0 + g * 8;
            int sz  = (gk < K) ? 16 : 0;
            int cs  = sz ? gk : 0;
            cp16(aOff + (row * HPAD + g * 8) * 2,
                 &A[(size_t)(m0 + row) * lda + cs], sz);
            int gn = n0 + row;
            int szb = (gn < N) ? sz : 0;
            cp16(bOff + (row * HPAD + g * 8) * 2,
                 &W[(size_t)((gn < N) ? gn : 0) * K + cs], szb);
        }
        cp_commit();
    };

    auto compute = [&](int buf) {
        const uint32_t aOff = sA + buf * HSTG * 2;
        const uint32_t bOff = sB + buf * HSTG * 2;
        #pragma unroll
        for (int kk = 0; kk < 4; kk++) {
            const int kb = kk * 16;
            uint32_t af[4][4], bf[4][2];
            #pragma unroll
            for (int mt = 0; mt < 4; mt++) {
                uint32_t a = aOff + (((wm + mt * 16 + laneRowA) * HPAD) + kb + laneKA) * 2;
                LDSM4(af[mt][0], af[mt][1], af[mt][2], af[mt][3], a);
            }
            #pragma unroll
            for (int nt = 0; nt < 4; nt += 2) {
                uint32_t a = bOff + (((wn + nt * 8 + laneRowB) * HPAD) + kb + laneKB) * 2;
                LDSM4(bf[nt][0], bf[nt][1], bf[nt+1][0], bf[nt+1][1], a);
            }
            #pragma unroll
            for (int mt = 0; mt < 4; mt++)
                #pragma unroll
                for (int nt = 0; nt < 4; nt++)
                    MMA_H(acc[mt][nt][0], acc[mt][nt][1], acc[mt][nt][2], acc[mt][nt][3],
                          af[mt][0], af[mt][1], af[mt][2], af[mt][3],
                          bf[nt][0], bf[nt][1]);
        }
    };

    issue_stage(0, 0);
    for (int t = 0; t < kt; t++) {
        cp_wait0();
        __syncthreads();
        if (t + 1 < kt) issue_stage(t + 1, (t + 1) & 1);
        compute(t & 1);
    }

    // Epilogue
    #pragma unroll
    for (int mt = 0; mt < 4; mt++) {
        int r0 = m0 + wm + mt * 16 + qr;
        int r1 = r0 + 8;
        #pragma unroll
        for (int nt = 0; nt < 4; nt++) {
            int col = n0 + wn + nt * 8 + qc * 2;
            if (col < N) {
                float bv0 = bias[col], bv1 = bias[col + 1];
                float v00 = acc[mt][nt][0] + bv0;
                float v01 = acc[mt][nt][1] + bv1;
                float v10 = acc[mt][nt][2] + bv0;
                float v11 = acc[mt][nt][3] + bv1;
                if (MODE == 1) {
                    v00 = v00 / (1.f + expf(-v00));
                    v01 = v01 / (1.f + expf(-v01));
                    v10 = v10 / (1.f + expf(-v10));
                    v11 = v11 / (1.f + expf(-v11));
                    *(__half2*)&Ch[(size_t)r0 * ldc + col] = __floats2half2_rn(v00, v01);
                    *(__half2*)&Ch[(size_t)r1 * ldc + col] = __floats2half2_rn(v10, v11);
                }
                if (MODE == 2) {
                    float2 e0 = __half22float2(*(const __half2*)&extrah[(size_t)r0 * ldc + col]);
                    float2 e1 = __half22float2(*(const __half2*)&extrah[(size_t)r1 * ldc + col]);
                    v00 *= e0.x; v01 *= e0.y; v10 *= e1.x; v11 *= e1.y;
                    *(__half2*)&Ch[(size_t)r0 * ldc + col] = __floats2half2_rn(v00, v01);
                    *(__half2*)&Ch[(size_t)r1 * ldc + col] = __floats2half2_rn(v10, v11);
                }
                if (MODE == 3) {
                    float2 e0 = *(const float2*)&extraf[(size_t)r0 * ldc + col];
                    float2 e1 = *(const float2*)&extraf[(size_t)r1 * ldc + col];
                    v00 += e0.x; v01 += e0.y; v10 += e1.x; v11 += e1.y;
                    *(float2*)&C[(size_t)r0 * ldc + col] = make_float2(v00, v01);
                    *(float2*)&C[(size_t)r1 * ldc + col] = make_float2(v10, v11);
                }
                if (MODE == 4) {
                    int part = col >> 10;
                    int cc   = col & 1023;
                    int hh   = cc >> 6;
                    int hd   = cc & 63;
                    int b0 = r0 >> 11, s0 = r0 & 2047;
                    int b1 = r1 >> 11, s1 = r1 & 2047;
                    size_t orow0 = ((size_t)(b0 * Hq + hh) * Sq + s0) * HDq;
                    size_t orow1 = ((size_t)(b1 * Hq + hh) * Sq + s1) * HDq;
                    if (part == 2) {
                        *(__half2*)&ov[orow0 + hd] = __floats2half2_rn(v00, v01);
                        *(__half2*)&ov[orow1 + hd] = __floats2half2_rn(v10, v11);
                    } else {
                        __half* dst = (part == 0) ? oq : ok;
                        int i = hd >> 1;
                        float2 r0l = rope[s0 * 32 + i];
                        float2 r1l = rope[s1 * 32 + i];
                        dst[orow0 + i]      = __float2half_rn(v00 * r0l.x - v01 * r0l.y);
                        dst[orow0 + 32 + i] = __float2half_rn(v00 * r0l.y + v01 * r0l.x);
                        dst[orow1 + i]      = __float2half_rn(v10 * r1l.x - v11 * r1l.y);
                        dst[orow1 + 32 + i] = __float2half_rn(v10 * r1l.y + v11 * r1l.x);
                    }
                }
            }
        }
    }
}

// ---------------- FP16 flash attention: cp.async K/V + trans-ldmatrix V -----
// Smem (halves): Qs[128][72] | Kd[2][64][72] | Vd[2][64][72] | Ps[128][72]
#define FA_BM 128
#define FA_BN 64
#define FPH 72
#define FA_Q  0
#define FA_K  (FA_BM * FPH)
#define FA_V  (FA_K + 2 * FA_BN * FPH)
#define FA_P  (FA_V + 2 * FA_BN * FPH)
#define FA_SMEMH ((FA_P + FA_BM * FPH) * 2)     // 73728 B

__global__ void __launch_bounds__(256, 2) flash_attn_h(const __half* __restrict__ Q,
                                                       const __half* __restrict__ K,
                                                       const __half* __restrict__ V,
                                                       __half* __restrict__ O)
{
    extern __shared__ __half fh[];
    const uint32_t sAll = (uint32_t)__cvta_generic_to_shared(fh);
    const uint32_t sQs = sAll + FA_Q * 2;
    const uint32_t sKd = sAll + FA_K * 2;
    const uint32_t sVd = sAll + FA_V * 2;
    const uint32_t sPs = sAll + FA_P * 2;
    __half* Qs = fh + FA_Q;
    __half* Ps = fh + FA_P;

    const int qt = gridDim.x - 1 - blockIdx.x;
    const int h = blockIdx.y, b = blockIdx.z;
    const int qm0 = qt * FA_BM;
    const size_t base = ((size_t)(b * Hq + h)) * Sq * HDq;
    const __half* Qb = Q + base;
    const __half* Kb = K + base;
    const __half* Vb = V + base;

    const int tid  = threadIdx.x;
    const int lane = tid & 31;
    const int w    = tid >> 5;
    const int qr   = lane >> 2;
    const int qc   = lane & 3;
    const int wrow = w * 16;

    const int laneRowA = lane & 15;
    const int laneKA   = (lane >> 4) << 3;
    const int laneRowB = (lane & 7) + ((lane >> 4) << 3);
    const int laneKB   = ((lane >> 3) & 1) << 3;
    const int laneRowV = lane & 15;              // key offset within 16
    const int laneColV = (lane >> 4) << 3;       // hd offset within 16

    // stage Q (plain stores; first loop barrier orders visibility)
    for (int i = tid; i < FA_BM * 32; i += 256) {
        int r = i >> 5, c2 = i & 31;
        __half2 v = ((const __half2*)Qb)[(size_t)(qm0 + r) * 32 + c2];
        *(__half2*)&Qs[r * FPH + c2 * 2] = v;
    }

    const int nkt = (qm0 + FA_BM) / FA_BN;

    auto issue_kv = [&](int t, int buf) {
        const int kn0 = t * FA_BN;
        const uint32_t kOff = sKd + buf * FA_BN * FPH * 2;
        const uint32_t vOff = sVd + buf * FA_BN * FPH * 2;
        #pragma unroll
        for (int i = 0; i < 2; i++) {            // 512 granules per operand
            int idx = tid + i * 256;
            int row = idx >> 3;                  // 0..63
            int g   = idx & 7;
            cp16(kOff + (row * FPH + g * 8) * 2,
                 &Kb[(size_t)(kn0 + row) * HDq + g * 8], 16);
            cp16(vOff + (row * FPH + g * 8) * 2,
                 &Vb[(size_t)(kn0 + row) * HDq + g * 8], 16);
        }
        cp_commit();
    };

    float o[8][4];
    #pragma unroll
    for (int j = 0; j < 8; j++)
        #pragma unroll
        for (int t = 0; t < 4; t++) o[j][t] = 0.f;
    float m0 = -1e30f, m1 = -1e30f, l0 = 0.f, l1 = 0.f;

    const int row0 = qm0 + wrow + qr;
    const int row1 = row0 + 8;

    issue_kv(0, 0);
    for (int kt = 0; kt < nkt; kt++) {
        const int kn0 = kt * FA_BN;
        cp_wait0();
        __syncthreads();                          // tile kt resident; prev buf free
        if (kt + 1 < nkt) issue_kv(kt + 1, (kt + 1) & 1);

        const uint32_t sKb = sKd + (kt & 1) * FA_BN * FPH * 2;
        const uint32_t sVb = sVd + (kt & 1) * FA_BN * FPH * 2;

        const bool active = (kn0 <= qm0 + wrow + 15);
        if (active) {
            // ---- S = Q @ K^T ----
            float s[8][4];
            #pragma unroll
            for (int j = 0; j < 8; j++)
                #pragma unroll
                for (int t = 0; t < 4; t++) s[j][t] = 0.f;

            #pragma unroll
            for (int kk = 0; kk < 4; kk++) {
                const int kb = kk * 16;
                uint32_t a0, a1, a2, a3;
                LDSM4(a0, a1, a2, a3,
                      sQs + (((wrow + laneRowA) * FPH) + kb + laneKA) * 2);
                #pragma unroll
                for (int j = 0; j < 8; j += 2) {
                    uint32_t b0, b1, b2, b3;
                    LDSM4(b0, b1, b2, b3,
                          sKb + (((j * 8 + laneRowB) * FPH) + kb + laneKB) * 2);
                    MMA_H(s[j][0],   s[j][1],   s[j][2],   s[j][3],   a0,a1,a2,a3, b0,b1);
                    MMA_H(s[j+1][0], s[j+1][1], s[j+1][2], s[j+1][3], a0,a1,a2,a3, b2,b3);
                }
            }

            // ---- causal mask + online softmax ----
            float rmax0 = -1e30f, rmax1 = -1e30f;
            #pragma unroll
            for (int j = 0; j < 8; j++) {
                int c0 = kn0 + j * 8 + 2 * qc, c1 = c0 + 1;
                s[j][0] = (c0 <= row0) ? s[j][0] * 0.125f : -1e30f;
                s[j][1] = (c1 <= row0) ? s[j][1] * 0.125f : -1e30f;
                s[j][2] = (c0 <= row1) ? s[j][2] * 0.125f : -1e30f;
                s[j][3] = (c1 <= row1) ? s[j][3] * 0.125f : -1e30f;
                rmax0 = fmaxf(rmax0, fmaxf(s[j][0], s[j][1]));
                rmax1 = fmaxf(rmax1, fmaxf(s[j][2], s[j][3]));
            }
            rmax0 = fmaxf(rmax0, __shfl_xor_sync(0xffffffffu, rmax0, 1));
            rmax0 = fmaxf(rmax0, __shfl_xor_sync(0xffffffffu, rmax0, 2));
            rmax1 = fmaxf(rmax1, __shfl_xor_sync(0xffffffffu, rmax1, 1));
            rmax1 = fmaxf(rmax1, __shfl_xor_sync(0xffffffffu, rmax1, 2));

            float mn0 = fmaxf(m0, rmax0), mn1 = fmaxf(m1, rmax1);
            float a0 = __expf(m0 - mn0),  a1 = __expf(m1 - mn1);
            float rs0 = 0.f, rs1 = 0.f;
            __half* pr0 = Ps + (wrow + qr) * FPH;
            __half* pr1 = pr0 + 8 * FPH;
            #pragma unroll
            for (int j = 0; j < 8; j++) {
                __half2 h0 = __floats2half2_rn(__expf(s[j][0] - mn0),
                                               __expf(s[j][1] - mn0));
                __half2 h1 = __floats2half2_rn(__expf(s[j][2] - mn1),
                                               __expf(s[j][3] - mn1));
                *(__half2*)&pr0[j * 8 + 2 * qc] = h0;
                *(__half2*)&pr1[j * 8 + 2 * qc] = h1;
                float2 f0 = __half22float2(h0), f1 = __half22float2(h1);
                rs0 += f0.x + f0.y;
                rs1 += f1.x + f1.y;
            }
            rs0 += __shfl_xor_sync(0xffffffffu, rs0, 1);
            rs0 += __shfl_xor_sync(0xffffffffu, rs0, 2);
            rs1 += __shfl_xor_sync(0xffffffffu, rs1, 1);
            rs1 += __shfl_xor_sync(0xffffffffu, rs1, 2);

            l0 = l0 * a0 + rs0; m0 = mn0;
            l1 = l1 * a1 + rs1; m1 = mn1;
            #pragma unroll
            for (int j = 0; j < 8; j++) {
                o[j][0] *= a0; o[j][1] *= a0;
                o[j][2] *= a1; o[j][3] *= a1;
            }
            __syncwarp();

            // ---- O += P @ V (V row-major; B-frags via trans ldmatrix) ----
            #pragma unroll
            for (int kk = 0; kk < 4; kk++) {
                const int kb = kk * 16;
                uint32_t a0f, a1f, a2f, a3f;
                LDSM4(a0f, a1f, a2f, a3f,
                      sPs + (((wrow + laneRowA) * FPH) + kb + laneKA) * 2);
                #pragma unroll
                for (int nt = 0; nt < 4; nt++) {      // hd chunks of 16
                    uint32_t b0, b1, b2, b3;
                    LDSM4T(b0, b1, b2, b3,
                           sVb + (((kb + laneRowV) * FPH) + nt * 16 + laneColV) * 2);
                    MMA_H(o[nt*2][0],   o[nt*2][1],   o[nt*2][2],   o[nt*2][3],
                          a0f,a1f,a2f,a3f, b0,b1);
                    MMA_H(o[nt*2+1][0], o[nt*2+1][1], o[nt*2+1][2], o[nt*2+1][3],
                          a0f,a1f,a2f,a3f, b2,b3);
                }
            }
        }
    }

    // ---- normalize + write O (fp16) as [b, s, h*64 + c] ----
    float inv0 = 1.f / l0, inv1 = 1.f / l1;
    #pragma unroll
    for (int j = 0; j < 8; j++) {
        int col = h * HDq + j * 8 + 2 * qc;
        size_t o0 = ((size_t)(b * Sq + row0)) * Dq + col;
        size_t o1 = ((size_t)(b * Sq + row1)) * Dq + col;
        *(__half2*)&O[o0] = __floats2half2_rn(o[j][0] * inv0, o[j][1] * inv0);
        *(__half2*)&O[o1] = __floats2half2_rn(o[j][2] * inv1, o[j][3] * inv1);
    }
}

// ---------------- launch --------------------------------------------------
extern "C" void kernel_launch(void* const* d_in, const int* in_sizes, int n_in,
                              void* d_out, int out_size)
{
    const float* x          = (const float*)d_in[0];
    const float* gamma_attn = (const float*)d_in[2];
    const float* w_qkv      = (const float*)d_in[3];
    const float* b_qkv      = (const float*)d_in[4];
    const float* w_out      = (const float*)d_in[5];
    const float* b_out      = (const float*)d_in[6];
    const float* gamma_ffn  = (const float*)d_in[7];
    const float* w1         = (const float*)d_in[8];
    const float* b1         = (const float*)d_in[9];
    const float* w2         = (const float*)d_in[10];
    const float* b2         = (const float*)d_in[11];
    const float* w3         = (const float*)d_in[12];
    const float* b3         = (const float*)d_in[13];
    float* out = (float*)d_out;

    float  *xn, *h, *hn;
    float2 *rope;
    __half *xnh, *qh, *kh, *vh, *attnh, *hnh, *ff1h, *ff2h;
    __half *wqkvh, *wouth, *w1h, *w2h, *w3ph;
    cudaGetSymbolAddress((void**)&xn,    g_xn);
    cudaGetSymbolAddress((void**)&xnh,   g_xnh);
    cudaGetSymbolAddress((void**)&qh,    g_qh);
    cudaGetSymbolAddress((void**)&kh,    g_kh);
    cudaGetSymbolAddress((void**)&vh,    g_vh);
    cudaGetSymbolAddress((void**)&attnh, g_attnh);
    cudaGetSymbolAddress((void**)&h,     g_h);
    cudaGetSymbolAddress((void**)&hn,    g_hn);
    cudaGetSymbolAddress((void**)&hnh,   g_hnh);
    cudaGetSymbolAddress((void**)&ff1h,  g_ff1h);
    cudaGetSymbolAddress((void**)&ff2h,  g_ff2h);
    cudaGetSymbolAddress((void**)&rope,  g_rope);
    cudaGetSymbolAddress((void**)&wqkvh, g_wqkvh);
    cudaGetSymbolAddress((void**)&wouth, g_wouth);
    cudaGetSymbolAddress((void**)&w1h,   g_w1h);
    cudaGetSymbolAddress((void**)&w2h,   g_w2h);
    cudaGetSymbolAddress((void**)&w3ph,  g_w3ph);

    cudaFuncSetAttribute(gemm_h<1>, cudaFuncAttributeMaxDynamicSharedMemorySize, SMEM_H);
    cudaFuncSetAttribute(gemm_h<2>, cudaFuncAttributeMaxDynamicSharedMemorySize, SMEM_H);
    cudaFuncSetAttribute(gemm_h<3>, cudaFuncAttributeMaxDynamicSharedMemorySize, SMEM_H);
    cudaFuncSetAttribute(gemm_h<4>, cudaFuncAttributeMaxDynamicSharedMemorySize, SMEM_H);
    cudaFuncSetAttribute(flash_attn_h, cudaFuncAttributeMaxDynamicSharedMemorySize, FA_SMEMH);

    // ---- fork: side stream converts weights not needed until step 4 --------
    cudaStream_t s2;
    cudaStreamCreateWithFlags(&s2, cudaStreamNonBlocking);
    cudaEvent_t eFork, eJoin;
    cudaEventCreateWithFlags(&eFork, cudaEventDisableTiming);
    cudaEventCreateWithFlags(&eJoin, cudaEventDisableTiming);

    cudaEventRecord(eFork, 0);
    cudaStreamWaitEvent(s2, eFork, 0);
    {
        int n, g;
        n = Dq*Dq/4;    g = (n/4 + 255)/256;  conv_half<<<g, 256, 0, s2>>>(w_out, wouth, n);
        n = DIq*Dq/4;   g = (n/4 + 255)/256;  conv_half<<<g, 256, 0, s2>>>(w1, w1h, n);
        n = DIq*Dq/4;   g = (n/4 + 255)/256;  conv_half<<<g, 256, 0, s2>>>(w2, w2h, n);
        conv_half_pad<<<dim3((DIpad+255)/256, Dq), 256, 0, s2>>>(w3, w3ph, DIq, DIpad);
        n = BSq*(DIpad-DIq); zero_pad_ff1<<<(n+255)/256, 256, 0, s2>>>(ff1h);
    }
    cudaEventRecord(eJoin, s2);

    // ---- main chain ---------------------------------------------------------
    {
        int n = 3*Dq*Dq/4, g = (n/4 + 255)/256;
        conv_half<<<g, 256>>>(w_qkv, wqkvh, n);
        rope_lut_k<<<(Sq*32)/256, 256>>>(rope);
    }

    // 1) xn = rmsnorm(x, gamma_attn)
    rmsnorm_k<<<BSq, 256>>>(x, gamma_attn, xn, xnh);

    // 2) q,k,v = rope(split(xnh @ wqkvh^T + b_qkv))
    gemm_h<4><<<dim3(3*Dq/128, BSq/128), 256, SMEM_H>>>(
        xnh, wqkvh, b_qkv, nullptr, nullptr, nullptr, nullptr,
        qh, kh, vh, rope, BSq, 3*Dq, Dq, Dq, 0);

    // 3) flash attention -> attnh
    flash_attn_h<<<dim3(Sq/FA_BM, Hq, Bq), 256, FA_SMEMH>>>(qh, kh, vh, attnh);

    cudaStreamWaitEvent(0, eJoin, 0);

    // 4) h = xn + attnh @ wouth^T + b_out
    gemm_h<3><<<dim3(Dq/128, BSq/128), 256, SMEM_H>>>(
        attnh, wouth, b_out, xn, nullptr, h, nullptr,
        nullptr, nullptr, nullptr, nullptr, BSq, Dq, Dq, Dq, Dq);

    // 5) hn = rmsnorm(h, gamma_ffn)
    rmsnorm_k<<<BSq, 256>>>(h, gamma_ffn, hn, hnh);

    // 6) gate = silu(hnh @ w2h^T + b2)
    gemm_h<1><<<dim3((DIq+127)/128, BSq/128), 256, SMEM_H>>>(
        hnh, w2h, b2, nullptr, nullptr, nullptr, ff2h,
        nullptr, nullptr, nullptr, nullptr, BSq, DIq, Dq, Dq, DIpad);

    // 7) ff1 = (hnh @ w1h^T + b1) * gate
    gemm_h<2><<<dim3((DIq+127)/128, BSq/128), 256, SMEM_H>>>(
        hnh, w1h, b1, nullptr, ff2h, nullptr, ff1h,
        nullptr, nullptr, nullptr, nullptr, BSq, DIq, Dq, Dq, DIpad);

    // 8) out = hn + ff1h @ w3ph^T + b3
    gemm_h<3><<<dim3(Dq/128, BSq/128), 256, SMEM_H>>>(
        ff1h, w3ph, b3, hn, nullptr, out, nullptr,
        nullptr, nullptr, nullptr, nullptr, BSq, Dq, DIpad, DIpad, Dq);
}